// round 3
// baseline (speedup 1.0000x reference)
#include <cuda_runtime.h>
#include <cuda_bf16.h>

#define B_    8
#define S_    1029
#define D_    1024
#define H_    16
#define HD_   64
#define M_    (B_*S_)     // 8232
#define NPFX  5
#define SCALE_ 0.125f

typedef unsigned long long ull;

// Scratch (device globals — no allocation allowed). 16B-aligned for float4 IO.
__device__ __align__(16) float g_q [B_*H_*S_*HD_];   // [b,h,s,d]
__device__ __align__(16) float g_k [B_*H_*S_*HD_];
__device__ __align__(16) float g_v [B_*H_*S_*HD_];
__device__ __align__(16) float g_ao[M_*D_];          // attention out, [m, n]

// ---- packed f32x2 helpers (FFMA2 path; ptxas emits only from explicit PTX) --
__device__ __forceinline__ ull pack2(float lo, float hi) {
    ull u;
    asm("mov.b64 %0, {%1, %2};" : "=l"(u)
        : "r"(__float_as_uint(lo)), "r"(__float_as_uint(hi)));
    return u;
}
__device__ __forceinline__ void unpack2(ull u, float& lo, float& hi) {
    unsigned int a, b;
    asm("mov.b64 {%0, %1}, %2;" : "=r"(a), "=r"(b) : "l"(u));
    lo = __uint_as_float(a); hi = __uint_as_float(b);
}
#define FMA2(acc, a, b) \
    asm("fma.rn.f32x2 %0, %1, %2, %0;" : "+l"(acc) : "l"(a), "l"(b))
#define MUL2(acc, a) \
    asm("mul.rn.f32x2 %0, %0, %1;" : "+l"(acc) : "l"(a))

// ---------------------------------------------------------------------------
// Generic GEMM: C[M x 1024] = A[M x 1024] * W[1024 x 1024] (+ bias)
// 128x128 tile, BK=16, 8x8 microtile via f32x2, double-buffered smem.
// mode 0: dst[m*1024+n] (out projection; A = g_ao when A==nullptr)
// mode 1/2/3: write to g_q/g_k/g_v in [b,h,s,d] layout.
// ---------------------------------------------------------------------------
__global__ __launch_bounds__(256) void gemm128(
    const float* __restrict__ A, const float* __restrict__ W,
    const float* __restrict__ bias, float* __restrict__ dst, int mode)
{
    __shared__ float As[2][16][132];
    __shared__ float Bs[2][16][132];
    const int tid = threadIdx.x;
    const int tx = tid & 15, ty = tid >> 4;
    const int bm = blockIdx.x * 128;
    const int bn = blockIdx.y * 128;
    const float* Ap = A ? A : g_ao;

    ull acc[8][4] = {};
    float4 pa[2], pb[2];

    const int am  = tid >> 2;          // 0..63
    const int akc = (tid & 3) * 4;     // 0,4,8,12
    const int bkk = tid >> 4;          // 0..15
    const int bn8 = (tid & 15) * 8;    // 0..120

    // prefetch k0 = 0
    #pragma unroll
    for (int L = 0; L < 2; L++) {
        int gm = bm + am + 64*L;
        pa[L] = (gm < M_) ? *(const float4*)(Ap + (size_t)gm * D_ + akc)
                          : make_float4(0.f, 0.f, 0.f, 0.f);
        pb[L] = *(const float4*)(W + (size_t)bkk * D_ + bn + bn8 + 4*L);
    }
    #pragma unroll
    for (int L = 0; L < 2; L++) {
        int m = am + 64*L;
        As[0][akc+0][m] = pa[L].x; As[0][akc+1][m] = pa[L].y;
        As[0][akc+2][m] = pa[L].z; As[0][akc+3][m] = pa[L].w;
        *(float4*)&Bs[0][bkk][bn8 + 4*L] = pb[L];
    }
    __syncthreads();

    const int NT = D_ / 16;
    for (int t = 0; t < NT; t++) {
        int buf = t & 1;
        if (t + 1 < NT) {
            int k0 = (t + 1) * 16;
            #pragma unroll
            for (int L = 0; L < 2; L++) {
                int gm = bm + am + 64*L;
                pa[L] = (gm < M_) ? *(const float4*)(Ap + (size_t)gm * D_ + k0 + akc)
                                  : make_float4(0.f, 0.f, 0.f, 0.f);
                pb[L] = *(const float4*)(W + (size_t)(k0 + bkk) * D_ + bn + bn8 + 4*L);
            }
        }
        #pragma unroll
        for (int kk = 0; kk < 16; kk++) {
            float4 a0 = *(const float4*)&As[buf][kk][ty*4];
            float4 a1 = *(const float4*)&As[buf][kk][64 + ty*4];
            float4 b0 = *(const float4*)&Bs[buf][kk][tx*4];
            float4 b1 = *(const float4*)&Bs[buf][kk][64 + tx*4];
            ull bu[4] = { pack2(b0.x, b0.y), pack2(b0.z, b0.w),
                          pack2(b1.x, b1.y), pack2(b1.z, b1.w) };
            float av[8] = {a0.x, a0.y, a0.z, a0.w, a1.x, a1.y, a1.z, a1.w};
            #pragma unroll
            for (int i = 0; i < 8; i++) {
                ull ad = pack2(av[i], av[i]);
                #pragma unroll
                for (int j = 0; j < 4; j++) FMA2(acc[i][j], ad, bu[j]);
            }
        }
        if (t + 1 < NT) {
            int nb = buf ^ 1;
            #pragma unroll
            for (int L = 0; L < 2; L++) {
                int m = am + 64*L;
                As[nb][akc+0][m] = pa[L].x; As[nb][akc+1][m] = pa[L].y;
                As[nb][akc+2][m] = pa[L].z; As[nb][akc+3][m] = pa[L].w;
                *(float4*)&Bs[nb][bkk][bn8 + 4*L] = pb[L];
            }
        }
        __syncthreads();
    }

    // epilogue
    #pragma unroll
    for (int i = 0; i < 8; i++) {
        int m = bm + ((i < 4) ? ty*4 + i : 64 + ty*4 + (i - 4));
        if (m >= M_) continue;
        float c[8];
        unpack2(acc[i][0], c[0], c[1]); unpack2(acc[i][1], c[2], c[3]);
        unpack2(acc[i][2], c[4], c[5]); unpack2(acc[i][3], c[6], c[7]);
        int b = m / S_, s = m % S_;
        #pragma unroll
        for (int j = 0; j < 8; j++) {
            int n = bn + ((j < 4) ? tx*4 + j : 64 + tx*4 + (j - 4));
            float v = c[j] + (bias ? bias[n] : 0.f);
            if (mode == 0) {
                dst[(size_t)m * D_ + n] = v;
            } else {
                int h = n >> 6, d = n & 63;
                float* g = (mode == 1) ? g_q : (mode == 2) ? g_k : g_v;
                g[(((size_t)(b * H_ + h)) * S_ + s) * HD_ + d] = v;
            }
        }
    }
}

// ---------------------------------------------------------------------------
// RoPE (patch tokens only) + q-scale (all tokens).
// ---------------------------------------------------------------------------
__global__ void rope_kernel(const float* __restrict__ cosp,
                            const float* __restrict__ sinp)
{
    const int total = B_*H_*S_*32;
    int i = blockIdx.x * blockDim.x + threadIdx.x;
    if (i >= total) return;
    const bool isQ = (blockIdx.y == 0);
    int dh = i & 31;
    int s  = (i >> 5) % S_;
    int bh = i / (32 * S_);
    float* ptr = (isQ ? g_q : g_k) + ((size_t)bh * S_ + s) * HD_;
    if (s < NPFX) {
        if (isQ) { ptr[dh] *= SCALE_; ptr[dh+32] *= SCALE_; }
        return;
    }
    int p = s - NPFX;
    float c0 = cosp[p*HD_ + dh],      c1 = cosp[p*HD_ + dh + 32];
    float s0 = sinp[p*HD_ + dh],      s1 = sinp[p*HD_ + dh + 32];
    float x0 = ptr[dh], x1 = ptr[dh+32];
    float y0 = x0*c0 - x1*s0;
    float y1 = x1*c1 + x0*s1;
    if (isQ) { y0 *= SCALE_; y1 *= SCALE_; }
    ptr[dh]    = y0;
    ptr[dh+32] = y1;
}

// ---------------------------------------------------------------------------
// Flash attention fp32/f32x2. CTA = (128-query tile, one b*h). KV tile = 64.
// ---------------------------------------------------------------------------
#define PQ 132   // stride for Qs/St (33*16B rows -> float4-aligned)
#define PK 68    // stride for Ks/Vs
#define ATT_SMEM_BYTES ((64*PQ*2 + 64*PK*2 + 128*3 + 256*2) * 4)   // 105984

__global__ __launch_bounds__(256) void attn_kernel()
{
    extern __shared__ float sm[];
    float* Qs   = sm;               // [64][PQ]  (d, q)
    float* Ks   = Qs + 64*PQ;       // [64][PK]  (d, n)
    float* St   = Ks + 64*PK;       // [64][PQ]  (n, q)  scores then P
    float* Vs   = St + 64*PQ;       // [64][PK]  (n, d)
    float* m_s  = Vs + 64*PK;       // [128]
    float* l_s  = m_s + 128;        // [128]
    float* al_s = l_s + 128;        // [128]
    float* redm = al_s + 128;       // [2][128]
    float* reds = redm + 256;       // [2][128]

    const int tid = threadIdx.x;
    const int tx = tid & 15, ty = tid >> 4;
    const int bh = blockIdx.y;
    const int m0 = blockIdx.x * 128;
    const float* qp = g_q + (size_t)bh * S_ * HD_;
    const float* kp = g_k + (size_t)bh * S_ * HD_;
    const float* vp = g_v + (size_t)bh * S_ * HD_;

    // load Q tile transposed: Qs[d][q], 32 elems/thread
    #pragma unroll
    for (int t8 = 0; t8 < 32; t8++) {
        int i  = tid + t8 * 256;
        int mm = i >> 6, d = i & 63;
        float v = (m0 + mm < S_) ? qp[(size_t)(m0 + mm) * HD_ + d] : 0.f;
        Qs[d*PQ + mm] = v;
    }
    if (tid < 128) { m_s[tid] = -1e30f; l_s[tid] = 0.f; }

    ull o2[8][2] = {};
    const int r = tid & 127, part = tid >> 7;

    for (int n0 = 0; n0 < S_; n0 += 64) {
        __syncthreads();   // also covers Qs/m_s init on first iteration
        #pragma unroll
        for (int t8 = 0; t8 < 16; t8++) {
            int i  = tid + t8 * 256;
            int nn = i >> 6, d = i & 63;
            float kv = 0.f, vv = 0.f;
            if (n0 + nn < S_) {
                size_t off = (size_t)(n0 + nn) * HD_ + d;
                kv = kp[off];
                vv = vp[off];
            }
            Ks[d*PK + nn] = kv;
            Vs[nn*PK + d] = vv;
        }
        __syncthreads();

        // S = Q^T K : 8 q-rows x 4 k-cols per thread, f32x2 along cols
        ull s2[8][2] = {};
        #pragma unroll
        for (int d = 0; d < 64; d++) {
            float4 a0 = *(const float4*)&Qs[d*PQ + ty*4];
            float4 a1 = *(const float4*)&Qs[d*PQ + 64 + ty*4];
            float4 bk = *(const float4*)&Ks[d*PK + tx*4];
            ull b0 = pack2(bk.x, bk.y), b1 = pack2(bk.z, bk.w);
            float av[8] = {a0.x, a0.y, a0.z, a0.w, a1.x, a1.y, a1.z, a1.w};
            #pragma unroll
            for (int i = 0; i < 8; i++) {
                ull ad = pack2(av[i], av[i]);
                FMA2(s2[i][0], ad, b0);
                FMA2(s2[i][1], ad, b1);
            }
        }
        // unpack + transposed store St[n][q] as float4 along q
        {
            float sc[8][4];
            #pragma unroll
            for (int i = 0; i < 8; i++) {
                unpack2(s2[i][0], sc[i][0], sc[i][1]);
                unpack2(s2[i][1], sc[i][2], sc[i][3]);
            }
            #pragma unroll
            for (int cc = 0; cc < 4; cc++) {
                int n = tx*4 + cc;
                bool valid = (n0 + n) < S_;
                float4 w0, w1;
                if (valid) {
                    w0 = make_float4(sc[0][cc], sc[1][cc], sc[2][cc], sc[3][cc]);
                    w1 = make_float4(sc[4][cc], sc[5][cc], sc[6][cc], sc[7][cc]);
                } else {
                    w0 = make_float4(-1e30f, -1e30f, -1e30f, -1e30f);
                    w1 = w0;
                }
                *(float4*)&St[n*PQ + ty*4]      = w0;
                *(float4*)&St[n*PQ + 64 + ty*4] = w1;
            }
        }
        __syncthreads();

        // per-query max (2 partials per query)
        {
            float pm = -1e30f;
            #pragma unroll
            for (int n = part*32; n < part*32 + 32; n++)
                pm = fmaxf(pm, St[n*PQ + r]);
            redm[part*128 + r] = pm;
        }
        __syncthreads();
        if (tid < 128) {
            float nm = fmaxf(fmaxf(redm[r], redm[128 + r]), m_s[r]);
            al_s[r] = __expf(m_s[r] - nm);
            m_s[r]  = nm;
        }
        __syncthreads();
        // exp in place + partial sums
        {
            float mr = m_s[r];
            float ps = 0.f;
            #pragma unroll
            for (int n = part*32; n < part*32 + 32; n++) {
                float e = __expf(St[n*PQ + r] - mr);
                St[n*PQ + r] = e;
                ps += e;
            }
            reds[part*128 + r] = ps;
        }
        __syncthreads();
        if (tid < 128)
            l_s[r] = l_s[r]*al_s[r] + reds[r] + reds[128 + r];

        // O = O*alpha + P * V   (8 q-rows x 4 d-cols, f32x2 along d)
        #pragma unroll
        for (int i = 0; i < 8; i++) {
            int qrow = (i < 4) ? ty*4 + i : 64 + ty*4 + (i - 4);
            float al = al_s[qrow];
            ull ad = pack2(al, al);
            MUL2(o2[i][0], ad);
            MUL2(o2[i][1], ad);
        }
        #pragma unroll
        for (int n = 0; n < 64; n++) {
            float4 p0 = *(const float4*)&St[n*PQ + ty*4];
            float4 p1 = *(const float4*)&St[n*PQ + 64 + ty*4];
            float4 vv = *(const float4*)&Vs[n*PK + tx*4];
            ull v0 = pack2(vv.x, vv.y), v1 = pack2(vv.z, vv.w);
            float pv[8] = {p0.x, p0.y, p0.z, p0.w, p1.x, p1.y, p1.z, p1.w};
            #pragma unroll
            for (int i = 0; i < 8; i++) {
                ull ad = pack2(pv[i], pv[i]);
                FMA2(o2[i][0], ad, v0);
                FMA2(o2[i][1], ad, v1);
            }
        }
    }
    __syncthreads();   // make final l_s visible

    const int b = bh / H_, h = bh % H_;
    #pragma unroll
    for (int i = 0; i < 8; i++) {
        int qrow = (i < 4) ? ty*4 + i : 64 + ty*4 + (i - 4);
        int mm = m0 + qrow;
        if (mm >= S_) continue;
        float inv = 1.f / l_s[qrow];
        float c0, c1, c2, c3;
        unpack2(o2[i][0], c0, c1);
        unpack2(o2[i][1], c2, c3);
        size_t base = ((size_t)b * S_ + mm) * D_ + h * HD_ + tx*4;
        g_ao[base + 0] = c0 * inv;
        g_ao[base + 1] = c1 * inv;
        g_ao[base + 2] = c2 * inv;
        g_ao[base + 3] = c3 * inv;
    }
}

// ---------------------------------------------------------------------------
extern "C" void kernel_launch(void* const* d_in, const int* in_sizes, int n_in,
                              void* d_out, int out_size)
{
    const float* x        = (const float*)d_in[0];
    const float* rope_cos = (const float*)d_in[1];
    const float* rope_sin = (const float*)d_in[2];
    const float* Wq       = (const float*)d_in[3];
    const float* bq       = (const float*)d_in[4];
    const float* Wk       = (const float*)d_in[5];
    const float* Wv       = (const float*)d_in[6];
    const float* bv       = (const float*)d_in[7];
    const float* Wo       = (const float*)d_in[8];
    const float* bo       = (const float*)d_in[9];
    float* out = (float*)d_out;

    cudaFuncSetAttribute(attn_kernel,
        cudaFuncAttributeMaxDynamicSharedMemorySize, ATT_SMEM_BYTES);

    dim3 gg((M_ + 127) / 128, D_ / 128);       // 65 x 8
    gemm128<<<gg, 256>>>(x, Wq, bq,      nullptr, 1);
    gemm128<<<gg, 256>>>(x, Wk, nullptr, nullptr, 2);
    gemm128<<<gg, 256>>>(x, Wv, bv,      nullptr, 3);

    int pairs = B_*H_*S_*32;
    dim3 g2((pairs + 255) / 256, 2);
    rope_kernel<<<g2, 256>>>(rope_cos, rope_sin);

    dim3 g3((S_ + 127) / 128, B_*H_);          // 9 x 128
    attn_kernel<<<g3, 256, ATT_SMEM_BYTES>>>();

    gemm128<<<gg, 256>>>(nullptr, Wo, bo, out, 0);
}

// round 5
// speedup vs baseline: 1.4190x; 1.4190x over previous
#include <cuda_runtime.h>
#include <cuda_bf16.h>
#include <cstdint>

#define B_    8
#define S_    1029
#define D_    1024
#define H_    16
#define HD_   64
#define M_    (B_*S_)     // 8232
#define MPAD  8320        // 65 * 128
#define NPFX  5
#define SCALE_ 0.125f

// ---------------------------------------------------------------------------
// Scratch (device globals — no allocation allowed). .bss is zero-initialized;
// pad rows [M_, MPAD) of the split arrays are never written and stay 0.
// ---------------------------------------------------------------------------
__device__ __align__(16) float g_q [B_*H_*S_*HD_];   // [b,h,s,d]
__device__ __align__(16) float g_k [B_*H_*S_*HD_];
__device__ __align__(16) float g_v [B_*H_*S_*HD_];
__device__ __align__(16) float g_ao[M_*D_];          // attention out [m,n]

__device__ __align__(16) __nv_bfloat16 g_xhi [MPAD*D_];
__device__ __align__(16) __nv_bfloat16 g_xlo [MPAD*D_];
__device__ __align__(16) __nv_bfloat16 g_aohi[MPAD*D_];
__device__ __align__(16) __nv_bfloat16 g_aolo[MPAD*D_];
__device__ __align__(16) __nv_bfloat16 g_wthi[4*D_*D_];   // W^T hi, [w][n][k]
__device__ __align__(16) __nv_bfloat16 g_wtlo[4*D_*D_];   // W^T lo

// ---------------------------------------------------------------------------
// mma.sync helpers (portable PTX — no sm_103a-only features)
// ---------------------------------------------------------------------------
__device__ __forceinline__ uint32_t smem_u32(const void* p) {
    uint32_t a;
    asm("{ .reg .u64 t; cvta.to.shared.u64 t, %1; cvt.u32.u64 %0, t; }"
        : "=r"(a) : "l"(p));
    return a;
}
__device__ __forceinline__ void ldsm4(uint32_t* r, uint32_t addr) {
    asm volatile("ldmatrix.sync.aligned.m8n8.x4.shared.b16 {%0,%1,%2,%3}, [%4];"
        : "=r"(r[0]), "=r"(r[1]), "=r"(r[2]), "=r"(r[3]) : "r"(addr));
}
__device__ __forceinline__ void mma16816(float* c, const uint32_t* a,
                                         const uint32_t* b) {
    asm volatile(
        "mma.sync.aligned.m16n8k16.row.col.f32.bf16.bf16.f32 "
        "{%0,%1,%2,%3}, {%4,%5,%6,%7}, {%8,%9}, {%0,%1,%2,%3};"
        : "+f"(c[0]), "+f"(c[1]), "+f"(c[2]), "+f"(c[3])
        : "r"(a[0]), "r"(a[1]), "r"(a[2]), "r"(a[3]), "r"(b[0]), "r"(b[1]));
}

// ---------------------------------------------------------------------------
// Split activations into bf16 hi/lo. dstsel 0: x-splits, 1: ao-splits
// (src == nullptr reads g_ao).
// ---------------------------------------------------------------------------
__global__ void split_act(const float* __restrict__ src, int dstsel)
{
    const int total4 = M_ * D_ / 4;
    int i = blockIdx.x * blockDim.x + threadIdx.x;
    if (i >= total4) return;
    const float* s = src ? src : g_ao;
    float4 v = ((const float4*)s)[i];
    __nv_bfloat16 h0 = __float2bfloat16(v.x), h1 = __float2bfloat16(v.y);
    __nv_bfloat16 h2 = __float2bfloat16(v.z), h3 = __float2bfloat16(v.w);
    __nv_bfloat16 l0 = __float2bfloat16(v.x - __bfloat162float(h0));
    __nv_bfloat16 l1 = __float2bfloat16(v.y - __bfloat162float(h1));
    __nv_bfloat16 l2 = __float2bfloat16(v.z - __bfloat162float(h2));
    __nv_bfloat16 l3 = __float2bfloat16(v.w - __bfloat162float(h3));
    __nv_bfloat162* Hi = (__nv_bfloat162*)(dstsel ? g_aohi : g_xhi);
    __nv_bfloat162* Lo = (__nv_bfloat162*)(dstsel ? g_aolo : g_xlo);
    Hi[2*i]   = __nv_bfloat162(h0, h1);
    Hi[2*i+1] = __nv_bfloat162(h2, h3);
    Lo[2*i]   = __nv_bfloat162(l0, l1);
    Lo[2*i+1] = __nv_bfloat162(l2, l3);
}

// ---------------------------------------------------------------------------
// Transpose + split a weight: W[k][n] fp32 -> Wt_hi/lo[n][k] bf16 at slot widx
// ---------------------------------------------------------------------------
__global__ void split_w(const float* __restrict__ W, int widx)
{
    __shared__ float t[32][33];
    int n0 = blockIdx.x * 32, k0 = blockIdx.y * 32;
    int tx = threadIdx.x, ty = threadIdx.y;   // 32 x 8
    #pragma unroll
    for (int i = 0; i < 4; i++)
        t[ty + 8*i][tx] = W[(size_t)(k0 + ty + 8*i) * D_ + n0 + tx];  // t[k][n]
    __syncthreads();
    __nv_bfloat16* Hi = g_wthi + (size_t)widx * D_ * D_;
    __nv_bfloat16* Lo = g_wtlo + (size_t)widx * D_ * D_;
    #pragma unroll
    for (int i = 0; i < 4; i++) {
        float v = t[tx][ty + 8*i];            // = W[k0+tx][n0+ty+8i]
        __nv_bfloat16 h = __float2bfloat16(v);
        size_t o = (size_t)(n0 + ty + 8*i) * D_ + k0 + tx;
        Hi[o] = h;
        Lo[o] = __float2bfloat16(v - __bfloat162float(h));
    }
}

// ---------------------------------------------------------------------------
// Tensor-core GEMM via mma.sync: C[m][n] = sum_k A[m][k] * W[k][n], 3-term
// bf16 split (hi*hi + lo*hi + hi*lo). Tile 128x128, BK=32, double-buffered.
// 8 warps in 2(m) x 4(n); warp tile 64x32. Smem rows stride 40 bf16 (80B)
// for conflict-free ldmatrix.
// asel: 0 = x splits, 1 = ao splits. mode 0: dst[m*D+n]; 1/2/3: g_q/g_k/g_v.
// ---------------------------------------------------------------------------
#define ASTRIDE 40
#define BUFELEM (128*ASTRIDE)

__global__ __launch_bounds__(256) void mma_gemm(
    int asel, int widx, const float* __restrict__ bias,
    float* __restrict__ dst, int mode)
{
    __shared__ __align__(16) __nv_bfloat16 As[2][BUFELEM];
    __shared__ __align__(16) __nv_bfloat16 Bs[2][BUFELEM];

    const int tid  = threadIdx.x;
    const int lane = tid & 31, wid = tid >> 5;
    const int wm = wid & 1, wn = wid >> 1;    // 2 x 4 warp grid
    const int bm = blockIdx.x * 128, bn = blockIdx.y * 128;

    const __nv_bfloat16* Ahi = asel ? g_aohi : g_xhi;
    const __nv_bfloat16* Alo = asel ? g_aolo : g_xlo;
    const __nv_bfloat16* Bhi = g_wthi + (size_t)widx * D_ * D_;
    const __nv_bfloat16* Blo = g_wtlo + (size_t)widx * D_ * D_;

    float acc[4][4][4] = {};

    // prologue: chunk 0 (pass 0: Ahi/Bhi, k0 = 0)
    #pragma unroll
    for (int it = 0; it < 2; it++) {
        int idx = tid + it * 256;
        int r = idx >> 2, c8 = (idx & 3) * 8;
        *(uint4*)&As[0][r*ASTRIDE + c8] =
            *(const uint4*)(Ahi + (size_t)(bm + r) * D_ + c8);
        *(uint4*)&Bs[0][r*ASTRIDE + c8] =
            *(const uint4*)(Bhi + (size_t)(bn + r) * D_ + c8);
    }
    __syncthreads();

    const uint32_t aB = smem_u32(&As[0][0]);
    const uint32_t bB = smem_u32(&Bs[0][0]);
    // ldmatrix lane addressing (byte offsets; row stride 80B)
    const uint32_t aOff = (uint32_t)(wm*64 + (lane & 15)) * 80 + (lane >> 4) * 16;
    const uint32_t bOff = (uint32_t)(wn*32 + (lane & 7) + ((lane >> 4) << 3)) * 80
                          + ((lane >> 3) & 1) * 16;
    const uint32_t BUFB = BUFELEM * 2;   // bytes per buffer

    const int NCH = 96;                  // 3 passes x 32 chunks
    uint4 pa[2], pb[2];
    for (int t = 0; t < NCH; t++) {
        int buf = t & 1;
        if (t + 1 < NCH) {
            int tp = t + 1;
            int pass = tp >> 5;
            int k0 = (tp & 31) * 32;
            const __nv_bfloat16* Ap = (pass == 1) ? Alo : Ahi;
            const __nv_bfloat16* Bp = (pass == 2) ? Blo : Bhi;
            #pragma unroll
            for (int it = 0; it < 2; it++) {
                int idx = tid + it * 256;
                int r = idx >> 2, c8 = (idx & 3) * 8;
                pa[it] = *(const uint4*)(Ap + (size_t)(bm + r) * D_ + k0 + c8);
                pb[it] = *(const uint4*)(Bp + (size_t)(bn + r) * D_ + k0 + c8);
            }
        }
        uint32_t ab = aB + buf * BUFB;
        uint32_t bb = bB + buf * BUFB;
        #pragma unroll
        for (int ks = 0; ks < 2; ks++) {
            uint32_t af[4][4], bf[2][4];
            #pragma unroll
            for (int mt = 0; mt < 4; mt++)
                ldsm4(af[mt], ab + aOff + mt * 16 * 80 + ks * 32);
            #pragma unroll
            for (int bt = 0; bt < 2; bt++)
                ldsm4(bf[bt], bb + bOff + bt * 16 * 80 + ks * 32);
            #pragma unroll
            for (int mt = 0; mt < 4; mt++)
                #pragma unroll
                for (int nt = 0; nt < 4; nt++)
                    mma16816(acc[mt][nt], af[mt], &bf[nt >> 1][(nt & 1) * 2]);
        }
        if (t + 1 < NCH) {
            int nb = buf ^ 1;
            #pragma unroll
            for (int it = 0; it < 2; it++) {
                int idx = tid + it * 256;
                int r = idx >> 2, c8 = (idx & 3) * 8;
                *(uint4*)&As[nb][r*ASTRIDE + c8] = pa[it];
                *(uint4*)&Bs[nb][r*ASTRIDE + c8] = pb[it];
            }
        }
        __syncthreads();
    }

    // epilogue: fragment layout c0,c1 -> (rg, cp..cp+1); c2,c3 -> (rg+8, ...)
    const int rg = lane >> 2, cp = (lane & 3) * 2;
    #pragma unroll
    for (int mt = 0; mt < 4; mt++) {
        #pragma unroll
        for (int nt = 0; nt < 4; nt++) {
            int n = bn + wn*32 + nt*8 + cp;
            float b0v = bias ? __ldg(bias + n)     : 0.f;
            float b1v = bias ? __ldg(bias + n + 1) : 0.f;
            #pragma unroll
            for (int h2 = 0; h2 < 2; h2++) {
                int m = bm + wm*64 + mt*16 + rg + h2*8;
                if (m >= M_) continue;
                float v0 = acc[mt][nt][h2*2 + 0] + b0v;
                float v1 = acc[mt][nt][h2*2 + 1] + b1v;
                if (mode == 0) {
                    dst[(size_t)m * D_ + n]     = v0;
                    dst[(size_t)m * D_ + n + 1] = v1;
                } else {
                    int b = m / S_, s = m % S_;
                    int h = n >> 6, d = n & 63;   // d <= 62, d+1 same head
                    float* g = (mode == 1) ? g_q : (mode == 2) ? g_k : g_v;
                    size_t o = (((size_t)(b * H_ + h)) * S_ + s) * HD_ + d;
                    g[o]     = v0;
                    g[o + 1] = v1;
                }
            }
        }
    }
}

// ---------------------------------------------------------------------------
// RoPE (patch tokens only) + q-scale (all tokens).
// ---------------------------------------------------------------------------
__global__ void rope_kernel(const float* __restrict__ cosp,
                            const float* __restrict__ sinp)
{
    const int total = B_*H_*S_*32;
    int i = blockIdx.x * blockDim.x + threadIdx.x;
    if (i >= total) return;
    const bool isQ = (blockIdx.y == 0);
    int dh = i & 31;
    int s  = (i >> 5) % S_;
    int bh = i / (32 * S_);
    float* ptr = (isQ ? g_q : g_k) + ((size_t)bh * S_ + s) * HD_;
    if (s < NPFX) {
        if (isQ) { ptr[dh] *= SCALE_; ptr[dh+32] *= SCALE_; }
        return;
    }
    int p = s - NPFX;
    float c0 = cosp[p*HD_ + dh],      c1 = cosp[p*HD_ + dh + 32];
    float s0 = sinp[p*HD_ + dh],      s1 = sinp[p*HD_ + dh + 32];
    float x0 = ptr[dh], x1 = ptr[dh+32];
    float y0 = x0*c0 - x1*s0;
    float y1 = x1*c1 + x0*s1;
    if (isQ) { y0 *= SCALE_; y1 *= SCALE_; }
    ptr[dh]    = y0;
    ptr[dh+32] = y1;
}

// ---------------------------------------------------------------------------
// fp32 flash attention (proven R2 version). CTA = (b*h, 64-row Q tile).
// ---------------------------------------------------------------------------
#define PADS 68
#define ATT_SMEM_BYTES ((64*PADS*3 + 64*64 + 64*3 + 64*8) * 4)   // 71424

__global__ __launch_bounds__(256) void attn_kernel()
{
    extern __shared__ float sm[];
    float* Qs   = sm;                 // [64][PADS]  (d, m)
    float* Ks   = Qs + 64*PADS;       // [64][PADS]  (d, n)
    float* St   = Ks + 64*PADS;       // [64][PADS]  (n, m)
    float* Vs   = St + 64*PADS;       // [64][64]    (n, d)
    float* m_s  = Vs + 64*64;
    float* l_s  = m_s + 64;
    float* al_s = l_s + 64;
    float* redm = al_s + 64;          // [4][64]
    float* reds = redm + 256;         // [4][64]

    const int tid = threadIdx.x;
    const int tx = tid & 15, ty = tid >> 4;
    const int bh = blockIdx.y;
    const int m0 = blockIdx.x * 64;
    const float* qp = g_q + (size_t)bh * S_ * HD_;
    const float* kp = g_k + (size_t)bh * S_ * HD_;
    const float* vp = g_v + (size_t)bh * S_ * HD_;

    #pragma unroll
    for (int t = 0; t < 16; t++) {
        int i  = tid + t * 256;
        int mm = i >> 6, d = i & 63;
        float val = 0.f;
        if (m0 + mm < S_) val = qp[(size_t)(m0 + mm) * HD_ + d];
        Qs[d*PADS + mm] = val;
    }
    if (tid < 64) { m_s[tid] = -1e30f; l_s[tid] = 0.f; }

    float o[4][4] = {};
    const int r = tid & 63, part = tid >> 6;

    for (int n0 = 0; n0 < S_; n0 += 64) {
        __syncthreads();
        #pragma unroll
        for (int t = 0; t < 16; t++) {
            int i  = tid + t * 256;
            int nn = i >> 6, d = i & 63;
            float kv = 0.f, vv = 0.f;
            if (n0 + nn < S_) {
                size_t off = (size_t)(n0 + nn) * HD_ + d;
                kv = kp[off];
                vv = vp[off];
            }
            Ks[d*PADS + nn] = kv;
            Vs[nn*64 + d] = vv;
        }
        __syncthreads();

        float s_[4][4] = {};
        #pragma unroll
        for (int d = 0; d < 64; d++) {
            float4 a4 = *(float4*)&Qs[d*PADS + ty*4];
            float4 b4 = *(float4*)&Ks[d*PADS + tx*4];
            const float* a = (const float*)&a4;
            const float* b = (const float*)&b4;
            #pragma unroll
            for (int i = 0; i < 4; i++)
                #pragma unroll
                for (int j = 0; j < 4; j++)
                    s_[i][j] = fmaf(a[i], b[j], s_[i][j]);
        }
        #pragma unroll
        for (int j = 0; j < 4; j++) {
            int n = tx*4 + j;
            bool valid = (n0 + n) < S_;
            #pragma unroll
            for (int i = 0; i < 4; i++)
                St[n*PADS + ty*4 + i] = valid ? s_[i][j] : -1e30f;
        }
        __syncthreads();

        {
            float pm = -1e30f;
            #pragma unroll
            for (int n = part*16; n < part*16 + 16; n++)
                pm = fmaxf(pm, St[n*PADS + r]);
            redm[part*64 + r] = pm;
        }
        __syncthreads();
        if (part == 0) {
            float nm = fmaxf(fmaxf(redm[r], redm[64+r]),
                             fmaxf(redm[128+r], redm[192+r]));
            nm = fmaxf(nm, m_s[r]);
            al_s[r] = __expf(m_s[r] - nm);
            m_s[r]  = nm;
        }
        __syncthreads();
        {
            float mr = m_s[r];
            float ps = 0.f;
            #pragma unroll
            for (int n = part*16; n < part*16 + 16; n++) {
                float e = __expf(St[n*PADS + r] - mr);
                St[n*PADS + r] = e;
                ps += e;
            }
            reds[part*64 + r] = ps;
        }
        __syncthreads();
        if (part == 0)
            l_s[r] = l_s[r]*al_s[r] + reds[r] + reds[64+r] + reds[128+r] + reds[192+r];

        {
            float alpha[4];
            #pragma unroll
            for (int i = 0; i < 4; i++) alpha[i] = al_s[ty*4 + i];
            #pragma unroll
            for (int i = 0; i < 4; i++)
                #pragma unroll
                for (int j = 0; j < 4; j++)
                    o[i][j] *= alpha[i];
            #pragma unroll
            for (int n = 0; n < 64; n++) {
                float4 p4 = *(float4*)&St[n*PADS + ty*4];
                float4 v4 = *(float4*)&Vs[n*64 + tx*4];
                const float* p = (const float*)&p4;
                const float* v = (const float*)&v4;
                #pragma unroll
                for (int i = 0; i < 4; i++)
                    #pragma unroll
                    for (int j = 0; j < 4; j++)
                        o[i][j] = fmaf(p[i], v[j], o[i][j]);
            }
        }
    }
    __syncthreads();

    const int b = bh / H_, h = bh % H_;
    #pragma unroll
    for (int i = 0; i < 4; i++) {
        int mm = m0 + ty*4 + i;
        if (mm >= S_) continue;
        float inv = 1.f / l_s[ty*4 + i];
        size_t base = ((size_t)b * S_ + mm) * D_ + h * HD_ + tx*4;
        #pragma unroll
        for (int j = 0; j < 4; j++)
            g_ao[base + j] = o[i][j] * inv;
    }
}

// ---------------------------------------------------------------------------
extern "C" void kernel_launch(void* const* d_in, const int* in_sizes, int n_in,
                              void* d_out, int out_size)
{
    const float* x        = (const float*)d_in[0];
    const float* rope_cos = (const float*)d_in[1];
    const float* rope_sin = (const float*)d_in[2];
    const float* Wq       = (const float*)d_in[3];
    const float* bq       = (const float*)d_in[4];
    const float* Wk       = (const float*)d_in[5];
    const float* Wv       = (const float*)d_in[6];
    const float* bv       = (const float*)d_in[7];
    const float* Wo       = (const float*)d_in[8];
    const float* bo       = (const float*)d_in[9];
    float* out = (float*)d_out;

    cudaFuncSetAttribute(attn_kernel,
        cudaFuncAttributeMaxDynamicSharedMemorySize, ATT_SMEM_BYTES);

    // conversions
    int t4 = M_ * D_ / 4;
    split_act<<<(t4 + 255) / 256, 256>>>(x, 0);
    dim3 wg(32, 32), wb(32, 8);
    split_w<<<wg, wb>>>(Wq, 0);
    split_w<<<wg, wb>>>(Wk, 1);
    split_w<<<wg, wb>>>(Wv, 2);
    split_w<<<wg, wb>>>(Wo, 3);

    // QKV projections (tensor core mma.sync)
    dim3 gg(MPAD / 128, D_ / 128);             // 65 x 8
    mma_gemm<<<gg, 256>>>(0, 0, bq,      nullptr, 1);
    mma_gemm<<<gg, 256>>>(0, 1, nullptr, nullptr, 2);
    mma_gemm<<<gg, 256>>>(0, 2, bv,      nullptr, 3);

    int pairs = B_*H_*S_*32;
    dim3 g2((pairs + 255) / 256, 2);
    rope_kernel<<<g2, 256>>>(rope_cos, rope_sin);

    dim3 g3((S_ + 63) / 64, B_*H_);            // 17 x 128
    attn_kernel<<<g3, 256, ATT_SMEM_BYTES>>>();

    // output projection
    split_act<<<(t4 + 255) / 256, 256>>>(nullptr, 1);
    mma_gemm<<<gg, 256>>>(1, 3, bo, out, 0);
}

// round 6
// speedup vs baseline: 1.8840x; 1.3277x over previous
#include <cuda_runtime.h>
#include <cuda_bf16.h>
#include <cuda_fp16.h>
#include <cstdint>

#define B_    8
#define S_    1029
#define D_    1024
#define H_    16
#define HD_   64
#define M_    (B_*S_)     // 8232
#define MPAD  8320        // 65 * 128
#define NPFX  5
#define SCALE_ 0.125f

// ---------------------------------------------------------------------------
// Scratch (device globals — no allocation allowed). .bss is zero-initialized;
// pad rows [M_, MPAD) of the split arrays are never written and stay 0.
// ---------------------------------------------------------------------------
__device__ __align__(16) float g_q [B_*H_*S_*HD_];   // [b,h,s,d]
__device__ __align__(16) float g_k [B_*H_*S_*HD_];
__device__ __align__(16) float g_v [B_*H_*S_*HD_];
__device__ __align__(16) float g_ao[M_*D_];          // attention out [m,n]

__device__ __align__(16) __nv_bfloat16 g_xhi [MPAD*D_];
__device__ __align__(16) __nv_bfloat16 g_xlo [MPAD*D_];
__device__ __align__(16) __nv_bfloat16 g_aohi[MPAD*D_];
__device__ __align__(16) __nv_bfloat16 g_aolo[MPAD*D_];
__device__ __align__(16) __nv_bfloat16 g_wthi[4*D_*D_];   // W^T hi, [w][n][k]
__device__ __align__(16) __nv_bfloat16 g_wtlo[4*D_*D_];   // W^T lo

// ---------------------------------------------------------------------------
// mma.sync helpers (portable PTX — no sm_103a-only features)
// ---------------------------------------------------------------------------
__device__ __forceinline__ uint32_t smem_u32(const void* p) {
    uint32_t a;
    asm("{ .reg .u64 t; cvta.to.shared.u64 t, %1; cvt.u32.u64 %0, t; }"
        : "=r"(a) : "l"(p));
    return a;
}
__device__ __forceinline__ void ldsm4(uint32_t* r, uint32_t addr) {
    asm volatile("ldmatrix.sync.aligned.m8n8.x4.shared.b16 {%0,%1,%2,%3}, [%4];"
        : "=r"(r[0]), "=r"(r[1]), "=r"(r[2]), "=r"(r[3]) : "r"(addr));
}
__device__ __forceinline__ void mma16816(float* c, const uint32_t* a,
                                         const uint32_t* b) {
    asm volatile(
        "mma.sync.aligned.m16n8k16.row.col.f32.bf16.bf16.f32 "
        "{%0,%1,%2,%3}, {%4,%5,%6,%7}, {%8,%9}, {%0,%1,%2,%3};"
        : "+f"(c[0]), "+f"(c[1]), "+f"(c[2]), "+f"(c[3])
        : "r"(a[0]), "r"(a[1]), "r"(a[2]), "r"(a[3]), "r"(b[0]), "r"(b[1]));
}
__device__ __forceinline__ void mmah16816(float* c, const uint32_t* a,
                                          const uint32_t* b) {
    asm volatile(
        "mma.sync.aligned.m16n8k16.row.col.f32.f16.f16.f32 "
        "{%0,%1,%2,%3}, {%4,%5,%6,%7}, {%8,%9}, {%0,%1,%2,%3};"
        : "+f"(c[0]), "+f"(c[1]), "+f"(c[2]), "+f"(c[3])
        : "r"(a[0]), "r"(a[1]), "r"(a[2]), "r"(a[3]), "r"(b[0]), "r"(b[1]));
}

// ---------------------------------------------------------------------------
// Split activations into bf16 hi/lo. dstsel 0: x-splits, 1: ao-splits.
// ---------------------------------------------------------------------------
__global__ void split_act(const float* __restrict__ src, int dstsel)
{
    const int total4 = M_ * D_ / 4;
    int i = blockIdx.x * blockDim.x + threadIdx.x;
    if (i >= total4) return;
    const float* s = src ? src : g_ao;
    float4 v = ((const float4*)s)[i];
    __nv_bfloat16 h0 = __float2bfloat16(v.x), h1 = __float2bfloat16(v.y);
    __nv_bfloat16 h2 = __float2bfloat16(v.z), h3 = __float2bfloat16(v.w);
    __nv_bfloat16 l0 = __float2bfloat16(v.x - __bfloat162float(h0));
    __nv_bfloat16 l1 = __float2bfloat16(v.y - __bfloat162float(h1));
    __nv_bfloat16 l2 = __float2bfloat16(v.z - __bfloat162float(h2));
    __nv_bfloat16 l3 = __float2bfloat16(v.w - __bfloat162float(h3));
    __nv_bfloat162* Hi = (__nv_bfloat162*)(dstsel ? g_aohi : g_xhi);
    __nv_bfloat162* Lo = (__nv_bfloat162*)(dstsel ? g_aolo : g_xlo);
    Hi[2*i]   = __nv_bfloat162(h0, h1);
    Hi[2*i+1] = __nv_bfloat162(h2, h3);
    Lo[2*i]   = __nv_bfloat162(l0, l1);
    Lo[2*i+1] = __nv_bfloat162(l2, l3);
}

// ---------------------------------------------------------------------------
// Transpose + split a weight: W[k][n] fp32 -> Wt_hi/lo[n][k] bf16 at slot widx
// ---------------------------------------------------------------------------
__global__ void split_w(const float* __restrict__ W, int widx)
{
    __shared__ float t[32][33];
    int n0 = blockIdx.x * 32, k0 = blockIdx.y * 32;
    int tx = threadIdx.x, ty = threadIdx.y;   // 32 x 8
    #pragma unroll
    for (int i = 0; i < 4; i++)
        t[ty + 8*i][tx] = W[(size_t)(k0 + ty + 8*i) * D_ + n0 + tx];
    __syncthreads();
    __nv_bfloat16* Hi = g_wthi + (size_t)widx * D_ * D_;
    __nv_bfloat16* Lo = g_wtlo + (size_t)widx * D_ * D_;
    #pragma unroll
    for (int i = 0; i < 4; i++) {
        float v = t[tx][ty + 8*i];
        __nv_bfloat16 h = __float2bfloat16(v);
        size_t o = (size_t)(n0 + ty + 8*i) * D_ + k0 + tx;
        Hi[o] = h;
        Lo[o] = __float2bfloat16(v - __bfloat162float(h));
    }
}

// ---------------------------------------------------------------------------
// Tensor-core GEMM (proven R5 engine). Tile 128x128, BK=32, double-buffered.
// ---------------------------------------------------------------------------
#define ASTRIDE 40
#define BUFELEM (128*ASTRIDE)

__global__ __launch_bounds__(256) void mma_gemm(
    int asel, int widx, const float* __restrict__ bias,
    float* __restrict__ dst, int mode)
{
    __shared__ __align__(16) __nv_bfloat16 As[2][BUFELEM];
    __shared__ __align__(16) __nv_bfloat16 Bs[2][BUFELEM];

    const int tid  = threadIdx.x;
    const int lane = tid & 31, wid = tid >> 5;
    const int wm = wid & 1, wn = wid >> 1;
    const int bm = blockIdx.x * 128, bn = blockIdx.y * 128;

    const __nv_bfloat16* Ahi = asel ? g_aohi : g_xhi;
    const __nv_bfloat16* Alo = asel ? g_aolo : g_xlo;
    const __nv_bfloat16* Bhi = g_wthi + (size_t)widx * D_ * D_;
    const __nv_bfloat16* Blo = g_wtlo + (size_t)widx * D_ * D_;

    float acc[4][4][4] = {};

    #pragma unroll
    for (int it = 0; it < 2; it++) {
        int idx = tid + it * 256;
        int r = idx >> 2, c8 = (idx & 3) * 8;
        *(uint4*)&As[0][r*ASTRIDE + c8] =
            *(const uint4*)(Ahi + (size_t)(bm + r) * D_ + c8);
        *(uint4*)&Bs[0][r*ASTRIDE + c8] =
            *(const uint4*)(Bhi + (size_t)(bn + r) * D_ + c8);
    }
    __syncthreads();

    const uint32_t aB = smem_u32(&As[0][0]);
    const uint32_t bB = smem_u32(&Bs[0][0]);
    const uint32_t aOff = (uint32_t)(wm*64 + (lane & 15)) * 80 + (lane >> 4) * 16;
    const uint32_t bOff = (uint32_t)(wn*32 + (lane & 7) + ((lane >> 4) << 3)) * 80
                          + ((lane >> 3) & 1) * 16;
    const uint32_t BUFB = BUFELEM * 2;

    const int NCH = 96;
    uint4 pa[2], pb[2];
    for (int t = 0; t < NCH; t++) {
        int buf = t & 1;
        if (t + 1 < NCH) {
            int tp = t + 1;
            int pass = tp >> 5;
            int k0 = (tp & 31) * 32;
            const __nv_bfloat16* Ap = (pass == 1) ? Alo : Ahi;
            const __nv_bfloat16* Bp = (pass == 2) ? Blo : Bhi;
            #pragma unroll
            for (int it = 0; it < 2; it++) {
                int idx = tid + it * 256;
                int r = idx >> 2, c8 = (idx & 3) * 8;
                pa[it] = *(const uint4*)(Ap + (size_t)(bm + r) * D_ + k0 + c8);
                pb[it] = *(const uint4*)(Bp + (size_t)(bn + r) * D_ + k0 + c8);
            }
        }
        uint32_t ab = aB + buf * BUFB;
        uint32_t bb = bB + buf * BUFB;
        #pragma unroll
        for (int ks = 0; ks < 2; ks++) {
            uint32_t af[4][4], bf[2][4];
            #pragma unroll
            for (int mt = 0; mt < 4; mt++)
                ldsm4(af[mt], ab + aOff + mt * 16 * 80 + ks * 32);
            #pragma unroll
            for (int bt = 0; bt < 2; bt++)
                ldsm4(bf[bt], bb + bOff + bt * 16 * 80 + ks * 32);
            #pragma unroll
            for (int mt = 0; mt < 4; mt++)
                #pragma unroll
                for (int nt = 0; nt < 4; nt++)
                    mma16816(acc[mt][nt], af[mt], &bf[nt >> 1][(nt & 1) * 2]);
        }
        if (t + 1 < NCH) {
            int nb = buf ^ 1;
            #pragma unroll
            for (int it = 0; it < 2; it++) {
                int idx = tid + it * 256;
                int r = idx >> 2, c8 = (idx & 3) * 8;
                *(uint4*)&As[nb][r*ASTRIDE + c8] = pa[it];
                *(uint4*)&Bs[nb][r*ASTRIDE + c8] = pb[it];
            }
        }
        __syncthreads();
    }

    const int rg = lane >> 2, cp = (lane & 3) * 2;
    #pragma unroll
    for (int mt = 0; mt < 4; mt++) {
        #pragma unroll
        for (int nt = 0; nt < 4; nt++) {
            int n = bn + wn*32 + nt*8 + cp;
            float b0v = bias ? __ldg(bias + n)     : 0.f;
            float b1v = bias ? __ldg(bias + n + 1) : 0.f;
            #pragma unroll
            for (int h2 = 0; h2 < 2; h2++) {
                int m = bm + wm*64 + mt*16 + rg + h2*8;
                if (m >= M_) continue;
                float v0 = acc[mt][nt][h2*2 + 0] + b0v;
                float v1 = acc[mt][nt][h2*2 + 1] + b1v;
                if (mode == 0) {
                    dst[(size_t)m * D_ + n]     = v0;
                    dst[(size_t)m * D_ + n + 1] = v1;
                } else {
                    int b = m / S_, s = m % S_;
                    int h = n >> 6, d = n & 63;
                    float* g = (mode == 1) ? g_q : (mode == 2) ? g_k : g_v;
                    size_t o = (((size_t)(b * H_ + h)) * S_ + s) * HD_ + d;
                    g[o]     = v0;
                    g[o + 1] = v1;
                }
            }
        }
    }
}

// ---------------------------------------------------------------------------
// RoPE (patch tokens only) + q-scale (all tokens).
// ---------------------------------------------------------------------------
__global__ void rope_kernel(const float* __restrict__ cosp,
                            const float* __restrict__ sinp)
{
    const int total = B_*H_*S_*32;
    int i = blockIdx.x * blockDim.x + threadIdx.x;
    if (i >= total) return;
    const bool isQ = (blockIdx.y == 0);
    int dh = i & 31;
    int s  = (i >> 5) % S_;
    int bh = i / (32 * S_);
    float* ptr = (isQ ? g_q : g_k) + ((size_t)bh * S_ + s) * HD_;
    if (s < NPFX) {
        if (isQ) { ptr[dh] *= SCALE_; ptr[dh+32] *= SCALE_; }
        return;
    }
    int p = s - NPFX;
    float c0 = cosp[p*HD_ + dh],      c1 = cosp[p*HD_ + dh + 32];
    float s0 = sinp[p*HD_ + dh],      s1 = sinp[p*HD_ + dh + 32];
    float x0 = ptr[dh], x1 = ptr[dh+32];
    float y0 = x0*c0 - x1*s0;
    float y1 = x1*c1 + x0*s1;
    if (isQ) { y0 *= SCALE_; y1 *= SCALE_; }
    ptr[dh]    = y0;
    ptr[dh+32] = y1;
}

// ---------------------------------------------------------------------------
// Tensor-core flash attention. CTA = (b*h, 64-query tile); 64-key tiles.
// QK: fp16 split 3-term. PV: P fp16 single, V fp16 split 2-term.
// 8 warps in 2(m) x 4(n). fp16 smem stride 72 halves (144 B, 16B-aligned).
// ---------------------------------------------------------------------------
#define QST 72
#define SST 73
#define ATT_SMEM (7*64*QST*2 + 64*SST*4 + (3*64 + 512)*4)   // 86016

__global__ __launch_bounds__(256) void attn_kernel()
{
    extern __shared__ char smx[];
    __half* Qhi  = (__half*)smx;            // [64][QST]  (q, d)
    __half* Qlo  = Qhi  + 64*QST;
    __half* Khi  = Qlo  + 64*QST;           // [64][QST]  (key, d)
    __half* Klo  = Khi  + 64*QST;
    __half* Vthi = Klo  + 64*QST;           // [64][QST]  (d, key)
    __half* Vtlo = Vthi + 64*QST;
    __half* Pm   = Vtlo + 64*QST;           // [64][QST]  (q, key)
    float*  S32  = (float*)(Pm + 64*QST);   // [64][SST]  (q, key)
    float*  m_s  = S32 + 64*SST;            // [64]
    float*  l_s  = m_s + 64;
    float*  al_s = l_s + 64;
    float*  redm = al_s + 64;               // [4][64]
    float*  reds = redm + 256;              // [4][64]

    const int tid  = threadIdx.x;
    const int lane = tid & 31, wid = tid >> 5;
    const int wm = wid & 1, wn = wid >> 1;     // 2 x 4 warp grid
    const int rg = lane >> 2, cp = (lane & 3) * 2;
    const int bh = blockIdx.y;
    const int m0 = blockIdx.x * 64;
    const float* qp = g_q + (size_t)bh * S_ * HD_;
    const float* kp = g_k + (size_t)bh * S_ * HD_;
    const float* vp = g_v + (size_t)bh * S_ * HD_;

    // load + split Q tile (q already scaled)
    #pragma unroll
    for (int it = 0; it < 4; it++) {
        int idx = tid + it * 256;              // 0..1023
        int r = idx >> 4, c4 = (idx & 15) * 4;
        float4 v = make_float4(0.f, 0.f, 0.f, 0.f);
        if (m0 + r < S_) v = *(const float4*)(qp + (size_t)(m0 + r) * HD_ + c4);
        __half h0 = __float2half_rn(v.x), h1 = __float2half_rn(v.y);
        __half h2 = __float2half_rn(v.z), h3 = __float2half_rn(v.w);
        *(__half2*)&Qhi[r*QST + c4]     = __halves2half2(h0, h1);
        *(__half2*)&Qhi[r*QST + c4 + 2] = __halves2half2(h2, h3);
        *(__half2*)&Qlo[r*QST + c4]     = __halves2half2(
            __float2half_rn(v.x - __half2float(h0)),
            __float2half_rn(v.y - __half2float(h1)));
        *(__half2*)&Qlo[r*QST + c4 + 2] = __halves2half2(
            __float2half_rn(v.z - __half2float(h2)),
            __float2half_rn(v.w - __half2float(h3)));
    }
    if (tid < 64) { m_s[tid] = -1e30f; l_s[tid] = 0.f; }

    const uint32_t QhiB = smem_u32(Qhi),  QloB = smem_u32(Qlo);
    const uint32_t KhiB = smem_u32(Khi),  KloB = smem_u32(Klo);
    const uint32_t VhiB = smem_u32(Vthi), VloB = smem_u32(Vtlo);
    const uint32_t PmB  = smem_u32(Pm);
    const uint32_t aOff = (uint32_t)(wm*32 + (lane & 15)) * 144 + (lane >> 4) * 16;
    const uint32_t bOff = (uint32_t)(wn*16 + (lane & 7) + ((lane >> 4) << 3)) * 144
                          + ((lane >> 3) & 1) * 16;

    float oacc[2][2][4] = {};
    const int sq = tid & 63, part = tid >> 6;

    for (int n0 = 0; n0 < S_; n0 += 64) {
        __syncthreads();   // protects K/V/P reuse + first-iter init
        // load + split K tile [key][d]
        #pragma unroll
        for (int it = 0; it < 4; it++) {
            int idx = tid + it * 256;
            int r = idx >> 4, c4 = (idx & 15) * 4;
            float4 v = make_float4(0.f, 0.f, 0.f, 0.f);
            if (n0 + r < S_) v = *(const float4*)(kp + (size_t)(n0 + r) * HD_ + c4);
            __half h0 = __float2half_rn(v.x), h1 = __float2half_rn(v.y);
            __half h2 = __float2half_rn(v.z), h3 = __float2half_rn(v.w);
            *(__half2*)&Khi[r*QST + c4]     = __halves2half2(h0, h1);
            *(__half2*)&Khi[r*QST + c4 + 2] = __halves2half2(h2, h3);
            *(__half2*)&Klo[r*QST + c4]     = __halves2half2(
                __float2half_rn(v.x - __half2float(h0)),
                __float2half_rn(v.y - __half2float(h1)));
            *(__half2*)&Klo[r*QST + c4 + 2] = __halves2half2(
                __float2half_rn(v.z - __half2float(h2)),
                __float2half_rn(v.w - __half2float(h3)));
        }
        // load + split + transpose V tile -> Vt[d][key]
        #pragma unroll
        for (int it = 0; it < 4; it++) {
            int idx = tid + it * 256;
            int n = idx & 63, c4 = (idx >> 6) * 4;
            float4 v = make_float4(0.f, 0.f, 0.f, 0.f);
            if (n0 + n < S_) v = *(const float4*)(vp + (size_t)(n0 + n) * HD_ + c4);
            const float* vf = (const float*)&v;
            #pragma unroll
            for (int j = 0; j < 4; j++) {
                __half h = __float2half_rn(vf[j]);
                Vthi[(c4 + j)*QST + n] = h;
                Vtlo[(c4 + j)*QST + n] =
                    __float2half_rn(vf[j] - __half2float(h));
            }
        }
        __syncthreads();

        // S = Q K^T (3-term split)
        float sacc[2][2][4] = {};
        #pragma unroll
        for (int ks = 0; ks < 4; ks++) {
            uint32_t ah[2][4], al[2][4], bhh[4], bll[4];
            #pragma unroll
            for (int mt = 0; mt < 2; mt++) {
                ldsm4(ah[mt], QhiB + aOff + mt * 16 * 144 + ks * 32);
                ldsm4(al[mt], QloB + aOff + mt * 16 * 144 + ks * 32);
            }
            ldsm4(bhh, KhiB + bOff + ks * 32);
            ldsm4(bll, KloB + bOff + ks * 32);
            #pragma unroll
            for (int mt = 0; mt < 2; mt++)
                #pragma unroll
                for (int nt = 0; nt < 2; nt++) {
                    mmah16816(sacc[mt][nt], ah[mt], &bhh[nt*2]);
                    mmah16816(sacc[mt][nt], al[mt], &bhh[nt*2]);
                    mmah16816(sacc[mt][nt], ah[mt], &bll[nt*2]);
                }
        }
        // store S frags (scalar; odd stride keeps softmax ~conflict-free)
        #pragma unroll
        for (int mt = 0; mt < 2; mt++)
            #pragma unroll
            for (int nt = 0; nt < 2; nt++) {
                int q0 = wm*32 + mt*16 + rg;
                int kc = wn*16 + nt*8 + cp;
                S32[q0*SST + kc]       = sacc[mt][nt][0];
                S32[q0*SST + kc + 1]   = sacc[mt][nt][1];
                S32[(q0+8)*SST + kc]     = sacc[mt][nt][2];
                S32[(q0+8)*SST + kc + 1] = sacc[mt][nt][3];
            }
        __syncthreads();

        // per-query max over this tile (4 partials)
        {
            float pm = -1e30f;
            #pragma unroll
            for (int i = 0; i < 16; i++) {
                int kk = part*16 + i;
                float v = S32[sq*SST + kk];
                pm = fmaxf(pm, (n0 + kk < S_) ? v : -1e30f);
            }
            redm[part*64 + sq] = pm;
        }
        __syncthreads();
        if (tid < 64) {
            float nm = fmaxf(fmaxf(redm[sq], redm[64+sq]),
                             fmaxf(redm[128+sq], redm[192+sq]));
            nm = fmaxf(nm, m_s[sq]);
            al_s[sq] = __expf(m_s[sq] - nm);
            m_s[sq]  = nm;
        }
        __syncthreads();
        // exp -> P fp16, partial sums
        {
            float mr = m_s[sq];
            float ps = 0.f;
            #pragma unroll
            for (int i = 0; i < 16; i++) {
                int kk = part*16 + i;
                float e = 0.f;
                if (n0 + kk < S_) e = __expf(S32[sq*SST + kk] - mr);
                Pm[sq*QST + kk] = __float2half_rn(e);
                ps += e;
            }
            reds[part*64 + sq] = ps;
        }
        __syncthreads();
        if (tid < 64)
            l_s[sq] = l_s[sq]*al_s[sq] + reds[sq] + reds[64+sq]
                      + reds[128+sq] + reds[192+sq];

        // rescale O frags by alpha
        #pragma unroll
        for (int mt = 0; mt < 2; mt++) {
            float a0 = al_s[wm*32 + mt*16 + rg];
            float a1 = al_s[wm*32 + mt*16 + rg + 8];
            #pragma unroll
            for (int nt = 0; nt < 2; nt++) {
                oacc[mt][nt][0] *= a0; oacc[mt][nt][1] *= a0;
                oacc[mt][nt][2] *= a1; oacc[mt][nt][3] *= a1;
            }
        }
        // O += P * V (V split 2-term)
        #pragma unroll
        for (int ks = 0; ks < 4; ks++) {
            uint32_t ap[2][4], vh[4], vl[4];
            #pragma unroll
            for (int mt = 0; mt < 2; mt++)
                ldsm4(ap[mt], PmB + aOff + mt * 16 * 144 + ks * 32);
            ldsm4(vh, VhiB + bOff + ks * 32);
            ldsm4(vl, VloB + bOff + ks * 32);
            #pragma unroll
            for (int mt = 0; mt < 2; mt++)
                #pragma unroll
                for (int nt = 0; nt < 2; nt++) {
                    mmah16816(oacc[mt][nt], ap[mt], &vh[nt*2]);
                    mmah16816(oacc[mt][nt], ap[mt], &vl[nt*2]);
                }
        }
    }
    __syncthreads();   // final l_s visible

    const int b = bh / H_, h = bh % H_;
    #pragma unroll
    for (int mt = 0; mt < 2; mt++) {
        #pragma unroll
        for (int h2 = 0; h2 < 2; h2++) {
            int q0 = wm*32 + mt*16 + rg + h2*8;
            int m = m0 + q0;
            if (m >= S_) continue;
            float inv = 1.f / l_s[q0];
            #pragma unroll
            for (int nt = 0; nt < 2; nt++) {
                int d0 = wn*16 + nt*8 + cp;
                float2 w;
                w.x = oacc[mt][nt][h2*2 + 0] * inv;
                w.y = oacc[mt][nt][h2*2 + 1] * inv;
                *(float2*)&g_ao[((size_t)b * S_ + m) * D_ + h * HD_ + d0] = w;
            }
        }
    }
}

// ---------------------------------------------------------------------------
extern "C" void kernel_launch(void* const* d_in, const int* in_sizes, int n_in,
                              void* d_out, int out_size)
{
    const float* x        = (const float*)d_in[0];
    const float* rope_cos = (const float*)d_in[1];
    const float* rope_sin = (const float*)d_in[2];
    const float* Wq       = (const float*)d_in[3];
    const float* bq       = (const float*)d_in[4];
    const float* Wk       = (const float*)d_in[5];
    const float* Wv       = (const float*)d_in[6];
    const float* bv       = (const float*)d_in[7];
    const float* Wo       = (const float*)d_in[8];
    const float* bo       = (const float*)d_in[9];
    float* out = (float*)d_out;

    cudaFuncSetAttribute(attn_kernel,
        cudaFuncAttributeMaxDynamicSharedMemorySize, ATT_SMEM);

    // conversions
    int t4 = M_ * D_ / 4;
    split_act<<<(t4 + 255) / 256, 256>>>(x, 0);
    dim3 wg(32, 32), wb(32, 8);
    split_w<<<wg, wb>>>(Wq, 0);
    split_w<<<wg, wb>>>(Wk, 1);
    split_w<<<wg, wb>>>(Wv, 2);
    split_w<<<wg, wb>>>(Wo, 3);

    // QKV projections (tensor core mma.sync)
    dim3 gg(MPAD / 128, D_ / 128);             // 65 x 8
    mma_gemm<<<gg, 256>>>(0, 0, bq,      nullptr, 1);
    mma_gemm<<<gg, 256>>>(0, 1, nullptr, nullptr, 2);
    mma_gemm<<<gg, 256>>>(0, 2, bv,      nullptr, 3);

    int pairs = B_*H_*S_*32;
    dim3 g2((pairs + 255) / 256, 2);
    rope_kernel<<<g2, 256>>>(rope_cos, rope_sin);

    dim3 g3((S_ + 63) / 64, B_*H_);            // 17 x 128
    attn_kernel<<<g3, 256, ATT_SMEM>>>();

    // output projection
    split_act<<<(t4 + 255) / 256, 256>>>(nullptr, 1);
    mma_gemm<<<gg, 256>>>(1, 3, bo, out, 0);
}

// round 7
// speedup vs baseline: 2.0387x; 1.0821x over previous
#include <cuda_runtime.h>
#include <cuda_bf16.h>
#include <cuda_fp16.h>
#include <cstdint>

#define B_    8
#define S_    1029
#define D_    1024
#define H_    16
#define HD_   64
#define M_    (B_*S_)     // 8232
#define MPAD  8320        // 65 * 128
#define NPFX  5
#define SCALE_ 0.125f
#define SVP   1088        // padded key-stride for transposed V (16B-aligned rows)

// ---------------------------------------------------------------------------
// Scratch (device globals — no allocation allowed). .bss is zero-initialized;
// pad regions are never written and stay 0 (deterministic).
// ---------------------------------------------------------------------------
__device__ __align__(16) float g_q [B_*H_*S_*HD_];   // fp32 Q pre-rope [b,h,s,d]
__device__ __align__(16) float g_k [B_*H_*S_*HD_];   // fp32 K pre-rope
__device__ __align__(16) float g_ao[M_*D_];          // attention out [m,n]

// attention operands, fp16 split form (written once, read by attn)
__device__ __align__(16) __half g_qh[B_*H_*S_*HD_];
__device__ __align__(16) __half g_ql[B_*H_*S_*HD_];
__device__ __align__(16) __half g_kh[B_*H_*S_*HD_];
__device__ __align__(16) __half g_kl[B_*H_*S_*HD_];
__device__ __align__(16) __half g_vth[B_*H_*HD_*SVP];   // V^T [b,h,d,s]
__device__ __align__(16) __half g_vtl[B_*H_*HD_*SVP];

__device__ __align__(16) __nv_bfloat16 g_xhi [MPAD*D_];
__device__ __align__(16) __nv_bfloat16 g_xlo [MPAD*D_];
__device__ __align__(16) __nv_bfloat16 g_aohi[MPAD*D_];
__device__ __align__(16) __nv_bfloat16 g_aolo[MPAD*D_];
__device__ __align__(16) __nv_bfloat16 g_wthi[4*D_*D_];   // W^T hi, [w][n][k]
__device__ __align__(16) __nv_bfloat16 g_wtlo[4*D_*D_];   // W^T lo

// ---------------------------------------------------------------------------
// mma.sync helpers (portable PTX — no sm_103a-only features)
// ---------------------------------------------------------------------------
__device__ __forceinline__ uint32_t smem_u32(const void* p) {
    uint32_t a;
    asm("{ .reg .u64 t; cvta.to.shared.u64 t, %1; cvt.u32.u64 %0, t; }"
        : "=r"(a) : "l"(p));
    return a;
}
__device__ __forceinline__ void ldsm4(uint32_t* r, uint32_t addr) {
    asm volatile("ldmatrix.sync.aligned.m8n8.x4.shared.b16 {%0,%1,%2,%3}, [%4];"
        : "=r"(r[0]), "=r"(r[1]), "=r"(r[2]), "=r"(r[3]) : "r"(addr));
}
__device__ __forceinline__ void mma16816(float* c, const uint32_t* a,
                                         const uint32_t* b) {
    asm volatile(
        "mma.sync.aligned.m16n8k16.row.col.f32.bf16.bf16.f32 "
        "{%0,%1,%2,%3}, {%4,%5,%6,%7}, {%8,%9}, {%0,%1,%2,%3};"
        : "+f"(c[0]), "+f"(c[1]), "+f"(c[2]), "+f"(c[3])
        : "r"(a[0]), "r"(a[1]), "r"(a[2]), "r"(a[3]), "r"(b[0]), "r"(b[1]));
}
__device__ __forceinline__ void mmah16816(float* c, const uint32_t* a,
                                          const uint32_t* b) {
    asm volatile(
        "mma.sync.aligned.m16n8k16.row.col.f32.f16.f16.f32 "
        "{%0,%1,%2,%3}, {%4,%5,%6,%7}, {%8,%9}, {%0,%1,%2,%3};"
        : "+f"(c[0]), "+f"(c[1]), "+f"(c[2]), "+f"(c[3])
        : "r"(a[0]), "r"(a[1]), "r"(a[2]), "r"(a[3]), "r"(b[0]), "r"(b[1]));
}

// ---------------------------------------------------------------------------
// Split activations into bf16 hi/lo. dstsel 0: x-splits, 1: ao-splits.
// ---------------------------------------------------------------------------
__global__ void split_act(const float* __restrict__ src, int dstsel)
{
    const int total4 = M_ * D_ / 4;
    int i = blockIdx.x * blockDim.x + threadIdx.x;
    if (i >= total4) return;
    const float* s = src ? src : g_ao;
    float4 v = ((const float4*)s)[i];
    __nv_bfloat16 h0 = __float2bfloat16(v.x), h1 = __float2bfloat16(v.y);
    __nv_bfloat16 h2 = __float2bfloat16(v.z), h3 = __float2bfloat16(v.w);
    __nv_bfloat16 l0 = __float2bfloat16(v.x - __bfloat162float(h0));
    __nv_bfloat16 l1 = __float2bfloat16(v.y - __bfloat162float(h1));
    __nv_bfloat16 l2 = __float2bfloat16(v.z - __bfloat162float(h2));
    __nv_bfloat16 l3 = __float2bfloat16(v.w - __bfloat162float(h3));
    __nv_bfloat162* Hi = (__nv_bfloat162*)(dstsel ? g_aohi : g_xhi);
    __nv_bfloat162* Lo = (__nv_bfloat162*)(dstsel ? g_aolo : g_xlo);
    Hi[2*i]   = __nv_bfloat162(h0, h1);
    Hi[2*i+1] = __nv_bfloat162(h2, h3);
    Lo[2*i]   = __nv_bfloat162(l0, l1);
    Lo[2*i+1] = __nv_bfloat162(l2, l3);
}

// ---------------------------------------------------------------------------
// Transpose + split a weight: W[k][n] fp32 -> Wt_hi/lo[n][k] bf16 at slot widx
// ---------------------------------------------------------------------------
__global__ void split_w(const float* __restrict__ W, int widx)
{
    __shared__ float t[32][33];
    int n0 = blockIdx.x * 32, k0 = blockIdx.y * 32;
    int tx = threadIdx.x, ty = threadIdx.y;   // 32 x 8
    #pragma unroll
    for (int i = 0; i < 4; i++)
        t[ty + 8*i][tx] = W[(size_t)(k0 + ty + 8*i) * D_ + n0 + tx];
    __syncthreads();
    __nv_bfloat16* Hi = g_wthi + (size_t)widx * D_ * D_;
    __nv_bfloat16* Lo = g_wtlo + (size_t)widx * D_ * D_;
    #pragma unroll
    for (int i = 0; i < 4; i++) {
        float v = t[tx][ty + 8*i];
        __nv_bfloat16 h = __float2bfloat16(v);
        size_t o = (size_t)(n0 + ty + 8*i) * D_ + k0 + tx;
        Hi[o] = h;
        Lo[o] = __float2bfloat16(v - __bfloat162float(h));
    }
}

// ---------------------------------------------------------------------------
// Tensor-core GEMM (proven R5 engine). Tile 128x128, BK=32, double-buffered.
// mode 0: dst[m*D+n]; mode 1/2: fp32 g_q/g_k; mode 3: fp16 split V^T.
// ---------------------------------------------------------------------------
#define ASTRIDE 40
#define BUFELEM (128*ASTRIDE)

__global__ __launch_bounds__(256) void mma_gemm(
    int asel, int widx, const float* __restrict__ bias,
    float* __restrict__ dst, int mode)
{
    __shared__ __align__(16) __nv_bfloat16 As[2][BUFELEM];
    __shared__ __align__(16) __nv_bfloat16 Bs[2][BUFELEM];

    const int tid  = threadIdx.x;
    const int lane = tid & 31, wid = tid >> 5;
    const int wm = wid & 1, wn = wid >> 1;
    const int bm = blockIdx.x * 128, bn = blockIdx.y * 128;

    const __nv_bfloat16* Ahi = asel ? g_aohi : g_xhi;
    const __nv_bfloat16* Alo = asel ? g_aolo : g_xlo;
    const __nv_bfloat16* Bhi = g_wthi + (size_t)widx * D_ * D_;
    const __nv_bfloat16* Blo = g_wtlo + (size_t)widx * D_ * D_;

    float acc[4][4][4] = {};

    #pragma unroll
    for (int it = 0; it < 2; it++) {
        int idx = tid + it * 256;
        int r = idx >> 2, c8 = (idx & 3) * 8;
        *(uint4*)&As[0][r*ASTRIDE + c8] =
            *(const uint4*)(Ahi + (size_t)(bm + r) * D_ + c8);
        *(uint4*)&Bs[0][r*ASTRIDE + c8] =
            *(const uint4*)(Bhi + (size_t)(bn + r) * D_ + c8);
    }
    __syncthreads();

    const uint32_t aB = smem_u32(&As[0][0]);
    const uint32_t bB = smem_u32(&Bs[0][0]);
    const uint32_t aOff = (uint32_t)(wm*64 + (lane & 15)) * 80 + (lane >> 4) * 16;
    const uint32_t bOff = (uint32_t)(wn*32 + (lane & 7) + ((lane >> 4) << 3)) * 80
                          + ((lane >> 3) & 1) * 16;
    const uint32_t BUFB = BUFELEM * 2;

    const int NCH = 96;
    uint4 pa[2], pb[2];
    for (int t = 0; t < NCH; t++) {
        int buf = t & 1;
        if (t + 1 < NCH) {
            int tp = t + 1;
            int pass = tp >> 5;
            int k0 = (tp & 31) * 32;
            const __nv_bfloat16* Ap = (pass == 1) ? Alo : Ahi;
            const __nv_bfloat16* Bp = (pass == 2) ? Blo : Bhi;
            #pragma unroll
            for (int it = 0; it < 2; it++) {
                int idx = tid + it * 256;
                int r = idx >> 2, c8 = (idx & 3) * 8;
                pa[it] = *(const uint4*)(Ap + (size_t)(bm + r) * D_ + k0 + c8);
                pb[it] = *(const uint4*)(Bp + (size_t)(bn + r) * D_ + k0 + c8);
            }
        }
        uint32_t ab = aB + buf * BUFB;
        uint32_t bb = bB + buf * BUFB;
        #pragma unroll
        for (int ks = 0; ks < 2; ks++) {
            uint32_t af[4][4], bf[2][4];
            #pragma unroll
            for (int mt = 0; mt < 4; mt++)
                ldsm4(af[mt], ab + aOff + mt * 16 * 80 + ks * 32);
            #pragma unroll
            for (int bt = 0; bt < 2; bt++)
                ldsm4(bf[bt], bb + bOff + bt * 16 * 80 + ks * 32);
            #pragma unroll
            for (int mt = 0; mt < 4; mt++)
                #pragma unroll
                for (int nt = 0; nt < 4; nt++)
                    mma16816(acc[mt][nt], af[mt], &bf[nt >> 1][(nt & 1) * 2]);
        }
        if (t + 1 < NCH) {
            int nb = buf ^ 1;
            #pragma unroll
            for (int it = 0; it < 2; it++) {
                int idx = tid + it * 256;
                int r = idx >> 2, c8 = (idx & 3) * 8;
                *(uint4*)&As[nb][r*ASTRIDE + c8] = pa[it];
                *(uint4*)&Bs[nb][r*ASTRIDE + c8] = pb[it];
            }
        }
        __syncthreads();
    }

    const int rg = lane >> 2, cp = (lane & 3) * 2;
    #pragma unroll
    for (int mt = 0; mt < 4; mt++) {
        #pragma unroll
        for (int nt = 0; nt < 4; nt++) {
            int n = bn + wn*32 + nt*8 + cp;
            float b0v = bias ? __ldg(bias + n)     : 0.f;
            float b1v = bias ? __ldg(bias + n + 1) : 0.f;
            #pragma unroll
            for (int h2 = 0; h2 < 2; h2++) {
                int m = bm + wm*64 + mt*16 + rg + h2*8;
                if (m >= M_) continue;
                float v0 = acc[mt][nt][h2*2 + 0] + b0v;
                float v1 = acc[mt][nt][h2*2 + 1] + b1v;
                if (mode == 0) {
                    dst[(size_t)m * D_ + n]     = v0;
                    dst[(size_t)m * D_ + n + 1] = v1;
                } else if (mode == 3) {
                    // V: write transposed fp16 split [b,h,d,s]
                    int b = m / S_, s = m % S_;
                    int h = n >> 6, d = n & 63;
                    size_t o = ((size_t)(b * H_ + h) * HD_ + d) * SVP + s;
                    __half hv0 = __float2half_rn(v0);
                    __half hv1 = __float2half_rn(v1);
                    g_vth[o]       = hv0;
                    g_vtl[o]       = __float2half_rn(v0 - __half2float(hv0));
                    g_vth[o + SVP] = hv1;
                    g_vtl[o + SVP] = __float2half_rn(v1 - __half2float(hv1));
                } else {
                    int b = m / S_, s = m % S_;
                    int h = n >> 6, d = n & 63;
                    float* g = (mode == 1) ? g_q : g_k;
                    size_t o = (((size_t)(b * H_ + h)) * S_ + s) * HD_ + d;
                    g[o]     = v0;
                    g[o + 1] = v1;
                }
            }
        }
    }
}

// ---------------------------------------------------------------------------
// RoPE (patch tokens only) + q-scale; emits fp16 hi/lo splits directly.
// ---------------------------------------------------------------------------
__global__ void rope_kernel(const float* __restrict__ cosp,
                            const float* __restrict__ sinp)
{
    const int total = B_*H_*S_*32;
    int i = blockIdx.x * blockDim.x + threadIdx.x;
    if (i >= total) return;
    const bool isQ = (blockIdx.y == 0);
    int dh = i & 31;
    int s  = (i >> 5) % S_;
    int bh = i / (32 * S_);
    size_t base = ((size_t)bh * S_ + s) * HD_;
    const float* ptr = (isQ ? g_q : g_k) + base;
    float y0, y1;
    if (s < NPFX) {
        y0 = ptr[dh]; y1 = ptr[dh+32];
    } else {
        int p = s - NPFX;
        float c0 = cosp[p*HD_ + dh],      c1 = cosp[p*HD_ + dh + 32];
        float s0 = sinp[p*HD_ + dh],      s1 = sinp[p*HD_ + dh + 32];
        float x0 = ptr[dh], x1 = ptr[dh+32];
        y0 = x0*c0 - x1*s0;
        y1 = x1*c1 + x0*s1;
    }
    if (isQ) { y0 *= SCALE_; y1 *= SCALE_; }
    __half* Hi = isQ ? g_qh : g_kh;
    __half* Lo = isQ ? g_ql : g_kl;
    __half h0 = __float2half_rn(y0), h1 = __float2half_rn(y1);
    Hi[base + dh]      = h0;
    Hi[base + dh + 32] = h1;
    Lo[base + dh]      = __float2half_rn(y0 - __half2float(h0));
    Lo[base + dh + 32] = __float2half_rn(y1 - __half2float(h1));
}

// ---------------------------------------------------------------------------
// Tensor-core flash attention. Operands are precomputed fp16 splits —
// tile loads are pure uint4 copies. Layout/MMA identical to R6.
// ---------------------------------------------------------------------------
#define QST 72
#define SST 73
#define ATT_SMEM (7*64*QST*2 + 64*SST*4 + (3*64 + 512)*4)   // 86016

__global__ __launch_bounds__(256) void attn_kernel()
{
    extern __shared__ char smx[];
    __half* Qhi  = (__half*)smx;            // [64][QST]  (q, d)
    __half* Qlo  = Qhi  + 64*QST;
    __half* Khi  = Qlo  + 64*QST;           // [64][QST]  (key, d)
    __half* Klo  = Khi  + 64*QST;
    __half* Vthi = Klo  + 64*QST;           // [64][QST]  (d, key)
    __half* Vtlo = Vthi + 64*QST;
    __half* Pm   = Vtlo + 64*QST;           // [64][QST]  (q, key)
    float*  S32  = (float*)(Pm + 64*QST);   // [64][SST]  (q, key)
    float*  m_s  = S32 + 64*SST;            // [64]
    float*  l_s  = m_s + 64;
    float*  al_s = l_s + 64;
    float*  redm = al_s + 64;               // [4][64]
    float*  reds = redm + 256;              // [4][64]

    const int tid  = threadIdx.x;
    const int lane = tid & 31, wid = tid >> 5;
    const int wm = wid & 1, wn = wid >> 1;     // 2 x 4 warp grid
    const int rg = lane >> 2, cp = (lane & 3) * 2;
    const int bh = blockIdx.y;
    const int m0 = blockIdx.x * 64;
    const __half* qhp = g_qh + (size_t)bh * S_ * HD_;
    const __half* qlp = g_ql + (size_t)bh * S_ * HD_;
    const __half* khp = g_kh + (size_t)bh * S_ * HD_;
    const __half* klp = g_kl + (size_t)bh * S_ * HD_;
    const __half* vhp = g_vth + (size_t)bh * HD_ * SVP;
    const __half* vlp = g_vtl + (size_t)bh * HD_ * SVP;

    // Q tile: uint4 copies (zero-fill tail rows)
    const uint4 Z4 = make_uint4(0u, 0u, 0u, 0u);
    #pragma unroll
    for (int it = 0; it < 2; it++) {
        int idx = tid + it * 256;              // 0..511
        int r = idx >> 3, c8 = (idx & 7) * 8;
        uint4 vh = Z4, vl = Z4;
        if (m0 + r < S_) {
            size_t o = (size_t)(m0 + r) * HD_ + c8;
            vh = *(const uint4*)(qhp + o);
            vl = *(const uint4*)(qlp + o);
        }
        *(uint4*)&Qhi[r*QST + c8] = vh;
        *(uint4*)&Qlo[r*QST + c8] = vl;
    }
    if (tid < 64) { m_s[tid] = -1e30f; l_s[tid] = 0.f; }

    const uint32_t QhiB = smem_u32(Qhi),  QloB = smem_u32(Qlo);
    const uint32_t KhiB = smem_u32(Khi),  KloB = smem_u32(Klo);
    const uint32_t VhiB = smem_u32(Vthi), VloB = smem_u32(Vtlo);
    const uint32_t PmB  = smem_u32(Pm);
    const uint32_t aOff = (uint32_t)(wm*32 + (lane & 15)) * 144 + (lane >> 4) * 16;
    const uint32_t bOff = (uint32_t)(wn*16 + (lane & 7) + ((lane >> 4) << 3)) * 144
                          + ((lane >> 3) & 1) * 16;

    float oacc[2][2][4] = {};
    const int sq = tid & 63, part = tid >> 6;

    for (int n0 = 0; n0 < S_; n0 += 64) {
        __syncthreads();   // protects K/V/P reuse + first-iter init
        // K tile [key][d]: uint4 copies
        #pragma unroll
        for (int it = 0; it < 2; it++) {
            int idx = tid + it * 256;
            int r = idx >> 3, c8 = (idx & 7) * 8;
            uint4 vh = Z4, vl = Z4;
            if (n0 + r < S_) {
                size_t o = (size_t)(n0 + r) * HD_ + c8;
                vh = *(const uint4*)(khp + o);
                vl = *(const uint4*)(klp + o);
            }
            *(uint4*)&Khi[r*QST + c8] = vh;
            *(uint4*)&Klo[r*QST + c8] = vl;
        }
        // Vt tile [d][key]: uint4 copies from padded transposed layout
        #pragma unroll
        for (int it = 0; it < 2; it++) {
            int idx = tid + it * 256;
            int d = idx >> 3, k8 = (idx & 7) * 8;
            size_t o = (size_t)d * SVP + n0 + k8;
            *(uint4*)&Vthi[d*QST + k8] = *(const uint4*)(vhp + o);
            *(uint4*)&Vtlo[d*QST + k8] = *(const uint4*)(vlp + o);
        }
        __syncthreads();

        // S = Q K^T (3-term split)
        float sacc[2][2][4] = {};
        #pragma unroll
        for (int ks = 0; ks < 4; ks++) {
            uint32_t ah[2][4], al[2][4], bhh[4], bll[4];
            #pragma unroll
            for (int mt = 0; mt < 2; mt++) {
                ldsm4(ah[mt], QhiB + aOff + mt * 16 * 144 + ks * 32);
                ldsm4(al[mt], QloB + aOff + mt * 16 * 144 + ks * 32);
            }
            ldsm4(bhh, KhiB + bOff + ks * 32);
            ldsm4(bll, KloB + bOff + ks * 32);
            #pragma unroll
            for (int mt = 0; mt < 2; mt++)
                #pragma unroll
                for (int nt = 0; nt < 2; nt++) {
                    mmah16816(sacc[mt][nt], ah[mt], &bhh[nt*2]);
                    mmah16816(sacc[mt][nt], al[mt], &bhh[nt*2]);
                    mmah16816(sacc[mt][nt], ah[mt], &bll[nt*2]);
                }
        }
        // store S frags
        #pragma unroll
        for (int mt = 0; mt < 2; mt++)
            #pragma unroll
            for (int nt = 0; nt < 2; nt++) {
                int q0 = wm*32 + mt*16 + rg;
                int kc = wn*16 + nt*8 + cp;
                S32[q0*SST + kc]       = sacc[mt][nt][0];
                S32[q0*SST + kc + 1]   = sacc[mt][nt][1];
                S32[(q0+8)*SST + kc]     = sacc[mt][nt][2];
                S32[(q0+8)*SST + kc + 1] = sacc[mt][nt][3];
            }
        __syncthreads();

        // per-query max over this tile (4 partials)
        {
            float pm = -1e30f;
            #pragma unroll
            for (int i = 0; i < 16; i++) {
                int kk = part*16 + i;
                float v = S32[sq*SST + kk];
                pm = fmaxf(pm, (n0 + kk < S_) ? v : -1e30f);
            }
            redm[part*64 + sq] = pm;
        }
        __syncthreads();
        if (tid < 64) {
            float nm = fmaxf(fmaxf(redm[sq], redm[64+sq]),
                             fmaxf(redm[128+sq], redm[192+sq]));
            nm = fmaxf(nm, m_s[sq]);
            al_s[sq] = __expf(m_s[sq] - nm);
            m_s[sq]  = nm;
        }
        __syncthreads();
        // exp -> P fp16, partial sums
        {
            float mr = m_s[sq];
            float ps = 0.f;
            #pragma unroll
            for (int i = 0; i < 16; i++) {
                int kk = part*16 + i;
                float e = 0.f;
                if (n0 + kk < S_) e = __expf(S32[sq*SST + kk] - mr);
                Pm[sq*QST + kk] = __float2half_rn(e);
                ps += e;
            }
            reds[part*64 + sq] = ps;
        }
        __syncthreads();
        if (tid < 64)
            l_s[sq] = l_s[sq]*al_s[sq] + reds[sq] + reds[64+sq]
                      + reds[128+sq] + reds[192+sq];

        // rescale O frags by alpha
        #pragma unroll
        for (int mt = 0; mt < 2; mt++) {
            float a0 = al_s[wm*32 + mt*16 + rg];
            float a1 = al_s[wm*32 + mt*16 + rg + 8];
            #pragma unroll
            for (int nt = 0; nt < 2; nt++) {
                oacc[mt][nt][0] *= a0; oacc[mt][nt][1] *= a0;
                oacc[mt][nt][2] *= a1; oacc[mt][nt][3] *= a1;
            }
        }
        // O += P * V (V split 2-term)
        #pragma unroll
        for (int ks = 0; ks < 4; ks++) {
            uint32_t ap[2][4], vh[4], vl[4];
            #pragma unroll
            for (int mt = 0; mt < 2; mt++)
                ldsm4(ap[mt], PmB + aOff + mt * 16 * 144 + ks * 32);
            ldsm4(vh, VhiB + bOff + ks * 32);
            ldsm4(vl, VloB + bOff + ks * 32);
            #pragma unroll
            for (int mt = 0; mt < 2; mt++)
                #pragma unroll
                for (int nt = 0; nt < 2; nt++) {
                    mmah16816(oacc[mt][nt], ap[mt], &vh[nt*2]);
                    mmah16816(oacc[mt][nt], ap[mt], &vl[nt*2]);
                }
        }
    }
    __syncthreads();   // final l_s visible

    const int b = bh / H_, h = bh % H_;
    #pragma unroll
    for (int mt = 0; mt < 2; mt++) {
        #pragma unroll
        for (int h2 = 0; h2 < 2; h2++) {
            int q0 = wm*32 + mt*16 + rg + h2*8;
            int m = m0 + q0;
            if (m >= S_) continue;
            float inv = 1.f / l_s[q0];
            #pragma unroll
            for (int nt = 0; nt < 2; nt++) {
                int d0 = wn*16 + nt*8 + cp;
                float2 w;
                w.x = oacc[mt][nt][h2*2 + 0] * inv;
                w.y = oacc[mt][nt][h2*2 + 1] * inv;
                *(float2*)&g_ao[((size_t)b * S_ + m) * D_ + h * HD_ + d0] = w;
            }
        }
    }
}

// ---------------------------------------------------------------------------
extern "C" void kernel_launch(void* const* d_in, const int* in_sizes, int n_in,
                              void* d_out, int out_size)
{
    const float* x        = (const float*)d_in[0];
    const float* rope_cos = (const float*)d_in[1];
    const float* rope_sin = (const float*)d_in[2];
    const float* Wq       = (const float*)d_in[3];
    const float* bq       = (const float*)d_in[4];
    const float* Wk       = (const float*)d_in[5];
    const float* Wv       = (const float*)d_in[6];
    const float* bv       = (const float*)d_in[7];
    const float* Wo       = (const float*)d_in[8];
    const float* bo       = (const float*)d_in[9];
    float* out = (float*)d_out;

    cudaFuncSetAttribute(attn_kernel,
        cudaFuncAttributeMaxDynamicSharedMemorySize, ATT_SMEM);

    // conversions
    int t4 = M_ * D_ / 4;
    split_act<<<(t4 + 255) / 256, 256>>>(x, 0);
    dim3 wg(32, 32), wb(32, 8);
    split_w<<<wg, wb>>>(Wq, 0);
    split_w<<<wg, wb>>>(Wk, 1);
    split_w<<<wg, wb>>>(Wv, 2);
    split_w<<<wg, wb>>>(Wo, 3);

    // QKV projections (tensor core mma.sync)
    dim3 gg(MPAD / 128, D_ / 128);             // 65 x 8
    mma_gemm<<<gg, 256>>>(0, 0, bq,      nullptr, 1);
    mma_gemm<<<gg, 256>>>(0, 1, nullptr, nullptr, 2);
    mma_gemm<<<gg, 256>>>(0, 2, bv,      nullptr, 3);

    int pairs = B_*H_*S_*32;
    dim3 g2((pairs + 255) / 256, 2);
    rope_kernel<<<g2, 256>>>(rope_cos, rope_sin);

    dim3 g3((S_ + 63) / 64, B_*H_);            // 17 x 128
    attn_kernel<<<g3, 256, ATT_SMEM>>>();

    // output projection
    split_act<<<(t4 + 255) / 256, 256>>>(nullptr, 1);
    mma_gemm<<<gg, 256>>>(1, 3, bo, out, 0);
}

// round 8
// speedup vs baseline: 2.0971x; 1.0286x over previous
#include <cuda_runtime.h>
#include <cuda_bf16.h>
#include <cuda_fp16.h>
#include <cstdint>

#define B_    8
#define S_    1029
#define D_    1024
#define H_    16
#define HD_   64
#define M_    (B_*S_)     // 8232
#define MPAD  8320        // 65 * 128
#define NPFX  5
#define SCALE_ 0.125f
#define SVP   1088        // padded key-stride for transposed V (16B-aligned rows)

// ---------------------------------------------------------------------------
// Scratch (device globals — no allocation allowed). .bss is zero-initialized;
// pad regions are never written and stay 0 (deterministic).
// ---------------------------------------------------------------------------
__device__ __align__(16) float g_q [B_*H_*S_*HD_];   // fp32 Q pre-rope [b,h,s,d]
__device__ __align__(16) float g_k [B_*H_*S_*HD_];   // fp32 K pre-rope
__device__ __align__(16) float g_ao[M_*D_];          // attention out [m,n]

// attention operands, fp16 split form (written once, read by attn)
__device__ __align__(16) __half g_qh[B_*H_*S_*HD_];
__device__ __align__(16) __half g_ql[B_*H_*S_*HD_];
__device__ __align__(16) __half g_kh[B_*H_*S_*HD_];
__device__ __align__(16) __half g_kl[B_*H_*S_*HD_];
__device__ __align__(16) __half g_vth[B_*H_*HD_*SVP];   // V^T [b,h,d,s]
__device__ __align__(16) __half g_vtl[B_*H_*HD_*SVP];

__device__ __align__(16) __nv_bfloat16 g_xhi [MPAD*D_];
__device__ __align__(16) __nv_bfloat16 g_xlo [MPAD*D_];
__device__ __align__(16) __nv_bfloat16 g_aohi[MPAD*D_];
__device__ __align__(16) __nv_bfloat16 g_aolo[MPAD*D_];
__device__ __align__(16) __nv_bfloat16 g_wthi[4*D_*D_];   // W^T hi, [w][n][k]
__device__ __align__(16) __nv_bfloat16 g_wtlo[4*D_*D_];   // W^T lo

// ---------------------------------------------------------------------------
// mma.sync helpers (portable PTX — no sm_103a-only features)
// ---------------------------------------------------------------------------
__device__ __forceinline__ uint32_t smem_u32(const void* p) {
    uint32_t a;
    asm("{ .reg .u64 t; cvta.to.shared.u64 t, %1; cvt.u32.u64 %0, t; }"
        : "=r"(a) : "l"(p));
    return a;
}
__device__ __forceinline__ void ldsm4(uint32_t* r, uint32_t addr) {
    asm volatile("ldmatrix.sync.aligned.m8n8.x4.shared.b16 {%0,%1,%2,%3}, [%4];"
        : "=r"(r[0]), "=r"(r[1]), "=r"(r[2]), "=r"(r[3]) : "r"(addr));
}
__device__ __forceinline__ void mma16816(float* c, const uint32_t* a,
                                         const uint32_t* b) {
    asm volatile(
        "mma.sync.aligned.m16n8k16.row.col.f32.bf16.bf16.f32 "
        "{%0,%1,%2,%3}, {%4,%5,%6,%7}, {%8,%9}, {%0,%1,%2,%3};"
        : "+f"(c[0]), "+f"(c[1]), "+f"(c[2]), "+f"(c[3])
        : "r"(a[0]), "r"(a[1]), "r"(a[2]), "r"(a[3]), "r"(b[0]), "r"(b[1]));
}
__device__ __forceinline__ void mmah16816(float* c, const uint32_t* a,
                                          const uint32_t* b) {
    asm volatile(
        "mma.sync.aligned.m16n8k16.row.col.f32.f16.f16.f32 "
        "{%0,%1,%2,%3}, {%4,%5,%6,%7}, {%8,%9}, {%0,%1,%2,%3};"
        : "+f"(c[0]), "+f"(c[1]), "+f"(c[2]), "+f"(c[3])
        : "r"(a[0]), "r"(a[1]), "r"(a[2]), "r"(a[3]), "r"(b[0]), "r"(b[1]));
}

// ---------------------------------------------------------------------------
// Split activations into bf16 hi/lo. dstsel 0: x-splits, 1: ao-splits.
// ---------------------------------------------------------------------------
__global__ void split_act(const float* __restrict__ src, int dstsel)
{
    const int total4 = M_ * D_ / 4;
    int i = blockIdx.x * blockDim.x + threadIdx.x;
    if (i >= total4) return;
    const float* s = src ? src : g_ao;
    float4 v = ((const float4*)s)[i];
    __nv_bfloat16 h0 = __float2bfloat16(v.x), h1 = __float2bfloat16(v.y);
    __nv_bfloat16 h2 = __float2bfloat16(v.z), h3 = __float2bfloat16(v.w);
    __nv_bfloat16 l0 = __float2bfloat16(v.x - __bfloat162float(h0));
    __nv_bfloat16 l1 = __float2bfloat16(v.y - __bfloat162float(h1));
    __nv_bfloat16 l2 = __float2bfloat16(v.z - __bfloat162float(h2));
    __nv_bfloat16 l3 = __float2bfloat16(v.w - __bfloat162float(h3));
    __nv_bfloat162* Hi = (__nv_bfloat162*)(dstsel ? g_aohi : g_xhi);
    __nv_bfloat162* Lo = (__nv_bfloat162*)(dstsel ? g_aolo : g_xlo);
    Hi[2*i]   = __nv_bfloat162(h0, h1);
    Hi[2*i+1] = __nv_bfloat162(h2, h3);
    Lo[2*i]   = __nv_bfloat162(l0, l1);
    Lo[2*i+1] = __nv_bfloat162(l2, l3);
}

// ---------------------------------------------------------------------------
// Transpose + split a weight: W[k][n] fp32 -> Wt_hi/lo[n][k] bf16 at slot widx
// ---------------------------------------------------------------------------
__global__ void split_w(const float* __restrict__ W, int widx)
{
    __shared__ float t[32][33];
    int n0 = blockIdx.x * 32, k0 = blockIdx.y * 32;
    int tx = threadIdx.x, ty = threadIdx.y;   // 32 x 8
    #pragma unroll
    for (int i = 0; i < 4; i++)
        t[ty + 8*i][tx] = W[(size_t)(k0 + ty + 8*i) * D_ + n0 + tx];
    __syncthreads();
    __nv_bfloat16* Hi = g_wthi + (size_t)widx * D_ * D_;
    __nv_bfloat16* Lo = g_wtlo + (size_t)widx * D_ * D_;
    #pragma unroll
    for (int i = 0; i < 4; i++) {
        float v = t[tx][ty + 8*i];
        __nv_bfloat16 h = __float2bfloat16(v);
        size_t o = (size_t)(n0 + ty + 8*i) * D_ + k0 + tx;
        Hi[o] = h;
        Lo[o] = __float2bfloat16(v - __bfloat162float(h));
    }
}

// ---------------------------------------------------------------------------
// Merged-pass tensor-core GEMM: per k-chunk loads Ahi/Alo/Bhi/Blo and issues
// all 3 split terms (hi*hi + lo*hi + hi*lo). 32 chunks, BK=32, double-buffered
// dynamic smem (2 bufs x 4 tiles x 128x40 bf16 = 80 KB).
// mode 0: dst[m*D+n]; mode 1/2: fp32 g_q/g_k; mode 3: fp16 split V^T.
// ---------------------------------------------------------------------------
#define ASTRIDE 40
#define TILEB (128*ASTRIDE)                 // elems per tile
#define GEMM_SMEM (2*4*TILEB*2)             // 81920 bytes

__global__ __launch_bounds__(256) void mma_gemm(
    int asel, int widx, const float* __restrict__ bias,
    float* __restrict__ dst, int mode)
{
    extern __shared__ __nv_bfloat16 smg[];  // [2][4][TILEB]: Ahi,Alo,Bhi,Blo

    const int tid  = threadIdx.x;
    const int lane = tid & 31, wid = tid >> 5;
    const int wm = wid & 1, wn = wid >> 1;
    const int bm = blockIdx.x * 128, bn = blockIdx.y * 128;

    const __nv_bfloat16* Ahi = asel ? g_aohi : g_xhi;
    const __nv_bfloat16* Alo = asel ? g_aolo : g_xlo;
    const __nv_bfloat16* Bhi = g_wthi + (size_t)widx * D_ * D_;
    const __nv_bfloat16* Blo = g_wtlo + (size_t)widx * D_ * D_;

    float acc[4][4][4] = {};

    const int lr  = tid >> 2;           // 0..63? no: 256 thr -> tid>>2 = 0..63
    // per-tile load: 128 rows x 32 cols bf16 = 4096 elems = 256 thr x 16 elems
    // thread covers rows via idx = tid + it*256: r = idx>>2 (0..127), c8=(idx&3)*8

    // prologue: chunk 0
    #pragma unroll
    for (int it = 0; it < 2; it++) {
        int idx = tid + it * 256;
        int r = idx >> 2, c8 = (idx & 3) * 8;
        size_t ao = (size_t)(bm + r) * D_ + c8;
        size_t bo = (size_t)(bn + r) * D_ + c8;
        *(uint4*)&smg[0*TILEB + r*ASTRIDE + c8] = *(const uint4*)(Ahi + ao);
        *(uint4*)&smg[1*TILEB + r*ASTRIDE + c8] = *(const uint4*)(Alo + ao);
        *(uint4*)&smg[2*TILEB + r*ASTRIDE + c8] = *(const uint4*)(Bhi + bo);
        *(uint4*)&smg[3*TILEB + r*ASTRIDE + c8] = *(const uint4*)(Blo + bo);
    }
    __syncthreads();

    const uint32_t smB = smem_u32(smg);
    const uint32_t aOff = (uint32_t)(wm*64 + (lane & 15)) * 80 + (lane >> 4) * 16;
    const uint32_t bOff = (uint32_t)(wn*32 + (lane & 7) + ((lane >> 4) << 3)) * 80
                          + ((lane >> 3) & 1) * 16;
    const uint32_t TB = TILEB * 2;      // tile bytes
    const uint32_t BUFB = 4 * TB;       // buffer bytes

    const int NCH = 32;
    uint4 p[8];
    for (int t = 0; t < NCH; t++) {
        int buf = t & 1;
        if (t + 1 < NCH) {
            int k0 = (t + 1) * 32;
            #pragma unroll
            for (int it = 0; it < 2; it++) {
                int idx = tid + it * 256;
                int r = idx >> 2, c8 = (idx & 3) * 8;
                size_t ao = (size_t)(bm + r) * D_ + k0 + c8;
                size_t bo = (size_t)(bn + r) * D_ + k0 + c8;
                p[it*4 + 0] = *(const uint4*)(Ahi + ao);
                p[it*4 + 1] = *(const uint4*)(Alo + ao);
                p[it*4 + 2] = *(const uint4*)(Bhi + bo);
                p[it*4 + 3] = *(const uint4*)(Blo + bo);
            }
        }
        uint32_t aHiB = smB + buf * BUFB;
        uint32_t aLoB = aHiB + TB;
        uint32_t bHiB = aHiB + 2 * TB;
        uint32_t bLoB = aHiB + 3 * TB;
        #pragma unroll
        for (int ks = 0; ks < 2; ks++) {
            uint32_t afh[4][4], bfh[2][4];
            #pragma unroll
            for (int mt = 0; mt < 4; mt++)
                ldsm4(afh[mt], aHiB + aOff + mt * 16 * 80 + ks * 32);
            #pragma unroll
            for (int bt = 0; bt < 2; bt++)
                ldsm4(bfh[bt], bHiB + bOff + bt * 16 * 80 + ks * 32);
            #pragma unroll
            for (int mt = 0; mt < 4; mt++)
                #pragma unroll
                for (int nt = 0; nt < 4; nt++)
                    mma16816(acc[mt][nt], afh[mt], &bfh[nt >> 1][(nt & 1) * 2]);
            // lo * hi
            {
                uint32_t afl[4][4];
                #pragma unroll
                for (int mt = 0; mt < 4; mt++)
                    ldsm4(afl[mt], aLoB + aOff + mt * 16 * 80 + ks * 32);
                #pragma unroll
                for (int mt = 0; mt < 4; mt++)
                    #pragma unroll
                    for (int nt = 0; nt < 4; nt++)
                        mma16816(acc[mt][nt], afl[mt], &bfh[nt >> 1][(nt & 1) * 2]);
            }
            // hi * lo
            {
                uint32_t bfl[2][4];
                #pragma unroll
                for (int bt = 0; bt < 2; bt++)
                    ldsm4(bfl[bt], bLoB + bOff + bt * 16 * 80 + ks * 32);
                #pragma unroll
                for (int mt = 0; mt < 4; mt++)
                    #pragma unroll
                    for (int nt = 0; nt < 4; nt++)
                        mma16816(acc[mt][nt], afh[mt], &bfl[nt >> 1][(nt & 1) * 2]);
            }
        }
        if (t + 1 < NCH) {
            int nb = buf ^ 1;
            __nv_bfloat16* d0 = smg + nb * 4 * TILEB;
            #pragma unroll
            for (int it = 0; it < 2; it++) {
                int idx = tid + it * 256;
                int r = idx >> 2, c8 = (idx & 3) * 8;
                *(uint4*)&d0[0*TILEB + r*ASTRIDE + c8] = p[it*4 + 0];
                *(uint4*)&d0[1*TILEB + r*ASTRIDE + c8] = p[it*4 + 1];
                *(uint4*)&d0[2*TILEB + r*ASTRIDE + c8] = p[it*4 + 2];
                *(uint4*)&d0[3*TILEB + r*ASTRIDE + c8] = p[it*4 + 3];
            }
        }
        __syncthreads();
    }

    const int rg = lane >> 2, cp = (lane & 3) * 2;
    #pragma unroll
    for (int mt = 0; mt < 4; mt++) {
        #pragma unroll
        for (int nt = 0; nt < 4; nt++) {
            int n = bn + wn*32 + nt*8 + cp;
            float b0v = bias ? __ldg(bias + n)     : 0.f;
            float b1v = bias ? __ldg(bias + n + 1) : 0.f;
            #pragma unroll
            for (int h2 = 0; h2 < 2; h2++) {
                int m = bm + wm*64 + mt*16 + rg + h2*8;
                if (m >= M_) continue;
                float v0 = acc[mt][nt][h2*2 + 0] + b0v;
                float v1 = acc[mt][nt][h2*2 + 1] + b1v;
                if (mode == 0) {
                    dst[(size_t)m * D_ + n]     = v0;
                    dst[(size_t)m * D_ + n + 1] = v1;
                } else if (mode == 3) {
                    // V: write transposed fp16 split [b,h,d,s]
                    int b = m / S_, s = m % S_;
                    int h = n >> 6, d = n & 63;
                    size_t o = ((size_t)(b * H_ + h) * HD_ + d) * SVP + s;
                    __half hv0 = __float2half_rn(v0);
                    __half hv1 = __float2half_rn(v1);
                    g_vth[o]       = hv0;
                    g_vtl[o]       = __float2half_rn(v0 - __half2float(hv0));
                    g_vth[o + SVP] = hv1;
                    g_vtl[o + SVP] = __float2half_rn(v1 - __half2float(hv1));
                } else {
                    int b = m / S_, s = m % S_;
                    int h = n >> 6, d = n & 63;
                    float* g = (mode == 1) ? g_q : g_k;
                    size_t o = (((size_t)(b * H_ + h)) * S_ + s) * HD_ + d;
                    g[o]     = v0;
                    g[o + 1] = v1;
                }
            }
        }
    }
}

// ---------------------------------------------------------------------------
// RoPE (patch tokens only) + q-scale; emits fp16 hi/lo splits directly.
// ---------------------------------------------------------------------------
__global__ void rope_kernel(const float* __restrict__ cosp,
                            const float* __restrict__ sinp)
{
    const int total = B_*H_*S_*32;
    int i = blockIdx.x * blockDim.x + threadIdx.x;
    if (i >= total) return;
    const bool isQ = (blockIdx.y == 0);
    int dh = i & 31;
    int s  = (i >> 5) % S_;
    int bh = i / (32 * S_);
    size_t base = ((size_t)bh * S_ + s) * HD_;
    const float* ptr = (isQ ? g_q : g_k) + base;
    float y0, y1;
    if (s < NPFX) {
        y0 = ptr[dh]; y1 = ptr[dh+32];
    } else {
        int p = s - NPFX;
        float c0 = cosp[p*HD_ + dh],      c1 = cosp[p*HD_ + dh + 32];
        float s0 = sinp[p*HD_ + dh],      s1 = sinp[p*HD_ + dh + 32];
        float x0 = ptr[dh], x1 = ptr[dh+32];
        y0 = x0*c0 - x1*s0;
        y1 = x1*c1 + x0*s1;
    }
    if (isQ) { y0 *= SCALE_; y1 *= SCALE_; }
    __half* Hi = isQ ? g_qh : g_kh;
    __half* Lo = isQ ? g_ql : g_kl;
    __half h0 = __float2half_rn(y0), h1 = __float2half_rn(y1);
    Hi[base + dh]      = h0;
    Hi[base + dh + 32] = h1;
    Lo[base + dh]      = __float2half_rn(y0 - __half2float(h0));
    Lo[base + dh + 32] = __float2half_rn(y1 - __half2float(h1));
}

// ---------------------------------------------------------------------------
// Tensor-core flash attention (proven R7). Operands precomputed fp16 splits.
// ---------------------------------------------------------------------------
#define QST 72
#define SST 73
#define ATT_SMEM (7*64*QST*2 + 64*SST*4 + (3*64 + 512)*4)   // 86016

__global__ __launch_bounds__(256) void attn_kernel()
{
    extern __shared__ char smx[];
    __half* Qhi  = (__half*)smx;            // [64][QST]  (q, d)
    __half* Qlo  = Qhi  + 64*QST;
    __half* Khi  = Qlo  + 64*QST;           // [64][QST]  (key, d)
    __half* Klo  = Khi  + 64*QST;
    __half* Vthi = Klo  + 64*QST;           // [64][QST]  (d, key)
    __half* Vtlo = Vthi + 64*QST;
    __half* Pm   = Vtlo + 64*QST;           // [64][QST]  (q, key)
    float*  S32  = (float*)(Pm + 64*QST);   // [64][SST]  (q, key)
    float*  m_s  = S32 + 64*SST;            // [64]
    float*  l_s  = m_s + 64;
    float*  al_s = l_s + 64;
    float*  redm = al_s + 64;               // [4][64]
    float*  reds = redm + 256;              // [4][64]

    const int tid  = threadIdx.x;
    const int lane = tid & 31, wid = tid >> 5;
    const int wm = wid & 1, wn = wid >> 1;     // 2 x 4 warp grid
    const int rg = lane >> 2, cp = (lane & 3) * 2;
    const int bh = blockIdx.y;
    const int m0 = blockIdx.x * 64;
    const __half* qhp = g_qh + (size_t)bh * S_ * HD_;
    const __half* qlp = g_ql + (size_t)bh * S_ * HD_;
    const __half* khp = g_kh + (size_t)bh * S_ * HD_;
    const __half* klp = g_kl + (size_t)bh * S_ * HD_;
    const __half* vhp = g_vth + (size_t)bh * HD_ * SVP;
    const __half* vlp = g_vtl + (size_t)bh * HD_ * SVP;

    // Q tile: uint4 copies (zero-fill tail rows)
    const uint4 Z4 = make_uint4(0u, 0u, 0u, 0u);
    #pragma unroll
    for (int it = 0; it < 2; it++) {
        int idx = tid + it * 256;              // 0..511
        int r = idx >> 3, c8 = (idx & 7) * 8;
        uint4 vh = Z4, vl = Z4;
        if (m0 + r < S_) {
            size_t o = (size_t)(m0 + r) * HD_ + c8;
            vh = *(const uint4*)(qhp + o);
            vl = *(const uint4*)(qlp + o);
        }
        *(uint4*)&Qhi[r*QST + c8] = vh;
        *(uint4*)&Qlo[r*QST + c8] = vl;
    }
    if (tid < 64) { m_s[tid] = -1e30f; l_s[tid] = 0.f; }

    const uint32_t QhiB = smem_u32(Qhi),  QloB = smem_u32(Qlo);
    const uint32_t KhiB = smem_u32(Khi),  KloB = smem_u32(Klo);
    const uint32_t VhiB = smem_u32(Vthi), VloB = smem_u32(Vtlo);
    const uint32_t PmB  = smem_u32(Pm);
    const uint32_t aOff = (uint32_t)(wm*32 + (lane & 15)) * 144 + (lane >> 4) * 16;
    const uint32_t bOff = (uint32_t)(wn*16 + (lane & 7) + ((lane >> 4) << 3)) * 144
                          + ((lane >> 3) & 1) * 16;

    float oacc[2][2][4] = {};
    const int sq = tid & 63, part = tid >> 6;

    for (int n0 = 0; n0 < S_; n0 += 64) {
        __syncthreads();   // protects K/V/P reuse + first-iter init
        // K tile [key][d]: uint4 copies
        #pragma unroll
        for (int it = 0; it < 2; it++) {
            int idx = tid + it * 256;
            int r = idx >> 3, c8 = (idx & 7) * 8;
            uint4 vh = Z4, vl = Z4;
            if (n0 + r < S_) {
                size_t o = (size_t)(n0 + r) * HD_ + c8;
                vh = *(const uint4*)(khp + o);
                vl = *(const uint4*)(klp + o);
            }
            *(uint4*)&Khi[r*QST + c8] = vh;
            *(uint4*)&Klo[r*QST + c8] = vl;
        }
        // Vt tile [d][key]: uint4 copies from padded transposed layout
        #pragma unroll
        for (int it = 0; it < 2; it++) {
            int idx = tid + it * 256;
            int d = idx >> 3, k8 = (idx & 7) * 8;
            size_t o = (size_t)d * SVP + n0 + k8;
            *(uint4*)&Vthi[d*QST + k8] = *(const uint4*)(vhp + o);
            *(uint4*)&Vtlo[d*QST + k8] = *(const uint4*)(vlp + o);
        }
        __syncthreads();

        // S = Q K^T (3-term split)
        float sacc[2][2][4] = {};
        #pragma unroll
        for (int ks = 0; ks < 4; ks++) {
            uint32_t ah[2][4], al[2][4], bhh[4], bll[4];
            #pragma unroll
            for (int mt = 0; mt < 2; mt++) {
                ldsm4(ah[mt], QhiB + aOff + mt * 16 * 144 + ks * 32);
                ldsm4(al[mt], QloB + aOff + mt * 16 * 144 + ks * 32);
            }
            ldsm4(bhh, KhiB + bOff + ks * 32);
            ldsm4(bll, KloB + bOff + ks * 32);
            #pragma unroll
            for (int mt = 0; mt < 2; mt++)
                #pragma unroll
                for (int nt = 0; nt < 2; nt++) {
                    mmah16816(sacc[mt][nt], ah[mt], &bhh[nt*2]);
                    mmah16816(sacc[mt][nt], al[mt], &bhh[nt*2]);
                    mmah16816(sacc[mt][nt], ah[mt], &bll[nt*2]);
                }
        }
        // store S frags
        #pragma unroll
        for (int mt = 0; mt < 2; mt++)
            #pragma unroll
            for (int nt = 0; nt < 2; nt++) {
                int q0 = wm*32 + mt*16 + rg;
                int kc = wn*16 + nt*8 + cp;
                S32[q0*SST + kc]       = sacc[mt][nt][0];
                S32[q0*SST + kc + 1]   = sacc[mt][nt][1];
                S32[(q0+8)*SST + kc]     = sacc[mt][nt][2];
                S32[(q0+8)*SST + kc + 1] = sacc[mt][nt][3];
            }
        __syncthreads();

        // per-query max over this tile (4 partials)
        {
            float pm = -1e30f;
            #pragma unroll
            for (int i = 0; i < 16; i++) {
                int kk = part*16 + i;
                float v = S32[sq*SST + kk];
                pm = fmaxf(pm, (n0 + kk < S_) ? v : -1e30f);
            }
            redm[part*64 + sq] = pm;
        }
        __syncthreads();
        if (tid < 64) {
            float nm = fmaxf(fmaxf(redm[sq], redm[64+sq]),
                             fmaxf(redm[128+sq], redm[192+sq]));
            nm = fmaxf(nm, m_s[sq]);
            al_s[sq] = __expf(m_s[sq] - nm);
            m_s[sq]  = nm;
        }
        __syncthreads();
        // exp -> P fp16, partial sums
        {
            float mr = m_s[sq];
            float ps = 0.f;
            #pragma unroll
            for (int i = 0; i < 16; i++) {
                int kk = part*16 + i;
                float e = 0.f;
                if (n0 + kk < S_) e = __expf(S32[sq*SST + kk] - mr);
                Pm[sq*QST + kk] = __float2half_rn(e);
                ps += e;
            }
            reds[part*64 + sq] = ps;
        }
        __syncthreads();
        if (tid < 64)
            l_s[sq] = l_s[sq]*al_s[sq] + reds[sq] + reds[64+sq]
                      + reds[128+sq] + reds[192+sq];

        // rescale O frags by alpha
        #pragma unroll
        for (int mt = 0; mt < 2; mt++) {
            float a0 = al_s[wm*32 + mt*16 + rg];
            float a1 = al_s[wm*32 + mt*16 + rg + 8];
            #pragma unroll
            for (int nt = 0; nt < 2; nt++) {
                oacc[mt][nt][0] *= a0; oacc[mt][nt][1] *= a0;
                oacc[mt][nt][2] *= a1; oacc[mt][nt][3] *= a1;
            }
        }
        // O += P * V (V split 2-term)
        #pragma unroll
        for (int ks = 0; ks < 4; ks++) {
            uint32_t ap[2][4], vh[4], vl[4];
            #pragma unroll
            for (int mt = 0; mt < 2; mt++)
                ldsm4(ap[mt], PmB + aOff + mt * 16 * 144 + ks * 32);
            ldsm4(vh, VhiB + bOff + ks * 32);
            ldsm4(vl, VloB + bOff + ks * 32);
            #pragma unroll
            for (int mt = 0; mt < 2; mt++)
                #pragma unroll
                for (int nt = 0; nt < 2; nt++) {
                    mmah16816(oacc[mt][nt], ap[mt], &vh[nt*2]);
                    mmah16816(oacc[mt][nt], ap[mt], &vl[nt*2]);
                }
        }
    }
    __syncthreads();   // final l_s visible

    const int b = bh / H_, h = bh % H_;
    #pragma unroll
    for (int mt = 0; mt < 2; mt++) {
        #pragma unroll
        for (int h2 = 0; h2 < 2; h2++) {
            int q0 = wm*32 + mt*16 + rg + h2*8;
            int m = m0 + q0;
            if (m >= S_) continue;
            float inv = 1.f / l_s[q0];
            #pragma unroll
            for (int nt = 0; nt < 2; nt++) {
                int d0 = wn*16 + nt*8 + cp;
                float2 w;
                w.x = oacc[mt][nt][h2*2 + 0] * inv;
                w.y = oacc[mt][nt][h2*2 + 1] * inv;
                *(float2*)&g_ao[((size_t)b * S_ + m) * D_ + h * HD_ + d0] = w;
            }
        }
    }
}

// ---------------------------------------------------------------------------
extern "C" void kernel_launch(void* const* d_in, const int* in_sizes, int n_in,
                              void* d_out, int out_size)
{
    const float* x        = (const float*)d_in[0];
    const float* rope_cos = (const float*)d_in[1];
    const float* rope_sin = (const float*)d_in[2];
    const float* Wq       = (const float*)d_in[3];
    const float* bq       = (const float*)d_in[4];
    const float* Wk       = (const float*)d_in[5];
    const float* Wv       = (const float*)d_in[6];
    const float* bv       = (const float*)d_in[7];
    const float* Wo       = (const float*)d_in[8];
    const float* bo       = (const float*)d_in[9];
    float* out = (float*)d_out;

    cudaFuncSetAttribute(attn_kernel,
        cudaFuncAttributeMaxDynamicSharedMemorySize, ATT_SMEM);
    cudaFuncSetAttribute(mma_gemm,
        cudaFuncAttributeMaxDynamicSharedMemorySize, GEMM_SMEM);

    dim3 gg(MPAD / 128, D_ / 128);             // 65 x 8
    dim3 wg(32, 32), wb(32, 8);
    int t4 = M_ * D_ / 4;

    // interleaved so the ncu capture window lands on a mma_gemm launch
    split_act<<<(t4 + 255) / 256, 256>>>(x, 0);
    split_w<<<wg, wb>>>(Wq, 0);
    mma_gemm<<<gg, 256, GEMM_SMEM>>>(0, 0, bq,      nullptr, 1);
    split_w<<<wg, wb>>>(Wk, 1);
    mma_gemm<<<gg, 256, GEMM_SMEM>>>(0, 1, nullptr, nullptr, 2);
    split_w<<<wg, wb>>>(Wv, 2);
    mma_gemm<<<gg, 256, GEMM_SMEM>>>(0, 2, bv,      nullptr, 3);
    split_w<<<wg, wb>>>(Wo, 3);

    int pairs = B_*H_*S_*32;
    dim3 g2((pairs + 255) / 256, 2);
    rope_kernel<<<g2, 256>>>(rope_cos, rope_sin);

    dim3 g3((S_ + 63) / 64, B_*H_);            // 17 x 128
    attn_kernel<<<g3, 256, ATT_SMEM>>>();

    // output projection
    split_act<<<(t4 + 255) / 256, 256>>>(nullptr, 1);
    mma_gemm<<<gg, 256, GEMM_SMEM>>>(1, 3, bo, out, 0);
}

// round 9
// speedup vs baseline: 2.1777x; 1.0385x over previous
#include <cuda_runtime.h>
#include <cuda_bf16.h>
#include <cuda_fp16.h>
#include <cstdint>

#define B_    8
#define S_    1029
#define D_    1024
#define H_    16
#define HD_   64
#define M_    (B_*S_)     // 8232
#define MPAD  8320        // 65 * 128
#define NPFX  5
#define SCALE_ 0.125f
#define SVP   1088        // padded key-stride for transposed V (16B-aligned rows)

// ---------------------------------------------------------------------------
// Scratch (device globals — no allocation allowed). .bss is zero-initialized;
// pad regions are never written and stay 0 (deterministic).
// ---------------------------------------------------------------------------
__device__ __align__(16) float g_q [B_*H_*S_*HD_];   // fp32 Q pre-rope [b,h,s,d]
__device__ __align__(16) float g_k [B_*H_*S_*HD_];   // fp32 K pre-rope

// attention operands, fp16 split form (written once, read by attn)
__device__ __align__(16) __half g_qh[B_*H_*S_*HD_];
__device__ __align__(16) __half g_ql[B_*H_*S_*HD_];
__device__ __align__(16) __half g_kh[B_*H_*S_*HD_];
__device__ __align__(16) __half g_vth[B_*H_*HD_*SVP];   // V^T [b,h,d,s]
__device__ __align__(16) __half g_vtl[B_*H_*HD_*SVP];

__device__ __align__(16) __nv_bfloat16 g_xhi [MPAD*D_];
__device__ __align__(16) __nv_bfloat16 g_xlo [MPAD*D_];
__device__ __align__(16) __nv_bfloat16 g_aohi[MPAD*D_];  // attn out split [m,n]
__device__ __align__(16) __nv_bfloat16 g_aolo[MPAD*D_];
__device__ __align__(16) __nv_bfloat16 g_wthi[4*D_*D_];  // W^T hi, [w][n][k]
__device__ __align__(16) __nv_bfloat16 g_wtlo[4*D_*D_];  // W^T lo

// ---------------------------------------------------------------------------
// mma.sync helpers (portable PTX — no sm_103a-only features)
// ---------------------------------------------------------------------------
__device__ __forceinline__ uint32_t smem_u32(const void* p) {
    uint32_t a;
    asm("{ .reg .u64 t; cvta.to.shared.u64 t, %1; cvt.u32.u64 %0, t; }"
        : "=r"(a) : "l"(p));
    return a;
}
__device__ __forceinline__ void ldsm4(uint32_t* r, uint32_t addr) {
    asm volatile("ldmatrix.sync.aligned.m8n8.x4.shared.b16 {%0,%1,%2,%3}, [%4];"
        : "=r"(r[0]), "=r"(r[1]), "=r"(r[2]), "=r"(r[3]) : "r"(addr));
}
__device__ __forceinline__ void mma16816(float* c, const uint32_t* a,
                                         const uint32_t* b) {
    asm volatile(
        "mma.sync.aligned.m16n8k16.row.col.f32.bf16.bf16.f32 "
        "{%0,%1,%2,%3}, {%4,%5,%6,%7}, {%8,%9}, {%0,%1,%2,%3};"
        : "+f"(c[0]), "+f"(c[1]), "+f"(c[2]), "+f"(c[3])
        : "r"(a[0]), "r"(a[1]), "r"(a[2]), "r"(a[3]), "r"(b[0]), "r"(b[1]));
}
__device__ __forceinline__ void mmah16816(float* c, const uint32_t* a,
                                          const uint32_t* b) {
    asm volatile(
        "mma.sync.aligned.m16n8k16.row.col.f32.f16.f16.f32 "
        "{%0,%1,%2,%3}, {%4,%5,%6,%7}, {%8,%9}, {%0,%1,%2,%3};"
        : "+f"(c[0]), "+f"(c[1]), "+f"(c[2]), "+f"(c[3])
        : "r"(a[0]), "r"(a[1]), "r"(a[2]), "r"(a[3]), "r"(b[0]), "r"(b[1]));
}

// ---------------------------------------------------------------------------
// Split x into bf16 hi/lo.
// ---------------------------------------------------------------------------
__global__ void split_act(const float* __restrict__ src)
{
    const int total4 = M_ * D_ / 4;
    int i = blockIdx.x * blockDim.x + threadIdx.x;
    if (i >= total4) return;
    float4 v = ((const float4*)src)[i];
    __nv_bfloat16 h0 = __float2bfloat16(v.x), h1 = __float2bfloat16(v.y);
    __nv_bfloat16 h2 = __float2bfloat16(v.z), h3 = __float2bfloat16(v.w);
    __nv_bfloat16 l0 = __float2bfloat16(v.x - __bfloat162float(h0));
    __nv_bfloat16 l1 = __float2bfloat16(v.y - __bfloat162float(h1));
    __nv_bfloat16 l2 = __float2bfloat16(v.z - __bfloat162float(h2));
    __nv_bfloat16 l3 = __float2bfloat16(v.w - __bfloat162float(h3));
    __nv_bfloat162* Hi = (__nv_bfloat162*)g_xhi;
    __nv_bfloat162* Lo = (__nv_bfloat162*)g_xlo;
    Hi[2*i]   = __nv_bfloat162(h0, h1);
    Hi[2*i+1] = __nv_bfloat162(h2, h3);
    Lo[2*i]   = __nv_bfloat162(l0, l1);
    Lo[2*i+1] = __nv_bfloat162(l2, l3);
}

// ---------------------------------------------------------------------------
// Transpose + split a weight: W[k][n] fp32 -> Wt_hi/lo[n][k] bf16 at slot widx
// ---------------------------------------------------------------------------
__global__ void split_w(const float* __restrict__ W, int widx)
{
    __shared__ float t[32][33];
    int n0 = blockIdx.x * 32, k0 = blockIdx.y * 32;
    int tx = threadIdx.x, ty = threadIdx.y;   // 32 x 8
    #pragma unroll
    for (int i = 0; i < 4; i++)
        t[ty + 8*i][tx] = W[(size_t)(k0 + ty + 8*i) * D_ + n0 + tx];
    __syncthreads();
    __nv_bfloat16* Hi = g_wthi + (size_t)widx * D_ * D_;
    __nv_bfloat16* Lo = g_wtlo + (size_t)widx * D_ * D_;
    #pragma unroll
    for (int i = 0; i < 4; i++) {
        float v = t[tx][ty + 8*i];
        __nv_bfloat16 h = __float2bfloat16(v);
        size_t o = (size_t)(n0 + ty + 8*i) * D_ + k0 + tx;
        Hi[o] = h;
        Lo[o] = __float2bfloat16(v - __bfloat162float(h));
    }
}

// ---------------------------------------------------------------------------
// Merged-pass tensor-core GEMM (proven R8 engine). 32 chunks, BK=32,
// double-buffered 80KB dynamic smem.
// mode 0: dst[m*D+n]; mode 1/2: fp32 g_q/g_k; mode 3: fp16 split V^T.
// ---------------------------------------------------------------------------
#define ASTRIDE 40
#define TILEB (128*ASTRIDE)                 // elems per tile
#define GEMM_SMEM (2*4*TILEB*2)             // 81920 bytes

__global__ __launch_bounds__(256) void mma_gemm(
    int asel, int widx, const float* __restrict__ bias,
    float* __restrict__ dst, int mode)
{
    extern __shared__ __nv_bfloat16 smg[];  // [2][4][TILEB]: Ahi,Alo,Bhi,Blo

    const int tid  = threadIdx.x;
    const int lane = tid & 31, wid = tid >> 5;
    const int wm = wid & 1, wn = wid >> 1;
    const int bm = blockIdx.x * 128, bn = blockIdx.y * 128;

    const __nv_bfloat16* Ahi = asel ? g_aohi : g_xhi;
    const __nv_bfloat16* Alo = asel ? g_aolo : g_xlo;
    const __nv_bfloat16* Bhi = g_wthi + (size_t)widx * D_ * D_;
    const __nv_bfloat16* Blo = g_wtlo + (size_t)widx * D_ * D_;

    float acc[4][4][4] = {};

    // prologue: chunk 0
    #pragma unroll
    for (int it = 0; it < 2; it++) {
        int idx = tid + it * 256;
        int r = idx >> 2, c8 = (idx & 3) * 8;
        size_t ao = (size_t)(bm + r) * D_ + c8;
        size_t bo = (size_t)(bn + r) * D_ + c8;
        *(uint4*)&smg[0*TILEB + r*ASTRIDE + c8] = *(const uint4*)(Ahi + ao);
        *(uint4*)&smg[1*TILEB + r*ASTRIDE + c8] = *(const uint4*)(Alo + ao);
        *(uint4*)&smg[2*TILEB + r*ASTRIDE + c8] = *(const uint4*)(Bhi + bo);
        *(uint4*)&smg[3*TILEB + r*ASTRIDE + c8] = *(const uint4*)(Blo + bo);
    }
    __syncthreads();

    const uint32_t smB = smem_u32(smg);
    const uint32_t aOff = (uint32_t)(wm*64 + (lane & 15)) * 80 + (lane >> 4) * 16;
    const uint32_t bOff = (uint32_t)(wn*32 + (lane & 7) + ((lane >> 4) << 3)) * 80
                          + ((lane >> 3) & 1) * 16;
    const uint32_t TB = TILEB * 2;      // tile bytes
    const uint32_t BUFB = 4 * TB;       // buffer bytes

    const int NCH = 32;
    uint4 p[8];
    for (int t = 0; t < NCH; t++) {
        int buf = t & 1;
        if (t + 1 < NCH) {
            int k0 = (t + 1) * 32;
            #pragma unroll
            for (int it = 0; it < 2; it++) {
                int idx = tid + it * 256;
                int r = idx >> 2, c8 = (idx & 3) * 8;
                size_t ao = (size_t)(bm + r) * D_ + k0 + c8;
                size_t bo = (size_t)(bn + r) * D_ + k0 + c8;
                p[it*4 + 0] = *(const uint4*)(Ahi + ao);
                p[it*4 + 1] = *(const uint4*)(Alo + ao);
                p[it*4 + 2] = *(const uint4*)(Bhi + bo);
                p[it*4 + 3] = *(const uint4*)(Blo + bo);
            }
        }
        uint32_t aHiB = smB + buf * BUFB;
        uint32_t aLoB = aHiB + TB;
        uint32_t bHiB = aHiB + 2 * TB;
        uint32_t bLoB = aHiB + 3 * TB;
        #pragma unroll
        for (int ks = 0; ks < 2; ks++) {
            uint32_t afh[4][4], bfh[2][4];
            #pragma unroll
            for (int mt = 0; mt < 4; mt++)
                ldsm4(afh[mt], aHiB + aOff + mt * 16 * 80 + ks * 32);
            #pragma unroll
            for (int bt = 0; bt < 2; bt++)
                ldsm4(bfh[bt], bHiB + bOff + bt * 16 * 80 + ks * 32);
            #pragma unroll
            for (int mt = 0; mt < 4; mt++)
                #pragma unroll
                for (int nt = 0; nt < 4; nt++)
                    mma16816(acc[mt][nt], afh[mt], &bfh[nt >> 1][(nt & 1) * 2]);
            // lo * hi
            {
                uint32_t afl[4][4];
                #pragma unroll
                for (int mt = 0; mt < 4; mt++)
                    ldsm4(afl[mt], aLoB + aOff + mt * 16 * 80 + ks * 32);
                #pragma unroll
                for (int mt = 0; mt < 4; mt++)
                    #pragma unroll
                    for (int nt = 0; nt < 4; nt++)
                        mma16816(acc[mt][nt], afl[mt], &bfh[nt >> 1][(nt & 1) * 2]);
            }
            // hi * lo
            {
                uint32_t bfl[2][4];
                #pragma unroll
                for (int bt = 0; bt < 2; bt++)
                    ldsm4(bfl[bt], bLoB + bOff + bt * 16 * 80 + ks * 32);
                #pragma unroll
                for (int mt = 0; mt < 4; mt++)
                    #pragma unroll
                    for (int nt = 0; nt < 4; nt++)
                        mma16816(acc[mt][nt], afh[mt], &bfl[nt >> 1][(nt & 1) * 2]);
            }
        }
        if (t + 1 < NCH) {
            int nb = buf ^ 1;
            __nv_bfloat16* d0 = smg + nb * 4 * TILEB;
            #pragma unroll
            for (int it = 0; it < 2; it++) {
                int idx = tid + it * 256;
                int r = idx >> 2, c8 = (idx & 3) * 8;
                *(uint4*)&d0[0*TILEB + r*ASTRIDE + c8] = p[it*4 + 0];
                *(uint4*)&d0[1*TILEB + r*ASTRIDE + c8] = p[it*4 + 1];
                *(uint4*)&d0[2*TILEB + r*ASTRIDE + c8] = p[it*4 + 2];
                *(uint4*)&d0[3*TILEB + r*ASTRIDE + c8] = p[it*4 + 3];
            }
        }
        __syncthreads();
    }

    const int rg = lane >> 2, cp = (lane & 3) * 2;
    #pragma unroll
    for (int mt = 0; mt < 4; mt++) {
        #pragma unroll
        for (int nt = 0; nt < 4; nt++) {
            int n = bn + wn*32 + nt*8 + cp;
            float b0v = bias ? __ldg(bias + n)     : 0.f;
            float b1v = bias ? __ldg(bias + n + 1) : 0.f;
            #pragma unroll
            for (int h2 = 0; h2 < 2; h2++) {
                int m = bm + wm*64 + mt*16 + rg + h2*8;
                if (m >= M_) continue;
                float v0 = acc[mt][nt][h2*2 + 0] + b0v;
                float v1 = acc[mt][nt][h2*2 + 1] + b1v;
                if (mode == 0) {
                    dst[(size_t)m * D_ + n]     = v0;
                    dst[(size_t)m * D_ + n + 1] = v1;
                } else if (mode == 3) {
                    // V: write transposed fp16 split [b,h,d,s]
                    int b = m / S_, s = m % S_;
                    int h = n >> 6, d = n & 63;
                    size_t o = ((size_t)(b * H_ + h) * HD_ + d) * SVP + s;
                    __half hv0 = __float2half_rn(v0);
                    __half hv1 = __float2half_rn(v1);
                    g_vth[o]       = hv0;
                    g_vtl[o]       = __float2half_rn(v0 - __half2float(hv0));
                    g_vth[o + SVP] = hv1;
                    g_vtl[o + SVP] = __float2half_rn(v1 - __half2float(hv1));
                } else {
                    int b = m / S_, s = m % S_;
                    int h = n >> 6, d = n & 63;
                    float* g = (mode == 1) ? g_q : g_k;
                    size_t o = (((size_t)(b * H_ + h)) * S_ + s) * HD_ + d;
                    g[o]     = v0;
                    g[o + 1] = v1;
                }
            }
        }
    }
}

// ---------------------------------------------------------------------------
// RoPE (patch tokens only) + q-scale; emits fp16 splits (Q: hi+lo, K: hi only)
// ---------------------------------------------------------------------------
__global__ void rope_kernel(const float* __restrict__ cosp,
                            const float* __restrict__ sinp)
{
    const int total = B_*H_*S_*32;
    int i = blockIdx.x * blockDim.x + threadIdx.x;
    if (i >= total) return;
    const bool isQ = (blockIdx.y == 0);
    int dh = i & 31;
    int s  = (i >> 5) % S_;
    int bh = i / (32 * S_);
    size_t base = ((size_t)bh * S_ + s) * HD_;
    const float* ptr = (isQ ? g_q : g_k) + base;
    float y0, y1;
    if (s < NPFX) {
        y0 = ptr[dh]; y1 = ptr[dh+32];
    } else {
        int p = s - NPFX;
        float c0 = cosp[p*HD_ + dh],      c1 = cosp[p*HD_ + dh + 32];
        float s0 = sinp[p*HD_ + dh],      s1 = sinp[p*HD_ + dh + 32];
        float x0 = ptr[dh], x1 = ptr[dh+32];
        y0 = x0*c0 - x1*s0;
        y1 = x1*c1 + x0*s1;
    }
    __half h0, h1;
    if (isQ) {
        y0 *= SCALE_; y1 *= SCALE_;
        h0 = __float2half_rn(y0); h1 = __float2half_rn(y1);
        g_qh[base + dh]      = h0;
        g_qh[base + dh + 32] = h1;
        g_ql[base + dh]      = __float2half_rn(y0 - __half2float(h0));
        g_ql[base + dh + 32] = __float2half_rn(y1 - __half2float(h1));
    } else {
        g_kh[base + dh]      = __float2half_rn(y0);
        g_kh[base + dh + 32] = __float2half_rn(y1);
    }
}

// ---------------------------------------------------------------------------
// Tensor-core flash attention. QK: 2-term (full-Q x K-hi). PV: P x (Vhi+Vlo).
// Epilogue writes bf16 hi/lo splits for the output projection directly.
// ---------------------------------------------------------------------------
#define QST 72
#define SST 73
#define ATT_SMEM (6*64*QST*2 + 64*SST*4 + (3*64 + 512)*4)   // 76800

__global__ __launch_bounds__(256) void attn_kernel()
{
    extern __shared__ char smx[];
    __half* Qhi  = (__half*)smx;            // [64][QST]  (q, d)
    __half* Qlo  = Qhi  + 64*QST;
    __half* Khi  = Qlo  + 64*QST;           // [64][QST]  (key, d)
    __half* Vthi = Khi  + 64*QST;           // [64][QST]  (d, key)
    __half* Vtlo = Vthi + 64*QST;
    __half* Pm   = Vtlo + 64*QST;           // [64][QST]  (q, key)
    float*  S32  = (float*)(Pm + 64*QST);   // [64][SST]  (q, key)
    float*  m_s  = S32 + 64*SST;            // [64]
    float*  l_s  = m_s + 64;
    float*  al_s = l_s + 64;
    float*  redm = al_s + 64;               // [4][64]
    float*  reds = redm + 256;              // [4][64]

    const int tid  = threadIdx.x;
    const int lane = tid & 31, wid = tid >> 5;
    const int wm = wid & 1, wn = wid >> 1;     // 2 x 4 warp grid
    const int rg = lane >> 2, cp = (lane & 3) * 2;
    const int bh = blockIdx.y;
    const int m0 = blockIdx.x * 64;
    const __half* qhp = g_qh + (size_t)bh * S_ * HD_;
    const __half* qlp = g_ql + (size_t)bh * S_ * HD_;
    const __half* khp = g_kh + (size_t)bh * S_ * HD_;
    const __half* vhp = g_vth + (size_t)bh * HD_ * SVP;
    const __half* vlp = g_vtl + (size_t)bh * HD_ * SVP;

    // Q tile: uint4 copies (zero-fill tail rows)
    const uint4 Z4 = make_uint4(0u, 0u, 0u, 0u);
    #pragma unroll
    for (int it = 0; it < 2; it++) {
        int idx = tid + it * 256;              // 0..511
        int r = idx >> 3, c8 = (idx & 7) * 8;
        uint4 vh = Z4, vl = Z4;
        if (m0 + r < S_) {
            size_t o = (size_t)(m0 + r) * HD_ + c8;
            vh = *(const uint4*)(qhp + o);
            vl = *(const uint4*)(qlp + o);
        }
        *(uint4*)&Qhi[r*QST + c8] = vh;
        *(uint4*)&Qlo[r*QST + c8] = vl;
    }
    if (tid < 64) { m_s[tid] = -1e30f; l_s[tid] = 0.f; }

    const uint32_t QhiB = smem_u32(Qhi),  QloB = smem_u32(Qlo);
    const uint32_t KhiB = smem_u32(Khi);
    const uint32_t VhiB = smem_u32(Vthi), VloB = smem_u32(Vtlo);
    const uint32_t PmB  = smem_u32(Pm);
    const uint32_t aOff = (uint32_t)(wm*32 + (lane & 15)) * 144 + (lane >> 4) * 16;
    const uint32_t bOff = (uint32_t)(wn*16 + (lane & 7) + ((lane >> 4) << 3)) * 144
                          + ((lane >> 3) & 1) * 16;

    float oacc[2][2][4] = {};
    const int sq = tid & 63, part = tid >> 6;

    for (int n0 = 0; n0 < S_; n0 += 64) {
        __syncthreads();   // protects K/V/P reuse + first-iter init
        // K tile [key][d]: uint4 copies (hi only)
        #pragma unroll
        for (int it = 0; it < 2; it++) {
            int idx = tid + it * 256;
            int r = idx >> 3, c8 = (idx & 7) * 8;
            uint4 vh = Z4;
            if (n0 + r < S_)
                vh = *(const uint4*)(khp + (size_t)(n0 + r) * HD_ + c8);
            *(uint4*)&Khi[r*QST + c8] = vh;
        }
        // Vt tile [d][key]: uint4 copies from padded transposed layout
        #pragma unroll
        for (int it = 0; it < 2; it++) {
            int idx = tid + it * 256;
            int d = idx >> 3, k8 = (idx & 7) * 8;
            size_t o = (size_t)d * SVP + n0 + k8;
            *(uint4*)&Vthi[d*QST + k8] = *(const uint4*)(vhp + o);
            *(uint4*)&Vtlo[d*QST + k8] = *(const uint4*)(vlp + o);
        }
        __syncthreads();

        // S = (Qhi + Qlo) K_hi^T  (2-term)
        float sacc[2][2][4] = {};
        #pragma unroll
        for (int ks = 0; ks < 4; ks++) {
            uint32_t ah[2][4], al[2][4], bhh[4];
            #pragma unroll
            for (int mt = 0; mt < 2; mt++) {
                ldsm4(ah[mt], QhiB + aOff + mt * 16 * 144 + ks * 32);
                ldsm4(al[mt], QloB + aOff + mt * 16 * 144 + ks * 32);
            }
            ldsm4(bhh, KhiB + bOff + ks * 32);
            #pragma unroll
            for (int mt = 0; mt < 2; mt++)
                #pragma unroll
                for (int nt = 0; nt < 2; nt++) {
                    mmah16816(sacc[mt][nt], ah[mt], &bhh[nt*2]);
                    mmah16816(sacc[mt][nt], al[mt], &bhh[nt*2]);
                }
        }
        // store S frags
        #pragma unroll
        for (int mt = 0; mt < 2; mt++)
            #pragma unroll
            for (int nt = 0; nt < 2; nt++) {
                int q0 = wm*32 + mt*16 + rg;
                int kc = wn*16 + nt*8 + cp;
                S32[q0*SST + kc]       = sacc[mt][nt][0];
                S32[q0*SST + kc + 1]   = sacc[mt][nt][1];
                S32[(q0+8)*SST + kc]     = sacc[mt][nt][2];
                S32[(q0+8)*SST + kc + 1] = sacc[mt][nt][3];
            }
        __syncthreads();

        // per-query max over this tile (4 partials)
        {
            float pm = -1e30f;
            #pragma unroll
            for (int i = 0; i < 16; i++) {
                int kk = part*16 + i;
                float v = S32[sq*SST + kk];
                pm = fmaxf(pm, (n0 + kk < S_) ? v : -1e30f);
            }
            redm[part*64 + sq] = pm;
        }
        __syncthreads();
        if (tid < 64) {
            float nm = fmaxf(fmaxf(redm[sq], redm[64+sq]),
                             fmaxf(redm[128+sq], redm[192+sq]));
            nm = fmaxf(nm, m_s[sq]);
            al_s[sq] = __expf(m_s[sq] - nm);
            m_s[sq]  = nm;
        }
        __syncthreads();
        // exp -> P fp16, partial sums
        {
            float mr = m_s[sq];
            float ps = 0.f;
            #pragma unroll
            for (int i = 0; i < 16; i++) {
                int kk = part*16 + i;
                float e = 0.f;
                if (n0 + kk < S_) e = __expf(S32[sq*SST + kk] - mr);
                Pm[sq*QST + kk] = __float2half_rn(e);
                ps += e;
            }
            reds[part*64 + sq] = ps;
        }
        __syncthreads();
        if (tid < 64)
            l_s[sq] = l_s[sq]*al_s[sq] + reds[sq] + reds[64+sq]
                      + reds[128+sq] + reds[192+sq];

        // rescale O frags by alpha
        #pragma unroll
        for (int mt = 0; mt < 2; mt++) {
            float a0 = al_s[wm*32 + mt*16 + rg];
            float a1 = al_s[wm*32 + mt*16 + rg + 8];
            #pragma unroll
            for (int nt = 0; nt < 2; nt++) {
                oacc[mt][nt][0] *= a0; oacc[mt][nt][1] *= a0;
                oacc[mt][nt][2] *= a1; oacc[mt][nt][3] *= a1;
            }
        }
        // O += P * V (V split 2-term)
        #pragma unroll
        for (int ks = 0; ks < 4; ks++) {
            uint32_t ap[2][4], vh[4], vl[4];
            #pragma unroll
            for (int mt = 0; mt < 2; mt++)
                ldsm4(ap[mt], PmB + aOff + mt * 16 * 144 + ks * 32);
            ldsm4(vh, VhiB + bOff + ks * 32);
            ldsm4(vl, VloB + bOff + ks * 32);
            #pragma unroll
            for (int mt = 0; mt < 2; mt++)
                #pragma unroll
                for (int nt = 0; nt < 2; nt++) {
                    mmah16816(oacc[mt][nt], ap[mt], &vh[nt*2]);
                    mmah16816(oacc[mt][nt], ap[mt], &vl[nt*2]);
                }
        }
    }
    __syncthreads();   // final l_s visible

    // epilogue: write bf16 hi/lo splits for the output projection
    const int b = bh / H_, h = bh % H_;
    #pragma unroll
    for (int mt = 0; mt < 2; mt++) {
        #pragma unroll
        for (int h2 = 0; h2 < 2; h2++) {
            int q0 = wm*32 + mt*16 + rg + h2*8;
            int m = m0 + q0;
            if (m >= S_) continue;
            float inv = 1.f / l_s[q0];
            #pragma unroll
            for (int nt = 0; nt < 2; nt++) {
                int d0 = wn*16 + nt*8 + cp;
                float w0 = oacc[mt][nt][h2*2 + 0] * inv;
                float w1 = oacc[mt][nt][h2*2 + 1] * inv;
                __nv_bfloat16 b0 = __float2bfloat16(w0);
                __nv_bfloat16 b1 = __float2bfloat16(w1);
                size_t o = ((size_t)b * S_ + m) * D_ + h * HD_ + d0;
                *(__nv_bfloat162*)&g_aohi[o] = __nv_bfloat162(b0, b1);
                *(__nv_bfloat162*)&g_aolo[o] = __nv_bfloat162(
                    __float2bfloat16(w0 - __bfloat162float(b0)),
                    __float2bfloat16(w1 - __bfloat162float(b1)));
            }
        }
    }
}

// ---------------------------------------------------------------------------
extern "C" void kernel_launch(void* const* d_in, const int* in_sizes, int n_in,
                              void* d_out, int out_size)
{
    const float* x        = (const float*)d_in[0];
    const float* rope_cos = (const float*)d_in[1];
    const float* rope_sin = (const float*)d_in[2];
    const float* Wq       = (const float*)d_in[3];
    const float* bq       = (const float*)d_in[4];
    const float* Wk       = (const float*)d_in[5];
    const float* Wv       = (const float*)d_in[6];
    const float* bv       = (const float*)d_in[7];
    const float* Wo       = (const float*)d_in[8];
    const float* bo       = (const float*)d_in[9];
    float* out = (float*)d_out;

    cudaFuncSetAttribute(attn_kernel,
        cudaFuncAttributeMaxDynamicSharedMemorySize, ATT_SMEM);
    cudaFuncSetAttribute(mma_gemm,
        cudaFuncAttributeMaxDynamicSharedMemorySize, GEMM_SMEM);

    dim3 gg(MPAD / 128, D_ / 128);             // 65 x 8
    dim3 wg(32, 32), wb(32, 8);
    int t4 = M_ * D_ / 4;

    split_act<<<(t4 + 255) / 256, 256>>>(x);
    split_w<<<wg, wb>>>(Wq, 0);
    mma_gemm<<<gg, 256, GEMM_SMEM>>>(0, 0, bq,      nullptr, 1);
    split_w<<<wg, wb>>>(Wk, 1);
    mma_gemm<<<gg, 256, GEMM_SMEM>>>(0, 1, nullptr, nullptr, 2);
    split_w<<<wg, wb>>>(Wv, 2);
    mma_gemm<<<gg, 256, GEMM_SMEM>>>(0, 2, bv,      nullptr, 3);
    split_w<<<wg, wb>>>(Wo, 3);

    int pairs = B_*H_*S_*32;
    dim3 g2((pairs + 255) / 256, 2);
    rope_kernel<<<g2, 256>>>(rope_cos, rope_sin);

    dim3 g3((S_ + 63) / 64, B_*H_);            // 17 x 128
    attn_kernel<<<g3, 256, ATT_SMEM>>>();

    // output projection (reads g_aohi/g_aolo written by attn)
    mma_gemm<<<gg, 256, GEMM_SMEM>>>(1, 3, bo, out, 0);
}

// round 10
// speedup vs baseline: 2.8098x; 1.2902x over previous
#include <cuda_runtime.h>
#include <cuda_bf16.h>
#include <cuda_fp16.h>
#include <cstdint>

#define B_    8
#define S_    1029
#define D_    1024
#define H_    16
#define HD_   64
#define M_    (B_*S_)     // 8232
#define MPAD  8320        // 65 * 128
#define NPFX  5
#define SCALE_ 0.125f
#define SVP   1088        // padded key-stride for transposed V (16B-aligned rows)

// ---------------------------------------------------------------------------
// Scratch (device globals — no allocation allowed). .bss is zero-initialized;
// pad regions are never written and stay 0 (deterministic).
// ---------------------------------------------------------------------------
__device__ __align__(16) float g_q [B_*H_*S_*HD_];   // fp32 Q pre-rope [b,h,s,d]
__device__ __align__(16) float g_k [B_*H_*S_*HD_];   // fp32 K pre-rope

// attention operands, fp16 split form (written once, read by attn)
__device__ __align__(16) __half g_qh[B_*H_*S_*HD_];
__device__ __align__(16) __half g_ql[B_*H_*S_*HD_];
__device__ __align__(16) __half g_kh[B_*H_*S_*HD_];
__device__ __align__(16) __half g_vth[B_*H_*HD_*SVP];   // V^T [b,h,d,s]
__device__ __align__(16) __half g_vtl[B_*H_*HD_*SVP];

// GEMM operands, fp16 split form
__device__ __align__(16) __half g_xhi [MPAD*D_];
__device__ __align__(16) __half g_xlo [MPAD*D_];
__device__ __align__(16) __half g_aohi[MPAD*D_];  // attn out split [m,n]
__device__ __align__(16) __half g_aolo[MPAD*D_];
__device__ __align__(16) __half g_wthi[4*D_*D_];  // W^T hi, [w][n][k]

// ---------------------------------------------------------------------------
// mma.sync helpers (portable PTX — no sm_103a-only features)
// ---------------------------------------------------------------------------
__device__ __forceinline__ uint32_t smem_u32(const void* p) {
    uint32_t a;
    asm("{ .reg .u64 t; cvta.to.shared.u64 t, %1; cvt.u32.u64 %0, t; }"
        : "=r"(a) : "l"(p));
    return a;
}
__device__ __forceinline__ void ldsm4(uint32_t* r, uint32_t addr) {
    asm volatile("ldmatrix.sync.aligned.m8n8.x4.shared.b16 {%0,%1,%2,%3}, [%4];"
        : "=r"(r[0]), "=r"(r[1]), "=r"(r[2]), "=r"(r[3]) : "r"(addr));
}
__device__ __forceinline__ void mmah16816(float* c, const uint32_t* a,
                                          const uint32_t* b) {
    asm volatile(
        "mma.sync.aligned.m16n8k16.row.col.f32.f16.f16.f32 "
        "{%0,%1,%2,%3}, {%4,%5,%6,%7}, {%8,%9}, {%0,%1,%2,%3};"
        : "+f"(c[0]), "+f"(c[1]), "+f"(c[2]), "+f"(c[3])
        : "r"(a[0]), "r"(a[1]), "r"(a[2]), "r"(a[3]), "r"(b[0]), "r"(b[1]));
}

// ---------------------------------------------------------------------------
// Split x into fp16 hi/lo.
// ---------------------------------------------------------------------------
__global__ void split_act(const float* __restrict__ src)
{
    const int total4 = M_ * D_ / 4;
    int i = blockIdx.x * blockDim.x + threadIdx.x;
    if (i >= total4) return;
    float4 v = ((const float4*)src)[i];
    __half h0 = __float2half_rn(v.x), h1 = __float2half_rn(v.y);
    __half h2 = __float2half_rn(v.z), h3 = __float2half_rn(v.w);
    __half2* Hi = (__half2*)g_xhi;
    __half2* Lo = (__half2*)g_xlo;
    Hi[2*i]   = __halves2half2(h0, h1);
    Hi[2*i+1] = __halves2half2(h2, h3);
    Lo[2*i]   = __halves2half2(__float2half_rn(v.x - __half2float(h0)),
                               __float2half_rn(v.y - __half2float(h1)));
    Lo[2*i+1] = __halves2half2(__float2half_rn(v.z - __half2float(h2)),
                               __float2half_rn(v.w - __half2float(h3)));
}

// ---------------------------------------------------------------------------
// Transpose + round a weight: W[k][n] fp32 -> Wt_hi[n][k] fp16 at slot widx
// ---------------------------------------------------------------------------
__global__ void split_w(const float* __restrict__ W, int widx)
{
    __shared__ float t[32][33];
    int n0 = blockIdx.x * 32, k0 = blockIdx.y * 32;
    int tx = threadIdx.x, ty = threadIdx.y;   // 32 x 8
    #pragma unroll
    for (int i = 0; i < 4; i++)
        t[ty + 8*i][tx] = W[(size_t)(k0 + ty + 8*i) * D_ + n0 + tx];
    __syncthreads();
    __half* Hi = g_wthi + (size_t)widx * D_ * D_;
    #pragma unroll
    for (int i = 0; i < 4; i++) {
        float v = t[tx][ty + 8*i];
        Hi[(size_t)(n0 + ty + 8*i) * D_ + k0 + tx] = __float2half_rn(v);
    }
}

// ---------------------------------------------------------------------------
// fp16 2-term tensor-core GEMM: C = (Ahi + Alo) * Bhi. 32 chunks, BK=32,
// double-buffered 60KB dynamic smem (2 bufs x 3 tiles x 128x40 fp16).
// mode 0: dst[m*D+n]; mode 1/2: fp32 g_q/g_k; mode 3: fp16 split V^T.
// ---------------------------------------------------------------------------
#define ASTRIDE 40
#define TILEB (128*ASTRIDE)                 // elems per tile
#define GEMM_SMEM (2*3*TILEB*2)             // 61440 bytes

__global__ __launch_bounds__(256) void mma_gemm(
    int asel, int widx, const float* __restrict__ bias,
    float* __restrict__ dst, int mode)
{
    extern __shared__ __half smg[];         // [2][3][TILEB]: Ahi,Alo,Bhi

    const int tid  = threadIdx.x;
    const int lane = tid & 31, wid = tid >> 5;
    const int wm = wid & 1, wn = wid >> 1;
    const int bm = blockIdx.x * 128, bn = blockIdx.y * 128;

    const __half* Ahi = asel ? g_aohi : g_xhi;
    const __half* Alo = asel ? g_aolo : g_xlo;
    const __half* Bhi = g_wthi + (size_t)widx * D_ * D_;

    float acc[4][4][4] = {};

    // prologue: chunk 0
    #pragma unroll
    for (int it = 0; it < 2; it++) {
        int idx = tid + it * 256;
        int r = idx >> 2, c8 = (idx & 3) * 8;
        size_t ao = (size_t)(bm + r) * D_ + c8;
        size_t bo = (size_t)(bn + r) * D_ + c8;
        *(uint4*)&smg[0*TILEB + r*ASTRIDE + c8] = *(const uint4*)(Ahi + ao);
        *(uint4*)&smg[1*TILEB + r*ASTRIDE + c8] = *(const uint4*)(Alo + ao);
        *(uint4*)&smg[2*TILEB + r*ASTRIDE + c8] = *(const uint4*)(Bhi + bo);
    }
    __syncthreads();

    const uint32_t smB = smem_u32(smg);
    const uint32_t aOff = (uint32_t)(wm*64 + (lane & 15)) * 80 + (lane >> 4) * 16;
    const uint32_t bOff = (uint32_t)(wn*32 + (lane & 7) + ((lane >> 4) << 3)) * 80
                          + ((lane >> 3) & 1) * 16;
    const uint32_t TB = TILEB * 2;      // tile bytes
    const uint32_t BUFB = 3 * TB;       // buffer bytes

    const int NCH = 32;
    uint4 p[6];
    for (int t = 0; t < NCH; t++) {
        int buf = t & 1;
        if (t + 1 < NCH) {
            int k0 = (t + 1) * 32;
            #pragma unroll
            for (int it = 0; it < 2; it++) {
                int idx = tid + it * 256;
                int r = idx >> 2, c8 = (idx & 3) * 8;
                size_t ao = (size_t)(bm + r) * D_ + k0 + c8;
                size_t bo = (size_t)(bn + r) * D_ + k0 + c8;
                p[it*3 + 0] = *(const uint4*)(Ahi + ao);
                p[it*3 + 1] = *(const uint4*)(Alo + ao);
                p[it*3 + 2] = *(const uint4*)(Bhi + bo);
            }
        }
        uint32_t aHiB = smB + buf * BUFB;
        uint32_t aLoB = aHiB + TB;
        uint32_t bHiB = aHiB + 2 * TB;
        #pragma unroll
        for (int ks = 0; ks < 2; ks++) {
            uint32_t afh[4][4], bfh[2][4];
            #pragma unroll
            for (int mt = 0; mt < 4; mt++)
                ldsm4(afh[mt], aHiB + aOff + mt * 16 * 80 + ks * 32);
            #pragma unroll
            for (int bt = 0; bt < 2; bt++)
                ldsm4(bfh[bt], bHiB + bOff + bt * 16 * 80 + ks * 32);
            #pragma unroll
            for (int mt = 0; mt < 4; mt++)
                #pragma unroll
                for (int nt = 0; nt < 4; nt++)
                    mmah16816(acc[mt][nt], afh[mt], &bfh[nt >> 1][(nt & 1) * 2]);
            // lo * hi
            {
                uint32_t afl[4][4];
                #pragma unroll
                for (int mt = 0; mt < 4; mt++)
                    ldsm4(afl[mt], aLoB + aOff + mt * 16 * 80 + ks * 32);
                #pragma unroll
                for (int mt = 0; mt < 4; mt++)
                    #pragma unroll
                    for (int nt = 0; nt < 4; nt++)
                        mmah16816(acc[mt][nt], afl[mt], &bfh[nt >> 1][(nt & 1) * 2]);
            }
        }
        if (t + 1 < NCH) {
            int nb = buf ^ 1;
            __half* d0 = smg + nb * 3 * TILEB;
            #pragma unroll
            for (int it = 0; it < 2; it++) {
                int idx = tid + it * 256;
                int r = idx >> 2, c8 = (idx & 3) * 8;
                *(uint4*)&d0[0*TILEB + r*ASTRIDE + c8] = p[it*3 + 0];
                *(uint4*)&d0[1*TILEB + r*ASTRIDE + c8] = p[it*3 + 1];
                *(uint4*)&d0[2*TILEB + r*ASTRIDE + c8] = p[it*3 + 2];
            }
        }
        __syncthreads();
    }

    const int rg = lane >> 2, cp = (lane & 3) * 2;
    #pragma unroll
    for (int mt = 0; mt < 4; mt++) {
        #pragma unroll
        for (int nt = 0; nt < 4; nt++) {
            int n = bn + wn*32 + nt*8 + cp;
            float b0v = bias ? __ldg(bias + n)     : 0.f;
            float b1v = bias ? __ldg(bias + n + 1) : 0.f;
            #pragma unroll
            for (int h2 = 0; h2 < 2; h2++) {
                int m = bm + wm*64 + mt*16 + rg + h2*8;
                if (m >= M_) continue;
                float v0 = acc[mt][nt][h2*2 + 0] + b0v;
                float v1 = acc[mt][nt][h2*2 + 1] + b1v;
                if (mode == 0) {
                    dst[(size_t)m * D_ + n]     = v0;
                    dst[(size_t)m * D_ + n + 1] = v1;
                } else if (mode == 3) {
                    // V: write transposed fp16 split [b,h,d,s]
                    int b = m / S_, s = m % S_;
                    int h = n >> 6, d = n & 63;
                    size_t o = ((size_t)(b * H_ + h) * HD_ + d) * SVP + s;
                    __half hv0 = __float2half_rn(v0);
                    __half hv1 = __float2half_rn(v1);
                    g_vth[o]       = hv0;
                    g_vtl[o]       = __float2half_rn(v0 - __half2float(hv0));
                    g_vth[o + SVP] = hv1;
                    g_vtl[o + SVP] = __float2half_rn(v1 - __half2float(hv1));
                } else {
                    int b = m / S_, s = m % S_;
                    int h = n >> 6, d = n & 63;
                    float* g = (mode == 1) ? g_q : g_k;
                    size_t o = (((size_t)(b * H_ + h)) * S_ + s) * HD_ + d;
                    g[o]     = v0;
                    g[o + 1] = v1;
                }
            }
        }
    }
}

// ---------------------------------------------------------------------------
// RoPE (patch tokens only) + q-scale; emits fp16 splits (Q: hi+lo, K: hi only)
// ---------------------------------------------------------------------------
__global__ void rope_kernel(const float* __restrict__ cosp,
                            const float* __restrict__ sinp)
{
    const int total = B_*H_*S_*32;
    int i = blockIdx.x * blockDim.x + threadIdx.x;
    if (i >= total) return;
    const bool isQ = (blockIdx.y == 0);
    int dh = i & 31;
    int s  = (i >> 5) % S_;
    int bh = i / (32 * S_);
    size_t base = ((size_t)bh * S_ + s) * HD_;
    const float* ptr = (isQ ? g_q : g_k) + base;
    float y0, y1;
    if (s < NPFX) {
        y0 = ptr[dh]; y1 = ptr[dh+32];
    } else {
        int p = s - NPFX;
        float c0 = cosp[p*HD_ + dh],      c1 = cosp[p*HD_ + dh + 32];
        float s0 = sinp[p*HD_ + dh],      s1 = sinp[p*HD_ + dh + 32];
        float x0 = ptr[dh], x1 = ptr[dh+32];
        y0 = x0*c0 - x1*s0;
        y1 = x1*c1 + x0*s1;
    }
    __half h0, h1;
    if (isQ) {
        y0 *= SCALE_; y1 *= SCALE_;
        h0 = __float2half_rn(y0); h1 = __float2half_rn(y1);
        g_qh[base + dh]      = h0;
        g_qh[base + dh + 32] = h1;
        g_ql[base + dh]      = __float2half_rn(y0 - __half2float(h0));
        g_ql[base + dh + 32] = __float2half_rn(y1 - __half2float(h1));
    } else {
        g_kh[base + dh]      = __float2half_rn(y0);
        g_kh[base + dh + 32] = __float2half_rn(y1);
    }
}

// ---------------------------------------------------------------------------
// Tensor-core flash attention (proven R9). QK: 2-term (full-Q x K-hi).
// PV: P x (Vhi+Vlo). Epilogue writes fp16 hi/lo splits for out projection.
// ---------------------------------------------------------------------------
#define QST 72
#define SST 73
#define ATT_SMEM (6*64*QST*2 + 64*SST*4 + (3*64 + 512)*4)   // 76800

__global__ __launch_bounds__(256) void attn_kernel()
{
    extern __shared__ char smx[];
    __half* Qhi  = (__half*)smx;            // [64][QST]  (q, d)
    __half* Qlo  = Qhi  + 64*QST;
    __half* Khi  = Qlo  + 64*QST;           // [64][QST]  (key, d)
    __half* Vthi = Khi  + 64*QST;           // [64][QST]  (d, key)
    __half* Vtlo = Vthi + 64*QST;
    __half* Pm   = Vtlo + 64*QST;           // [64][QST]  (q, key)
    float*  S32  = (float*)(Pm + 64*QST);   // [64][SST]  (q, key)
    float*  m_s  = S32 + 64*SST;            // [64]
    float*  l_s  = m_s + 64;
    float*  al_s = l_s + 64;
    float*  redm = al_s + 64;               // [4][64]
    float*  reds = redm + 256;              // [4][64]

    const int tid  = threadIdx.x;
    const int lane = tid & 31, wid = tid >> 5;
    const int wm = wid & 1, wn = wid >> 1;     // 2 x 4 warp grid
    const int rg = lane >> 2, cp = (lane & 3) * 2;
    const int bh = blockIdx.y;
    const int m0 = blockIdx.x * 64;
    const __half* qhp = g_qh + (size_t)bh * S_ * HD_;
    const __half* qlp = g_ql + (size_t)bh * S_ * HD_;
    const __half* khp = g_kh + (size_t)bh * S_ * HD_;
    const __half* vhp = g_vth + (size_t)bh * HD_ * SVP;
    const __half* vlp = g_vtl + (size_t)bh * HD_ * SVP;

    // Q tile: uint4 copies (zero-fill tail rows)
    const uint4 Z4 = make_uint4(0u, 0u, 0u, 0u);
    #pragma unroll
    for (int it = 0; it < 2; it++) {
        int idx = tid + it * 256;              // 0..511
        int r = idx >> 3, c8 = (idx & 7) * 8;
        uint4 vh = Z4, vl = Z4;
        if (m0 + r < S_) {
            size_t o = (size_t)(m0 + r) * HD_ + c8;
            vh = *(const uint4*)(qhp + o);
            vl = *(const uint4*)(qlp + o);
        }
        *(uint4*)&Qhi[r*QST + c8] = vh;
        *(uint4*)&Qlo[r*QST + c8] = vl;
    }
    if (tid < 64) { m_s[tid] = -1e30f; l_s[tid] = 0.f; }

    const uint32_t QhiB = smem_u32(Qhi),  QloB = smem_u32(Qlo);
    const uint32_t KhiB = smem_u32(Khi);
    const uint32_t VhiB = smem_u32(Vthi), VloB = smem_u32(Vtlo);
    const uint32_t PmB  = smem_u32(Pm);
    const uint32_t aOff = (uint32_t)(wm*32 + (lane & 15)) * 144 + (lane >> 4) * 16;
    const uint32_t bOff = (uint32_t)(wn*16 + (lane & 7) + ((lane >> 4) << 3)) * 144
                          + ((lane >> 3) & 1) * 16;

    float oacc[2][2][4] = {};
    const int sq = tid & 63, part = tid >> 6;

    for (int n0 = 0; n0 < S_; n0 += 64) {
        __syncthreads();   // protects K/V/P reuse + first-iter init
        // K tile [key][d]: uint4 copies (hi only)
        #pragma unroll
        for (int it = 0; it < 2; it++) {
            int idx = tid + it * 256;
            int r = idx >> 3, c8 = (idx & 7) * 8;
            uint4 vh = Z4;
            if (n0 + r < S_)
                vh = *(const uint4*)(khp + (size_t)(n0 + r) * HD_ + c8);
            *(uint4*)&Khi[r*QST + c8] = vh;
        }
        // Vt tile [d][key]: uint4 copies from padded transposed layout
        #pragma unroll
        for (int it = 0; it < 2; it++) {
            int idx = tid + it * 256;
            int d = idx >> 3, k8 = (idx & 7) * 8;
            size_t o = (size_t)d * SVP + n0 + k8;
            *(uint4*)&Vthi[d*QST + k8] = *(const uint4*)(vhp + o);
            *(uint4*)&Vtlo[d*QST + k8] = *(const uint4*)(vlp + o);
        }
        __syncthreads();

        // S = (Qhi + Qlo) K_hi^T  (2-term)
        float sacc[2][2][4] = {};
        #pragma unroll
        for (int ks = 0; ks < 4; ks++) {
            uint32_t ah[2][4], al[2][4], bhh[4];
            #pragma unroll
            for (int mt = 0; mt < 2; mt++) {
                ldsm4(ah[mt], QhiB + aOff + mt * 16 * 144 + ks * 32);
                ldsm4(al[mt], QloB + aOff + mt * 16 * 144 + ks * 32);
            }
            ldsm4(bhh, KhiB + bOff + ks * 32);
            #pragma unroll
            for (int mt = 0; mt < 2; mt++)
                #pragma unroll
                for (int nt = 0; nt < 2; nt++) {
                    mmah16816(sacc[mt][nt], ah[mt], &bhh[nt*2]);
                    mmah16816(sacc[mt][nt], al[mt], &bhh[nt*2]);
                }
        }
        // store S frags
        #pragma unroll
        for (int mt = 0; mt < 2; mt++)
            #pragma unroll
            for (int nt = 0; nt < 2; nt++) {
                int q0 = wm*32 + mt*16 + rg;
                int kc = wn*16 + nt*8 + cp;
                S32[q0*SST + kc]       = sacc[mt][nt][0];
                S32[q0*SST + kc + 1]   = sacc[mt][nt][1];
                S32[(q0+8)*SST + kc]     = sacc[mt][nt][2];
                S32[(q0+8)*SST + kc + 1] = sacc[mt][nt][3];
            }
        __syncthreads();

        // per-query max over this tile (4 partials)
        {
            float pm = -1e30f;
            #pragma unroll
            for (int i = 0; i < 16; i++) {
                int kk = part*16 + i;
                float v = S32[sq*SST + kk];
                pm = fmaxf(pm, (n0 + kk < S_) ? v : -1e30f);
            }
            redm[part*64 + sq] = pm;
        }
        __syncthreads();
        if (tid < 64) {
            float nm = fmaxf(fmaxf(redm[sq], redm[64+sq]),
                             fmaxf(redm[128+sq], redm[192+sq]));
            nm = fmaxf(nm, m_s[sq]);
            al_s[sq] = __expf(m_s[sq] - nm);
            m_s[sq]  = nm;
        }
        __syncthreads();
        // exp -> P fp16, partial sums
        {
            float mr = m_s[sq];
            float ps = 0.f;
            #pragma unroll
            for (int i = 0; i < 16; i++) {
                int kk = part*16 + i;
                float e = 0.f;
                if (n0 + kk < S_) e = __expf(S32[sq*SST + kk] - mr);
                Pm[sq*QST + kk] = __float2half_rn(e);
                ps += e;
            }
            reds[part*64 + sq] = ps;
        }
        __syncthreads();
        if (tid < 64)
            l_s[sq] = l_s[sq]*al_s[sq] + reds[sq] + reds[64+sq]
                      + reds[128+sq] + reds[192+sq];

        // rescale O frags by alpha
        #pragma unroll
        for (int mt = 0; mt < 2; mt++) {
            float a0 = al_s[wm*32 + mt*16 + rg];
            float a1 = al_s[wm*32 + mt*16 + rg + 8];
            #pragma unroll
            for (int nt = 0; nt < 2; nt++) {
                oacc[mt][nt][0] *= a0; oacc[mt][nt][1] *= a0;
                oacc[mt][nt][2] *= a1; oacc[mt][nt][3] *= a1;
            }
        }
        // O += P * V (V split 2-term)
        #pragma unroll
        for (int ks = 0; ks < 4; ks++) {
            uint32_t ap[2][4], vh[4], vl[4];
            #pragma unroll
            for (int mt = 0; mt < 2; mt++)
                ldsm4(ap[mt], PmB + aOff + mt * 16 * 144 + ks * 32);
            ldsm4(vh, VhiB + bOff + ks * 32);
            ldsm4(vl, VloB + bOff + ks * 32);
            #pragma unroll
            for (int mt = 0; mt < 2; mt++)
                #pragma unroll
                for (int nt = 0; nt < 2; nt++) {
                    mmah16816(oacc[mt][nt], ap[mt], &vh[nt*2]);
                    mmah16816(oacc[mt][nt], ap[mt], &vl[nt*2]);
                }
        }
    }
    __syncthreads();   // final l_s visible

    // epilogue: write fp16 hi/lo splits for the output projection
    const int b = bh / H_, h = bh % H_;
    #pragma unroll
    for (int mt = 0; mt < 2; mt++) {
        #pragma unroll
        for (int h2 = 0; h2 < 2; h2++) {
            int q0 = wm*32 + mt*16 + rg + h2*8;
            int m = m0 + q0;
            if (m >= S_) continue;
            float inv = 1.f / l_s[q0];
            #pragma unroll
            for (int nt = 0; nt < 2; nt++) {
                int d0 = wn*16 + nt*8 + cp;
                float w0 = oacc[mt][nt][h2*2 + 0] * inv;
                float w1 = oacc[mt][nt][h2*2 + 1] * inv;
                __half b0 = __float2half_rn(w0);
                __half b1 = __float2half_rn(w1);
                size_t o = ((size_t)b * S_ + m) * D_ + h * HD_ + d0;
                *(__half2*)&g_aohi[o] = __halves2half2(b0, b1);
                *(__half2*)&g_aolo[o] = __halves2half2(
                    __float2half_rn(w0 - __half2float(b0)),
                    __float2half_rn(w1 - __half2float(b1)));
            }
        }
    }
}

// ---------------------------------------------------------------------------
extern "C" void kernel_launch(void* const* d_in, const int* in_sizes, int n_in,
                              void* d_out, int out_size)
{
    const float* x        = (const float*)d_in[0];
    const float* rope_cos = (const float*)d_in[1];
    const float* rope_sin = (const float*)d_in[2];
    const float* Wq       = (const float*)d_in[3];
    const float* bq       = (const float*)d_in[4];
    const float* Wk       = (const float*)d_in[5];
    const float* Wv       = (const float*)d_in[6];
    const float* bv       = (const float*)d_in[7];
    const float* Wo       = (const float*)d_in[8];
    const float* bo       = (const float*)d_in[9];
    float* out = (float*)d_out;

    cudaFuncSetAttribute(attn_kernel,
        cudaFuncAttributeMaxDynamicSharedMemorySize, ATT_SMEM);
    cudaFuncSetAttribute(mma_gemm,
        cudaFuncAttributeMaxDynamicSharedMemorySize, GEMM_SMEM);

    dim3 gg(MPAD / 128, D_ / 128);             // 65 x 8
    dim3 wg(32, 32), wb(32, 8);
    int t4 = M_ * D_ / 4;

    split_act<<<(t4 + 255) / 256, 256>>>(x);
    split_w<<<wg, wb>>>(Wq, 0);
    mma_gemm<<<gg, 256, GEMM_SMEM>>>(0, 0, bq,      nullptr, 1);
    split_w<<<wg, wb>>>(Wk, 1);
    mma_gemm<<<gg, 256, GEMM_SMEM>>>(0, 1, nullptr, nullptr, 2);
    split_w<<<wg, wb>>>(Wv, 2);
    mma_gemm<<<gg, 256, GEMM_SMEM>>>(0, 2, bv,      nullptr, 3);
    split_w<<<wg, wb>>>(Wo, 3);

    int pairs = B_*H_*S_*32;
    dim3 g2((pairs + 255) / 256, 2);
    rope_kernel<<<g2, 256>>>(rope_cos, rope_sin);

    dim3 g3((S_ + 63) / 64, B_*H_);            // 17 x 128
    attn_kernel<<<g3, 256, ATT_SMEM>>>();

    // output projection (reads g_aohi/g_aolo written by attn)
    mma_gemm<<<gg, 256, GEMM_SMEM>>>(1, 3, bo, out, 0);
}

// round 11
// speedup vs baseline: 3.3263x; 1.1838x over previous
#include <cuda_runtime.h>
#include <cuda_bf16.h>
#include <cuda_fp16.h>
#include <cstdint>

#define B_    8
#define S_    1029
#define D_    1024
#define H_    16
#define HD_   64
#define M_    (B_*S_)     // 8232
#define MPAD  8320        // 65 * 128
#define NPFX  5
#define SCALE_ 0.125f
#define SVP   1088        // padded key-stride for transposed V (16B-aligned rows)

// ---------------------------------------------------------------------------
// Scratch (device globals — no allocation allowed). .bss is zero-initialized;
// pad regions are never written and stay 0 (deterministic).
// ---------------------------------------------------------------------------
__device__ __align__(16) float g_q [B_*H_*S_*HD_];   // fp32 Q pre-rope [b,h,s,d]
__device__ __align__(16) float g_k [B_*H_*S_*HD_];   // fp32 K pre-rope

// attention operands, fp16 form (written once, read by attn)
__device__ __align__(16) __half g_qh[B_*H_*S_*HD_];
__device__ __align__(16) __half g_ql[B_*H_*S_*HD_];
__device__ __align__(16) __half g_kh[B_*H_*S_*HD_];
__device__ __align__(16) __half g_vth[B_*H_*HD_*SVP];   // V^T hi [b,h,d,s]

// GEMM operands, fp16 split form
__device__ __align__(16) __half g_xhi [MPAD*D_];
__device__ __align__(16) __half g_xlo [MPAD*D_];
__device__ __align__(16) __half g_aohi[MPAD*D_];  // attn out (fp16) [m,n]
__device__ __align__(16) __half g_wthi[4*D_*D_];  // W^T hi, [w][n][k]

// ---------------------------------------------------------------------------
// mma.sync helpers (portable PTX — no sm_103a-only features)
// ---------------------------------------------------------------------------
__device__ __forceinline__ uint32_t smem_u32(const void* p) {
    uint32_t a;
    asm("{ .reg .u64 t; cvta.to.shared.u64 t, %1; cvt.u32.u64 %0, t; }"
        : "=r"(a) : "l"(p));
    return a;
}
__device__ __forceinline__ void ldsm4(uint32_t* r, uint32_t addr) {
    asm volatile("ldmatrix.sync.aligned.m8n8.x4.shared.b16 {%0,%1,%2,%3}, [%4];"
        : "=r"(r[0]), "=r"(r[1]), "=r"(r[2]), "=r"(r[3]) : "r"(addr));
}
__device__ __forceinline__ void mmah16816(float* c, const uint32_t* a,
                                          const uint32_t* b) {
    asm volatile(
        "mma.sync.aligned.m16n8k16.row.col.f32.f16.f16.f32 "
        "{%0,%1,%2,%3}, {%4,%5,%6,%7}, {%8,%9}, {%0,%1,%2,%3};"
        : "+f"(c[0]), "+f"(c[1]), "+f"(c[2]), "+f"(c[3])
        : "r"(a[0]), "r"(a[1]), "r"(a[2]), "r"(a[3]), "r"(b[0]), "r"(b[1]));
}

// ---------------------------------------------------------------------------
// Split x into fp16 hi/lo.
// ---------------------------------------------------------------------------
__global__ void split_act(const float* __restrict__ src)
{
    const int total4 = M_ * D_ / 4;
    int i = blockIdx.x * blockDim.x + threadIdx.x;
    if (i >= total4) return;
    float4 v = ((const float4*)src)[i];
    __half h0 = __float2half_rn(v.x), h1 = __float2half_rn(v.y);
    __half h2 = __float2half_rn(v.z), h3 = __float2half_rn(v.w);
    __half2* Hi = (__half2*)g_xhi;
    __half2* Lo = (__half2*)g_xlo;
    Hi[2*i]   = __halves2half2(h0, h1);
    Hi[2*i+1] = __halves2half2(h2, h3);
    Lo[2*i]   = __halves2half2(__float2half_rn(v.x - __half2float(h0)),
                               __float2half_rn(v.y - __half2float(h1)));
    Lo[2*i+1] = __halves2half2(__float2half_rn(v.z - __half2float(h2)),
                               __float2half_rn(v.w - __half2float(h3)));
}

// ---------------------------------------------------------------------------
// Transpose + round a weight: W[k][n] fp32 -> Wt_hi[n][k] fp16 at slot widx
// ---------------------------------------------------------------------------
__global__ void split_w(const float* __restrict__ W, int widx)
{
    __shared__ float t[32][33];
    int n0 = blockIdx.x * 32, k0 = blockIdx.y * 32;
    int tx = threadIdx.x, ty = threadIdx.y;   // 32 x 8
    #pragma unroll
    for (int i = 0; i < 4; i++)
        t[ty + 8*i][tx] = W[(size_t)(k0 + ty + 8*i) * D_ + n0 + tx];
    __syncthreads();
    __half* Hi = g_wthi + (size_t)widx * D_ * D_;
    #pragma unroll
    for (int i = 0; i < 4; i++) {
        float v = t[tx][ty + 8*i];
        Hi[(size_t)(n0 + ty + 8*i) * D_ + k0 + tx] = __float2half_rn(v);
    }
}

// ---------------------------------------------------------------------------
// fp16 tensor-core GEMM: C = (Ahi [+ Alo]) * Bhi. 32 chunks, BK=32,
// double-buffered 60KB dynamic smem. terms: 1 or 2 (Alo correction).
// mode 0: dst[m*D+n]; mode 1/2: fp32 g_q/g_k; mode 3: fp16 V^T hi.
// ---------------------------------------------------------------------------
#define ASTRIDE 40
#define TILEB (128*ASTRIDE)                 // elems per tile
#define GEMM_SMEM (2*3*TILEB*2)             // 61440 bytes

__global__ __launch_bounds__(256) void mma_gemm(
    int asel, int widx, const float* __restrict__ bias,
    float* __restrict__ dst, int mode, int terms)
{
    extern __shared__ __half smg[];         // [2][3][TILEB]: Ahi,Alo,Bhi

    const int tid  = threadIdx.x;
    const int lane = tid & 31, wid = tid >> 5;
    const int wm = wid & 1, wn = wid >> 1;
    const int bm = blockIdx.x * 128, bn = blockIdx.y * 128;

    const __half* Ahi = asel ? g_aohi : g_xhi;
    const __half* Alo = g_xlo;              // only used when terms == 2
    const __half* Bhi = g_wthi + (size_t)widx * D_ * D_;

    float acc[4][4][4] = {};

    // prologue: chunk 0
    #pragma unroll
    for (int it = 0; it < 2; it++) {
        int idx = tid + it * 256;
        int r = idx >> 2, c8 = (idx & 3) * 8;
        size_t ao = (size_t)(bm + r) * D_ + c8;
        size_t bo = (size_t)(bn + r) * D_ + c8;
        *(uint4*)&smg[0*TILEB + r*ASTRIDE + c8] = *(const uint4*)(Ahi + ao);
        if (terms == 2)
            *(uint4*)&smg[1*TILEB + r*ASTRIDE + c8] = *(const uint4*)(Alo + ao);
        *(uint4*)&smg[2*TILEB + r*ASTRIDE + c8] = *(const uint4*)(Bhi + bo);
    }
    __syncthreads();

    const uint32_t smB = smem_u32(smg);
    const uint32_t aOff = (uint32_t)(wm*64 + (lane & 15)) * 80 + (lane >> 4) * 16;
    const uint32_t bOff = (uint32_t)(wn*32 + (lane & 7) + ((lane >> 4) << 3)) * 80
                          + ((lane >> 3) & 1) * 16;
    const uint32_t TB = TILEB * 2;      // tile bytes
    const uint32_t BUFB = 3 * TB;       // buffer bytes

    const int NCH = 32;
    uint4 p[6];
    for (int t = 0; t < NCH; t++) {
        int buf = t & 1;
        if (t + 1 < NCH) {
            int k0 = (t + 1) * 32;
            #pragma unroll
            for (int it = 0; it < 2; it++) {
                int idx = tid + it * 256;
                int r = idx >> 2, c8 = (idx & 3) * 8;
                size_t ao = (size_t)(bm + r) * D_ + k0 + c8;
                size_t bo = (size_t)(bn + r) * D_ + k0 + c8;
                p[it*3 + 0] = *(const uint4*)(Ahi + ao);
                if (terms == 2) p[it*3 + 1] = *(const uint4*)(Alo + ao);
                p[it*3 + 2] = *(const uint4*)(Bhi + bo);
            }
        }
        uint32_t aHiB = smB + buf * BUFB;
        uint32_t aLoB = aHiB + TB;
        uint32_t bHiB = aHiB + 2 * TB;
        #pragma unroll
        for (int ks = 0; ks < 2; ks++) {
            uint32_t afh[4][4], bfh[2][4];
            #pragma unroll
            for (int mt = 0; mt < 4; mt++)
                ldsm4(afh[mt], aHiB + aOff + mt * 16 * 80 + ks * 32);
            #pragma unroll
            for (int bt = 0; bt < 2; bt++)
                ldsm4(bfh[bt], bHiB + bOff + bt * 16 * 80 + ks * 32);
            #pragma unroll
            for (int mt = 0; mt < 4; mt++)
                #pragma unroll
                for (int nt = 0; nt < 4; nt++)
                    mmah16816(acc[mt][nt], afh[mt], &bfh[nt >> 1][(nt & 1) * 2]);
            if (terms == 2) {
                uint32_t afl[4][4];
                #pragma unroll
                for (int mt = 0; mt < 4; mt++)
                    ldsm4(afl[mt], aLoB + aOff + mt * 16 * 80 + ks * 32);
                #pragma unroll
                for (int mt = 0; mt < 4; mt++)
                    #pragma unroll
                    for (int nt = 0; nt < 4; nt++)
                        mmah16816(acc[mt][nt], afl[mt], &bfh[nt >> 1][(nt & 1) * 2]);
            }
        }
        if (t + 1 < NCH) {
            int nb = buf ^ 1;
            __half* d0 = smg + nb * 3 * TILEB;
            #pragma unroll
            for (int it = 0; it < 2; it++) {
                int idx = tid + it * 256;
                int r = idx >> 2, c8 = (idx & 3) * 8;
                *(uint4*)&d0[0*TILEB + r*ASTRIDE + c8] = p[it*3 + 0];
                if (terms == 2)
                    *(uint4*)&d0[1*TILEB + r*ASTRIDE + c8] = p[it*3 + 1];
                *(uint4*)&d0[2*TILEB + r*ASTRIDE + c8] = p[it*3 + 2];
            }
        }
        __syncthreads();
    }

    const int rg = lane >> 2, cp = (lane & 3) * 2;
    #pragma unroll
    for (int mt = 0; mt < 4; mt++) {
        #pragma unroll
        for (int nt = 0; nt < 4; nt++) {
            int n = bn + wn*32 + nt*8 + cp;
            float b0v = bias ? __ldg(bias + n)     : 0.f;
            float b1v = bias ? __ldg(bias + n + 1) : 0.f;
            #pragma unroll
            for (int h2 = 0; h2 < 2; h2++) {
                int m = bm + wm*64 + mt*16 + rg + h2*8;
                if (m >= M_) continue;
                float v0 = acc[mt][nt][h2*2 + 0] + b0v;
                float v1 = acc[mt][nt][h2*2 + 1] + b1v;
                if (mode == 0) {
                    dst[(size_t)m * D_ + n]     = v0;
                    dst[(size_t)m * D_ + n + 1] = v1;
                } else if (mode == 3) {
                    // V: write transposed fp16 hi [b,h,d,s]
                    int b = m / S_, s = m % S_;
                    int h = n >> 6, d = n & 63;
                    size_t o = ((size_t)(b * H_ + h) * HD_ + d) * SVP + s;
                    g_vth[o]       = __float2half_rn(v0);
                    g_vth[o + SVP] = __float2half_rn(v1);
                } else {
                    int b = m / S_, s = m % S_;
                    int h = n >> 6, d = n & 63;
                    float* g = (mode == 1) ? g_q : g_k;
                    size_t o = (((size_t)(b * H_ + h)) * S_ + s) * HD_ + d;
                    g[o]     = v0;
                    g[o + 1] = v1;
                }
            }
        }
    }
}

// ---------------------------------------------------------------------------
// RoPE (patch tokens only) + q-scale; emits fp16 splits (Q: hi+lo, K: hi only)
// ---------------------------------------------------------------------------
__global__ void rope_kernel(const float* __restrict__ cosp,
                            const float* __restrict__ sinp)
{
    const int total = B_*H_*S_*32;
    int i = blockIdx.x * blockDim.x + threadIdx.x;
    if (i >= total) return;
    const bool isQ = (blockIdx.y == 0);
    int dh = i & 31;
    int s  = (i >> 5) % S_;
    int bh = i / (32 * S_);
    size_t base = ((size_t)bh * S_ + s) * HD_;
    const float* ptr = (isQ ? g_q : g_k) + base;
    float y0, y1;
    if (s < NPFX) {
        y0 = ptr[dh]; y1 = ptr[dh+32];
    } else {
        int p = s - NPFX;
        float c0 = cosp[p*HD_ + dh],      c1 = cosp[p*HD_ + dh + 32];
        float s0 = sinp[p*HD_ + dh],      s1 = sinp[p*HD_ + dh + 32];
        float x0 = ptr[dh], x1 = ptr[dh+32];
        y0 = x0*c0 - x1*s0;
        y1 = x1*c1 + x0*s1;
    }
    __half h0, h1;
    if (isQ) {
        y0 *= SCALE_; y1 *= SCALE_;
        h0 = __float2half_rn(y0); h1 = __float2half_rn(y1);
        g_qh[base + dh]      = h0;
        g_qh[base + dh + 32] = h1;
        g_ql[base + dh]      = __float2half_rn(y0 - __half2float(h0));
        g_ql[base + dh + 32] = __float2half_rn(y1 - __half2float(h1));
    } else {
        g_kh[base + dh]      = __float2half_rn(y0);
        g_kh[base + dh + 32] = __float2half_rn(y1);
    }
}

// ---------------------------------------------------------------------------
// Tensor-core flash attention. QK: 2-term (full-Q x K-hi). PV: P x V-hi.
// Epilogue writes fp16 ao for the 1-term output projection.
// ---------------------------------------------------------------------------
#define QST 72
#define SST 73
#define ATT_SMEM (5*64*QST*2 + 64*SST*4 + (3*64 + 512)*4)   // 67584

__global__ __launch_bounds__(256) void attn_kernel()
{
    extern __shared__ char smx[];
    __half* Qhi  = (__half*)smx;            // [64][QST]  (q, d)
    __half* Qlo  = Qhi  + 64*QST;
    __half* Khi  = Qlo  + 64*QST;           // [64][QST]  (key, d)
    __half* Vthi = Khi  + 64*QST;           // [64][QST]  (d, key)
    __half* Pm   = Vthi + 64*QST;           // [64][QST]  (q, key)
    float*  S32  = (float*)(Pm + 64*QST);   // [64][SST]  (q, key)
    float*  m_s  = S32 + 64*SST;            // [64]
    float*  l_s  = m_s + 64;
    float*  al_s = l_s + 64;
    float*  redm = al_s + 64;               // [4][64]
    float*  reds = redm + 256;              // [4][64]

    const int tid  = threadIdx.x;
    const int lane = tid & 31, wid = tid >> 5;
    const int wm = wid & 1, wn = wid >> 1;     // 2 x 4 warp grid
    const int rg = lane >> 2, cp = (lane & 3) * 2;
    const int bh = blockIdx.y;
    const int m0 = blockIdx.x * 64;
    const __half* qhp = g_qh + (size_t)bh * S_ * HD_;
    const __half* qlp = g_ql + (size_t)bh * S_ * HD_;
    const __half* khp = g_kh + (size_t)bh * S_ * HD_;
    const __half* vhp = g_vth + (size_t)bh * HD_ * SVP;

    // Q tile: uint4 copies (zero-fill tail rows)
    const uint4 Z4 = make_uint4(0u, 0u, 0u, 0u);
    #pragma unroll
    for (int it = 0; it < 2; it++) {
        int idx = tid + it * 256;              // 0..511
        int r = idx >> 3, c8 = (idx & 7) * 8;
        uint4 vh = Z4, vl = Z4;
        if (m0 + r < S_) {
            size_t o = (size_t)(m0 + r) * HD_ + c8;
            vh = *(const uint4*)(qhp + o);
            vl = *(const uint4*)(qlp + o);
        }
        *(uint4*)&Qhi[r*QST + c8] = vh;
        *(uint4*)&Qlo[r*QST + c8] = vl;
    }
    if (tid < 64) { m_s[tid] = -1e30f; l_s[tid] = 0.f; }

    const uint32_t QhiB = smem_u32(Qhi),  QloB = smem_u32(Qlo);
    const uint32_t KhiB = smem_u32(Khi);
    const uint32_t VhiB = smem_u32(Vthi);
    const uint32_t PmB  = smem_u32(Pm);
    const uint32_t aOff = (uint32_t)(wm*32 + (lane & 15)) * 144 + (lane >> 4) * 16;
    const uint32_t bOff = (uint32_t)(wn*16 + (lane & 7) + ((lane >> 4) << 3)) * 144
                          + ((lane >> 3) & 1) * 16;

    float oacc[2][2][4] = {};
    const int sq = tid & 63, part = tid >> 6;

    for (int n0 = 0; n0 < S_; n0 += 64) {
        __syncthreads();   // protects K/V/P reuse + first-iter init
        // K tile [key][d]: uint4 copies (hi only)
        #pragma unroll
        for (int it = 0; it < 2; it++) {
            int idx = tid + it * 256;
            int r = idx >> 3, c8 = (idx & 7) * 8;
            uint4 vh = Z4;
            if (n0 + r < S_)
                vh = *(const uint4*)(khp + (size_t)(n0 + r) * HD_ + c8);
            *(uint4*)&Khi[r*QST + c8] = vh;
        }
        // Vt tile [d][key]: uint4 copies from padded transposed layout
        #pragma unroll
        for (int it = 0; it < 2; it++) {
            int idx = tid + it * 256;
            int d = idx >> 3, k8 = (idx & 7) * 8;
            size_t o = (size_t)d * SVP + n0 + k8;
            *(uint4*)&Vthi[d*QST + k8] = *(const uint4*)(vhp + o);
        }
        __syncthreads();

        // S = (Qhi + Qlo) K_hi^T  (2-term)
        float sacc[2][2][4] = {};
        #pragma unroll
        for (int ks = 0; ks < 4; ks++) {
            uint32_t ah[2][4], al[2][4], bhh[4];
            #pragma unroll
            for (int mt = 0; mt < 2; mt++) {
                ldsm4(ah[mt], QhiB + aOff + mt * 16 * 144 + ks * 32);
                ldsm4(al[mt], QloB + aOff + mt * 16 * 144 + ks * 32);
            }
            ldsm4(bhh, KhiB + bOff + ks * 32);
            #pragma unroll
            for (int mt = 0; mt < 2; mt++)
                #pragma unroll
                for (int nt = 0; nt < 2; nt++) {
                    mmah16816(sacc[mt][nt], ah[mt], &bhh[nt*2]);
                    mmah16816(sacc[mt][nt], al[mt], &bhh[nt*2]);
                }
        }
        // store S frags
        #pragma unroll
        for (int mt = 0; mt < 2; mt++)
            #pragma unroll
            for (int nt = 0; nt < 2; nt++) {
                int q0 = wm*32 + mt*16 + rg;
                int kc = wn*16 + nt*8 + cp;
                S32[q0*SST + kc]       = sacc[mt][nt][0];
                S32[q0*SST + kc + 1]   = sacc[mt][nt][1];
                S32[(q0+8)*SST + kc]     = sacc[mt][nt][2];
                S32[(q0+8)*SST + kc + 1] = sacc[mt][nt][3];
            }
        __syncthreads();

        // per-query max over this tile (4 partials)
        {
            float pm = -1e30f;
            #pragma unroll
            for (int i = 0; i < 16; i++) {
                int kk = part*16 + i;
                float v = S32[sq*SST + kk];
                pm = fmaxf(pm, (n0 + kk < S_) ? v : -1e30f);
            }
            redm[part*64 + sq] = pm;
        }
        __syncthreads();
        if (tid < 64) {
            float nm = fmaxf(fmaxf(redm[sq], redm[64+sq]),
                             fmaxf(redm[128+sq], redm[192+sq]));
            nm = fmaxf(nm, m_s[sq]);
            al_s[sq] = __expf(m_s[sq] - nm);
            m_s[sq]  = nm;
        }
        __syncthreads();
        // exp -> P fp16, partial sums
        {
            float mr = m_s[sq];
            float ps = 0.f;
            #pragma unroll
            for (int i = 0; i < 16; i++) {
                int kk = part*16 + i;
                float e = 0.f;
                if (n0 + kk < S_) e = __expf(S32[sq*SST + kk] - mr);
                Pm[sq*QST + kk] = __float2half_rn(e);
                ps += e;
            }
            reds[part*64 + sq] = ps;
        }
        __syncthreads();
        if (tid < 64)
            l_s[sq] = l_s[sq]*al_s[sq] + reds[sq] + reds[64+sq]
                      + reds[128+sq] + reds[192+sq];

        // rescale O frags by alpha
        #pragma unroll
        for (int mt = 0; mt < 2; mt++) {
            float a0 = al_s[wm*32 + mt*16 + rg];
            float a1 = al_s[wm*32 + mt*16 + rg + 8];
            #pragma unroll
            for (int nt = 0; nt < 2; nt++) {
                oacc[mt][nt][0] *= a0; oacc[mt][nt][1] *= a0;
                oacc[mt][nt][2] *= a1; oacc[mt][nt][3] *= a1;
            }
        }
        // O += P * V_hi (1-term)
        #pragma unroll
        for (int ks = 0; ks < 4; ks++) {
            uint32_t ap[2][4], vh[4];
            #pragma unroll
            for (int mt = 0; mt < 2; mt++)
                ldsm4(ap[mt], PmB + aOff + mt * 16 * 144 + ks * 32);
            ldsm4(vh, VhiB + bOff + ks * 32);
            #pragma unroll
            for (int mt = 0; mt < 2; mt++)
                #pragma unroll
                for (int nt = 0; nt < 2; nt++)
                    mmah16816(oacc[mt][nt], ap[mt], &vh[nt*2]);
        }
    }
    __syncthreads();   // final l_s visible

    // epilogue: write fp16 ao for the 1-term output projection
    const int b = bh / H_, h = bh % H_;
    #pragma unroll
    for (int mt = 0; mt < 2; mt++) {
        #pragma unroll
        for (int h2 = 0; h2 < 2; h2++) {
            int q0 = wm*32 + mt*16 + rg + h2*8;
            int m = m0 + q0;
            if (m >= S_) continue;
            float inv = 1.f / l_s[q0];
            #pragma unroll
            for (int nt = 0; nt < 2; nt++) {
                int d0 = wn*16 + nt*8 + cp;
                float w0 = oacc[mt][nt][h2*2 + 0] * inv;
                float w1 = oacc[mt][nt][h2*2 + 1] * inv;
                size_t o = ((size_t)b * S_ + m) * D_ + h * HD_ + d0;
                *(__half2*)&g_aohi[o] = __halves2half2(
                    __float2half_rn(w0), __float2half_rn(w1));
            }
        }
    }
}

// ---------------------------------------------------------------------------
extern "C" void kernel_launch(void* const* d_in, const int* in_sizes, int n_in,
                              void* d_out, int out_size)
{
    const float* x        = (const float*)d_in[0];
    const float* rope_cos = (const float*)d_in[1];
    const float* rope_sin = (const float*)d_in[2];
    const float* Wq       = (const float*)d_in[3];
    const float* bq       = (const float*)d_in[4];
    const float* Wk       = (const float*)d_in[5];
    const float* Wv       = (const float*)d_in[6];
    const float* bv       = (const float*)d_in[7];
    const float* Wo       = (const float*)d_in[8];
    const float* bo       = (const float*)d_in[9];
    float* out = (float*)d_out;

    cudaFuncSetAttribute(attn_kernel,
        cudaFuncAttributeMaxDynamicSharedMemorySize, ATT_SMEM);
    cudaFuncSetAttribute(mma_gemm,
        cudaFuncAttributeMaxDynamicSharedMemorySize, GEMM_SMEM);

    dim3 gg(MPAD / 128, D_ / 128);             // 65 x 8
    dim3 wg(32, 32), wb(32, 8);
    int t4 = M_ * D_ / 4;

    // conversions first: launch index 5 (0-based) = first mma_gemm,
    // which is what ncu -s 5 -c 1 captures.
    split_act<<<(t4 + 255) / 256, 256>>>(x);
    split_w<<<wg, wb>>>(Wq, 0);
    split_w<<<wg, wb>>>(Wk, 1);
    split_w<<<wg, wb>>>(Wv, 2);
    split_w<<<wg, wb>>>(Wo, 3);

    mma_gemm<<<gg, 256, GEMM_SMEM>>>(0, 0, bq,      nullptr, 1, 2);
    mma_gemm<<<gg, 256, GEMM_SMEM>>>(0, 1, nullptr, nullptr, 2, 2);
    mma_gemm<<<gg, 256, GEMM_SMEM>>>(0, 2, bv,      nullptr, 3, 2);

    int pairs = B_*H_*S_*32;
    dim3 g2((pairs + 255) / 256, 2);
    rope_kernel<<<g2, 256>>>(rope_cos, rope_sin);

    dim3 g3((S_ + 63) / 64, B_*H_);            // 17 x 128
    attn_kernel<<<g3, 256, ATT_SMEM>>>();

    // output projection: 1-term (ao fp16 x Wo hi)
    mma_gemm<<<gg, 256, GEMM_SMEM>>>(1, 3, bo, out, 0, 1);
}

// round 12
// speedup vs baseline: 3.8627x; 1.1613x over previous
#include <cuda_runtime.h>
#include <cuda_bf16.h>
#include <cuda_fp16.h>
#include <cstdint>

#define B_    8
#define S_    1029
#define D_    1024
#define H_    16
#define HD_   64
#define M_    (B_*S_)     // 8232
#define MPAD  8320        // 65 * 128
#define NPFX  5
#define SCALE_ 0.125f
#define SVP   1088        // padded key-stride for transposed V (16B-aligned rows)

// ---------------------------------------------------------------------------
// Scratch (device globals — no allocation allowed). .bss is zero-initialized;
// pad regions are never written and stay 0 (deterministic).
// ---------------------------------------------------------------------------
__device__ __align__(16) float g_q [B_*H_*S_*HD_];   // fp32 Q pre-rope [b,h,s,d]
__device__ __align__(16) float g_k [B_*H_*S_*HD_];   // fp32 K pre-rope

// attention operands, fp16 (written once, read by attn)
__device__ __align__(16) __half g_qh[B_*H_*S_*HD_];
__device__ __align__(16) __half g_kh[B_*H_*S_*HD_];
__device__ __align__(16) __half g_vth[B_*H_*HD_*SVP];   // V^T [b,h,d,s]

// GEMM operands, fp16
__device__ __align__(16) __half g_xhi [MPAD*D_];
__device__ __align__(16) __half g_aohi[MPAD*D_];  // attn out (fp16) [m,n]
__device__ __align__(16) __half g_wthi[4*D_*D_];  // W^T, [w][n][k]

// ---------------------------------------------------------------------------
// mma.sync helpers (portable PTX — no sm_103a-only features)
// ---------------------------------------------------------------------------
__device__ __forceinline__ uint32_t smem_u32(const void* p) {
    uint32_t a;
    asm("{ .reg .u64 t; cvta.to.shared.u64 t, %1; cvt.u32.u64 %0, t; }"
        : "=r"(a) : "l"(p));
    return a;
}
__device__ __forceinline__ void ldsm4(uint32_t* r, uint32_t addr) {
    asm volatile("ldmatrix.sync.aligned.m8n8.x4.shared.b16 {%0,%1,%2,%3}, [%4];"
        : "=r"(r[0]), "=r"(r[1]), "=r"(r[2]), "=r"(r[3]) : "r"(addr));
}
__device__ __forceinline__ void mmah16816(float* c, const uint32_t* a,
                                          const uint32_t* b) {
    asm volatile(
        "mma.sync.aligned.m16n8k16.row.col.f32.f16.f16.f32 "
        "{%0,%1,%2,%3}, {%4,%5,%6,%7}, {%8,%9}, {%0,%1,%2,%3};"
        : "+f"(c[0]), "+f"(c[1]), "+f"(c[2]), "+f"(c[3])
        : "r"(a[0]), "r"(a[1]), "r"(a[2]), "r"(a[3]), "r"(b[0]), "r"(b[1]));
}

// ---------------------------------------------------------------------------
// Round x to fp16.
// ---------------------------------------------------------------------------
__global__ void split_act(const float* __restrict__ src)
{
    const int total4 = M_ * D_ / 4;
    int i = blockIdx.x * blockDim.x + threadIdx.x;
    if (i >= total4) return;
    float4 v = ((const float4*)src)[i];
    __half2* Hi = (__half2*)g_xhi;
    Hi[2*i]   = __halves2half2(__float2half_rn(v.x), __float2half_rn(v.y));
    Hi[2*i+1] = __halves2half2(__float2half_rn(v.z), __float2half_rn(v.w));
}

// ---------------------------------------------------------------------------
// Transpose + round a weight: W[k][n] fp32 -> Wt[n][k] fp16 at slot widx
// ---------------------------------------------------------------------------
__global__ void split_w(const float* __restrict__ W, int widx)
{
    __shared__ float t[32][33];
    int n0 = blockIdx.x * 32, k0 = blockIdx.y * 32;
    int tx = threadIdx.x, ty = threadIdx.y;   // 32 x 8
    #pragma unroll
    for (int i = 0; i < 4; i++)
        t[ty + 8*i][tx] = W[(size_t)(k0 + ty + 8*i) * D_ + n0 + tx];
    __syncthreads();
    __half* Hi = g_wthi + (size_t)widx * D_ * D_;
    #pragma unroll
    for (int i = 0; i < 4; i++) {
        float v = t[tx][ty + 8*i];
        Hi[(size_t)(n0 + ty + 8*i) * D_ + k0 + tx] = __float2half_rn(v);
    }
}

// ---------------------------------------------------------------------------
// fp16 1-term tensor-core GEMM: C = A * B. 32 chunks, BK=32, double-buffered
// 40KB dynamic smem (2 bufs x 2 tiles x 128x40 fp16).
// mode 0: dst[m*D+n]; mode 1/2: fp32 g_q/g_k; mode 3: fp16 V^T.
// ---------------------------------------------------------------------------
#define ASTRIDE 40
#define TILEB (128*ASTRIDE)                 // elems per tile
#define GEMM_SMEM (2*2*TILEB*2)             // 40960 bytes

__global__ __launch_bounds__(256) void mma_gemm(
    int asel, int widx, const float* __restrict__ bias,
    float* __restrict__ dst, int mode)
{
    extern __shared__ __half smg[];         // [2][2][TILEB]: A,B

    const int tid  = threadIdx.x;
    const int lane = tid & 31, wid = tid >> 5;
    const int wm = wid & 1, wn = wid >> 1;
    const int bm = blockIdx.x * 128, bn = blockIdx.y * 128;

    const __half* A = asel ? g_aohi : g_xhi;
    const __half* Bw = g_wthi + (size_t)widx * D_ * D_;

    float acc[4][4][4] = {};

    // prologue: chunk 0
    #pragma unroll
    for (int it = 0; it < 2; it++) {
        int idx = tid + it * 256;
        int r = idx >> 2, c8 = (idx & 3) * 8;
        *(uint4*)&smg[0*TILEB + r*ASTRIDE + c8] =
            *(const uint4*)(A + (size_t)(bm + r) * D_ + c8);
        *(uint4*)&smg[1*TILEB + r*ASTRIDE + c8] =
            *(const uint4*)(Bw + (size_t)(bn + r) * D_ + c8);
    }
    __syncthreads();

    const uint32_t smB = smem_u32(smg);
    const uint32_t aOff = (uint32_t)(wm*64 + (lane & 15)) * 80 + (lane >> 4) * 16;
    const uint32_t bOff = (uint32_t)(wn*32 + (lane & 7) + ((lane >> 4) << 3)) * 80
                          + ((lane >> 3) & 1) * 16;
    const uint32_t TB = TILEB * 2;      // tile bytes
    const uint32_t BUFB = 2 * TB;       // buffer bytes

    const int NCH = 32;
    uint4 p[4];
    for (int t = 0; t < NCH; t++) {
        int buf = t & 1;
        if (t + 1 < NCH) {
            int k0 = (t + 1) * 32;
            #pragma unroll
            for (int it = 0; it < 2; it++) {
                int idx = tid + it * 256;
                int r = idx >> 2, c8 = (idx & 3) * 8;
                p[it*2 + 0] = *(const uint4*)(A  + (size_t)(bm + r) * D_ + k0 + c8);
                p[it*2 + 1] = *(const uint4*)(Bw + (size_t)(bn + r) * D_ + k0 + c8);
            }
        }
        uint32_t aB = smB + buf * BUFB;
        uint32_t bB = aB + TB;
        #pragma unroll
        for (int ks = 0; ks < 2; ks++) {
            uint32_t af[4][4], bf[2][4];
            #pragma unroll
            for (int mt = 0; mt < 4; mt++)
                ldsm4(af[mt], aB + aOff + mt * 16 * 80 + ks * 32);
            #pragma unroll
            for (int bt = 0; bt < 2; bt++)
                ldsm4(bf[bt], bB + bOff + bt * 16 * 80 + ks * 32);
            #pragma unroll
            for (int mt = 0; mt < 4; mt++)
                #pragma unroll
                for (int nt = 0; nt < 4; nt++)
                    mmah16816(acc[mt][nt], af[mt], &bf[nt >> 1][(nt & 1) * 2]);
        }
        if (t + 1 < NCH) {
            int nb = buf ^ 1;
            __half* d0 = smg + nb * 2 * TILEB;
            #pragma unroll
            for (int it = 0; it < 2; it++) {
                int idx = tid + it * 256;
                int r = idx >> 2, c8 = (idx & 3) * 8;
                *(uint4*)&d0[0*TILEB + r*ASTRIDE + c8] = p[it*2 + 0];
                *(uint4*)&d0[1*TILEB + r*ASTRIDE + c8] = p[it*2 + 1];
            }
        }
        __syncthreads();
    }

    const int rg = lane >> 2, cp = (lane & 3) * 2;
    #pragma unroll
    for (int mt = 0; mt < 4; mt++) {
        #pragma unroll
        for (int nt = 0; nt < 4; nt++) {
            int n = bn + wn*32 + nt*8 + cp;
            float b0v = bias ? __ldg(bias + n)     : 0.f;
            float b1v = bias ? __ldg(bias + n + 1) : 0.f;
            #pragma unroll
            for (int h2 = 0; h2 < 2; h2++) {
                int m = bm + wm*64 + mt*16 + rg + h2*8;
                if (m >= M_) continue;
                float v0 = acc[mt][nt][h2*2 + 0] + b0v;
                float v1 = acc[mt][nt][h2*2 + 1] + b1v;
                if (mode == 0) {
                    dst[(size_t)m * D_ + n]     = v0;
                    dst[(size_t)m * D_ + n + 1] = v1;
                } else if (mode == 3) {
                    // V: write transposed fp16 [b,h,d,s]
                    int b = m / S_, s = m % S_;
                    int h = n >> 6, d = n & 63;
                    size_t o = ((size_t)(b * H_ + h) * HD_ + d) * SVP + s;
                    g_vth[o]       = __float2half_rn(v0);
                    g_vth[o + SVP] = __float2half_rn(v1);
                } else {
                    int b = m / S_, s = m % S_;
                    int h = n >> 6, d = n & 63;
                    float* g = (mode == 1) ? g_q : g_k;
                    size_t o = (((size_t)(b * H_ + h)) * S_ + s) * HD_ + d;
                    g[o]     = v0;
                    g[o + 1] = v1;
                }
            }
        }
    }
}

// ---------------------------------------------------------------------------
// RoPE (patch tokens only) + q-scale; emits fp16 Q and K.
// ---------------------------------------------------------------------------
__global__ void rope_kernel(const float* __restrict__ cosp,
                            const float* __restrict__ sinp)
{
    const int total = B_*H_*S_*32;
    int i = blockIdx.x * blockDim.x + threadIdx.x;
    if (i >= total) return;
    const bool isQ = (blockIdx.y == 0);
    int dh = i & 31;
    int s  = (i >> 5) % S_;
    int bh = i / (32 * S_);
    size_t base = ((size_t)bh * S_ + s) * HD_;
    const float* ptr = (isQ ? g_q : g_k) + base;
    float y0, y1;
    if (s < NPFX) {
        y0 = ptr[dh]; y1 = ptr[dh+32];
    } else {
        int p = s - NPFX;
        float c0 = cosp[p*HD_ + dh],      c1 = cosp[p*HD_ + dh + 32];
        float s0 = sinp[p*HD_ + dh],      s1 = sinp[p*HD_ + dh + 32];
        float x0 = ptr[dh], x1 = ptr[dh+32];
        y0 = x0*c0 - x1*s0;
        y1 = x1*c1 + x0*s1;
    }
    __half* Hp = isQ ? g_qh : g_kh;
    if (isQ) { y0 *= SCALE_; y1 *= SCALE_; }
    Hp[base + dh]      = __float2half_rn(y0);
    Hp[base + dh + 32] = __float2half_rn(y1);
}

// ---------------------------------------------------------------------------
// Tensor-core flash attention, fully fp16 1-term (Q·K, P·V).
// Epilogue writes fp16 ao for the output projection.
// ---------------------------------------------------------------------------
#define QST 72
#define SST 73
#define ATT_SMEM (4*64*QST*2 + 64*SST*4 + (3*64 + 512)*4)   // 58368

__global__ __launch_bounds__(256) void attn_kernel()
{
    extern __shared__ char smx[];
    __half* Qhi  = (__half*)smx;            // [64][QST]  (q, d)
    __half* Khi  = Qhi  + 64*QST;           // [64][QST]  (key, d)
    __half* Vthi = Khi  + 64*QST;           // [64][QST]  (d, key)
    __half* Pm   = Vthi + 64*QST;           // [64][QST]  (q, key)
    float*  S32  = (float*)(Pm + 64*QST);   // [64][SST]  (q, key)
    float*  m_s  = S32 + 64*SST;            // [64]
    float*  l_s  = m_s + 64;
    float*  al_s = l_s + 64;
    float*  redm = al_s + 64;               // [4][64]
    float*  reds = redm + 256;              // [4][64]

    const int tid  = threadIdx.x;
    const int lane = tid & 31, wid = tid >> 5;
    const int wm = wid & 1, wn = wid >> 1;     // 2 x 4 warp grid
    const int rg = lane >> 2, cp = (lane & 3) * 2;
    const int bh = blockIdx.y;
    const int m0 = blockIdx.x * 64;
    const __half* qhp = g_qh + (size_t)bh * S_ * HD_;
    const __half* khp = g_kh + (size_t)bh * S_ * HD_;
    const __half* vhp = g_vth + (size_t)bh * HD_ * SVP;

    // Q tile: uint4 copies (zero-fill tail rows)
    const uint4 Z4 = make_uint4(0u, 0u, 0u, 0u);
    #pragma unroll
    for (int it = 0; it < 2; it++) {
        int idx = tid + it * 256;              // 0..511
        int r = idx >> 3, c8 = (idx & 7) * 8;
        uint4 vh = Z4;
        if (m0 + r < S_)
            vh = *(const uint4*)(qhp + (size_t)(m0 + r) * HD_ + c8);
        *(uint4*)&Qhi[r*QST + c8] = vh;
    }
    if (tid < 64) { m_s[tid] = -1e30f; l_s[tid] = 0.f; }

    const uint32_t QhiB = smem_u32(Qhi);
    const uint32_t KhiB = smem_u32(Khi);
    const uint32_t VhiB = smem_u32(Vthi);
    const uint32_t PmB  = smem_u32(Pm);
    const uint32_t aOff = (uint32_t)(wm*32 + (lane & 15)) * 144 + (lane >> 4) * 16;
    const uint32_t bOff = (uint32_t)(wn*16 + (lane & 7) + ((lane >> 4) << 3)) * 144
                          + ((lane >> 3) & 1) * 16;

    float oacc[2][2][4] = {};
    const int sq = tid & 63, part = tid >> 6;

    for (int n0 = 0; n0 < S_; n0 += 64) {
        __syncthreads();   // protects K/V/P reuse + first-iter init
        // K tile [key][d]
        #pragma unroll
        for (int it = 0; it < 2; it++) {
            int idx = tid + it * 256;
            int r = idx >> 3, c8 = (idx & 7) * 8;
            uint4 vh = Z4;
            if (n0 + r < S_)
                vh = *(const uint4*)(khp + (size_t)(n0 + r) * HD_ + c8);
            *(uint4*)&Khi[r*QST + c8] = vh;
        }
        // Vt tile [d][key] from padded transposed layout
        #pragma unroll
        for (int it = 0; it < 2; it++) {
            int idx = tid + it * 256;
            int d = idx >> 3, k8 = (idx & 7) * 8;
            *(uint4*)&Vthi[d*QST + k8] =
                *(const uint4*)(vhp + (size_t)d * SVP + n0 + k8);
        }
        __syncthreads();

        // S = Q K^T (1-term)
        float sacc[2][2][4] = {};
        #pragma unroll
        for (int ks = 0; ks < 4; ks++) {
            uint32_t ah[2][4], bhh[4];
            #pragma unroll
            for (int mt = 0; mt < 2; mt++)
                ldsm4(ah[mt], QhiB + aOff + mt * 16 * 144 + ks * 32);
            ldsm4(bhh, KhiB + bOff + ks * 32);
            #pragma unroll
            for (int mt = 0; mt < 2; mt++)
                #pragma unroll
                for (int nt = 0; nt < 2; nt++)
                    mmah16816(sacc[mt][nt], ah[mt], &bhh[nt*2]);
        }
        // store S frags
        #pragma unroll
        for (int mt = 0; mt < 2; mt++)
            #pragma unroll
            for (int nt = 0; nt < 2; nt++) {
                int q0 = wm*32 + mt*16 + rg;
                int kc = wn*16 + nt*8 + cp;
                S32[q0*SST + kc]       = sacc[mt][nt][0];
                S32[q0*SST + kc + 1]   = sacc[mt][nt][1];
                S32[(q0+8)*SST + kc]     = sacc[mt][nt][2];
                S32[(q0+8)*SST + kc + 1] = sacc[mt][nt][3];
            }
        __syncthreads();

        // per-query max over this tile (4 partials)
        {
            float pm = -1e30f;
            #pragma unroll
            for (int i = 0; i < 16; i++) {
                int kk = part*16 + i;
                float v = S32[sq*SST + kk];
                pm = fmaxf(pm, (n0 + kk < S_) ? v : -1e30f);
            }
            redm[part*64 + sq] = pm;
        }
        __syncthreads();
        if (tid < 64) {
            float nm = fmaxf(fmaxf(redm[sq], redm[64+sq]),
                             fmaxf(redm[128+sq], redm[192+sq]));
            nm = fmaxf(nm, m_s[sq]);
            al_s[sq] = __expf(m_s[sq] - nm);
            m_s[sq]  = nm;
        }
        __syncthreads();
        // exp -> P fp16, partial sums
        {
            float mr = m_s[sq];
            float ps = 0.f;
            #pragma unroll
            for (int i = 0; i < 16; i++) {
                int kk = part*16 + i;
                float e = 0.f;
                if (n0 + kk < S_) e = __expf(S32[sq*SST + kk] - mr);
                Pm[sq*QST + kk] = __float2half_rn(e);
                ps += e;
            }
            reds[part*64 + sq] = ps;
        }
        __syncthreads();
        if (tid < 64)
            l_s[sq] = l_s[sq]*al_s[sq] + reds[sq] + reds[64+sq]
                      + reds[128+sq] + reds[192+sq];

        // rescale O frags by alpha
        #pragma unroll
        for (int mt = 0; mt < 2; mt++) {
            float a0 = al_s[wm*32 + mt*16 + rg];
            float a1 = al_s[wm*32 + mt*16 + rg + 8];
            #pragma unroll
            for (int nt = 0; nt < 2; nt++) {
                oacc[mt][nt][0] *= a0; oacc[mt][nt][1] *= a0;
                oacc[mt][nt][2] *= a1; oacc[mt][nt][3] *= a1;
            }
        }
        // O += P * V (1-term)
        #pragma unroll
        for (int ks = 0; ks < 4; ks++) {
            uint32_t ap[2][4], vh[4];
            #pragma unroll
            for (int mt = 0; mt < 2; mt++)
                ldsm4(ap[mt], PmB + aOff + mt * 16 * 144 + ks * 32);
            ldsm4(vh, VhiB + bOff + ks * 32);
            #pragma unroll
            for (int mt = 0; mt < 2; mt++)
                #pragma unroll
                for (int nt = 0; nt < 2; nt++)
                    mmah16816(oacc[mt][nt], ap[mt], &vh[nt*2]);
        }
    }
    __syncthreads();   // final l_s visible

    // epilogue: write fp16 ao for the output projection
    const int b = bh / H_, h = bh % H_;
    #pragma unroll
    for (int mt = 0; mt < 2; mt++) {
        #pragma unroll
        for (int h2 = 0; h2 < 2; h2++) {
            int q0 = wm*32 + mt*16 + rg + h2*8;
            int m = m0 + q0;
            if (m >= S_) continue;
            float inv = 1.f / l_s[q0];
            #pragma unroll
            for (int nt = 0; nt < 2; nt++) {
                int d0 = wn*16 + nt*8 + cp;
                float w0 = oacc[mt][nt][h2*2 + 0] * inv;
                float w1 = oacc[mt][nt][h2*2 + 1] * inv;
                size_t o = ((size_t)b * S_ + m) * D_ + h * HD_ + d0;
                *(__half2*)&g_aohi[o] = __halves2half2(
                    __float2half_rn(w0), __float2half_rn(w1));
            }
        }
    }
}

// ---------------------------------------------------------------------------
extern "C" void kernel_launch(void* const* d_in, const int* in_sizes, int n_in,
                              void* d_out, int out_size)
{
    const float* x        = (const float*)d_in[0];
    const float* rope_cos = (const float*)d_in[1];
    const float* rope_sin = (const float*)d_in[2];
    const float* Wq       = (const float*)d_in[3];
    const float* bq       = (const float*)d_in[4];
    const float* Wk       = (const float*)d_in[5];
    const float* Wv       = (const float*)d_in[6];
    const float* bv       = (const float*)d_in[7];
    const float* Wo       = (const float*)d_in[8];
    const float* bo       = (const float*)d_in[9];
    float* out = (float*)d_out;

    cudaFuncSetAttribute(attn_kernel,
        cudaFuncAttributeMaxDynamicSharedMemorySize, ATT_SMEM);
    cudaFuncSetAttribute(mma_gemm,
        cudaFuncAttributeMaxDynamicSharedMemorySize, GEMM_SMEM);

    dim3 gg(MPAD / 128, D_ / 128);             // 65 x 8
    dim3 wg(32, 32), wb(32, 8);
    int t4 = M_ * D_ / 4;

    // conversions first: launch index 5 (0-based) = first mma_gemm (= ncu -s 5)
    split_act<<<(t4 + 255) / 256, 256>>>(x);
    split_w<<<wg, wb>>>(Wq, 0);
    split_w<<<wg, wb>>>(Wk, 1);
    split_w<<<wg, wb>>>(Wv, 2);
    split_w<<<wg, wb>>>(Wo, 3);

    mma_gemm<<<gg, 256, GEMM_SMEM>>>(0, 0, bq,      nullptr, 1);
    mma_gemm<<<gg, 256, GEMM_SMEM>>>(0, 1, nullptr, nullptr, 2);
    mma_gemm<<<gg, 256, GEMM_SMEM>>>(0, 2, bv,      nullptr, 3);

    int pairs = B_*H_*S_*32;
    dim3 g2((pairs + 255) / 256, 2);
    rope_kernel<<<g2, 256>>>(rope_cos, rope_sin);

    dim3 g3((S_ + 63) / 64, B_*H_);            // 17 x 128
    attn_kernel<<<g3, 256, ATT_SMEM>>>();

    // output projection (ao fp16 x Wo fp16)
    mma_gemm<<<gg, 256, GEMM_SMEM>>>(1, 3, bo, out, 0);
}

// round 13
// speedup vs baseline: 4.2025x; 1.0880x over previous
#include <cuda_runtime.h>
#include <cuda_bf16.h>
#include <cuda_fp16.h>
#include <cstdint>

#define B_    8
#define S_    1029
#define D_    1024
#define H_    16
#define HD_   64
#define M_    (B_*S_)     // 8232
#define MPAD  8320        // 65 * 128
#define NPFX  5
#define SCALE_ 0.125f
#define SVP   1088        // padded key-stride for transposed V (16B-aligned rows)

// ---------------------------------------------------------------------------
// Scratch (device globals — no allocation allowed). .bss zero-init; pad
// regions never written (deterministic).
// ---------------------------------------------------------------------------
__device__ __align__(16) float g_q [B_*H_*S_*HD_];   // fp32 Q pre-rope [b,h,s,d]
__device__ __align__(16) float g_k [B_*H_*S_*HD_];   // fp32 K pre-rope

__device__ __align__(16) __half g_qh[B_*H_*S_*HD_];
__device__ __align__(16) __half g_kh[B_*H_*S_*HD_];
__device__ __align__(16) __half g_vth[B_*H_*HD_*SVP];   // V^T [b,h,d,s]

__device__ __align__(16) __half g_xhi [MPAD*D_];
__device__ __align__(16) __half g_aohi[MPAD*D_];  // attn out (fp16) [m,n]
__device__ __align__(16) __half g_wthi[4*D_*D_];  // W^T, [w][n][k]

// ---------------------------------------------------------------------------
// mma.sync helpers (portable PTX)
// ---------------------------------------------------------------------------
__device__ __forceinline__ uint32_t smem_u32(const void* p) {
    uint32_t a;
    asm("{ .reg .u64 t; cvta.to.shared.u64 t, %1; cvt.u32.u64 %0, t; }"
        : "=r"(a) : "l"(p));
    return a;
}
__device__ __forceinline__ void ldsm4(uint32_t* r, uint32_t addr) {
    asm volatile("ldmatrix.sync.aligned.m8n8.x4.shared.b16 {%0,%1,%2,%3}, [%4];"
        : "=r"(r[0]), "=r"(r[1]), "=r"(r[2]), "=r"(r[3]) : "r"(addr));
}
__device__ __forceinline__ void mmah16816(float* c, const uint32_t* a,
                                          const uint32_t* b) {
    asm volatile(
        "mma.sync.aligned.m16n8k16.row.col.f32.f16.f16.f32 "
        "{%0,%1,%2,%3}, {%4,%5,%6,%7}, {%8,%9}, {%0,%1,%2,%3};"
        : "+f"(c[0]), "+f"(c[1]), "+f"(c[2]), "+f"(c[3])
        : "r"(a[0]), "r"(a[1]), "r"(a[2]), "r"(a[3]), "r"(b[0]), "r"(b[1]));
}

// ---------------------------------------------------------------------------
// Round x to fp16.
// ---------------------------------------------------------------------------
__global__ void split_act(const float* __restrict__ src)
{
    const int total4 = M_ * D_ / 4;
    int i = blockIdx.x * blockDim.x + threadIdx.x;
    if (i >= total4) return;
    float4 v = ((const float4*)src)[i];
    __half2* Hi = (__half2*)g_xhi;
    Hi[2*i]   = __halves2half2(__float2half_rn(v.x), __float2half_rn(v.y));
    Hi[2*i+1] = __halves2half2(__float2half_rn(v.z), __float2half_rn(v.w));
}

// ---------------------------------------------------------------------------
// Transpose + round all 4 weights (blockIdx.z = widx).
// ---------------------------------------------------------------------------
__global__ void split_w(const float* __restrict__ W0, const float* __restrict__ W1,
                        const float* __restrict__ W2, const float* __restrict__ W3)
{
    __shared__ float t[32][33];
    int widx = blockIdx.z;
    const float* W = (widx == 0) ? W0 : (widx == 1) ? W1 : (widx == 2) ? W2 : W3;
    int n0 = blockIdx.x * 32, k0 = blockIdx.y * 32;
    int tx = threadIdx.x, ty = threadIdx.y;   // 32 x 8
    #pragma unroll
    for (int i = 0; i < 4; i++)
        t[ty + 8*i][tx] = W[(size_t)(k0 + ty + 8*i) * D_ + n0 + tx];
    __syncthreads();
    __half* Hi = g_wthi + (size_t)widx * D_ * D_;
    #pragma unroll
    for (int i = 0; i < 4; i++) {
        float v = t[tx][ty + 8*i];
        Hi[(size_t)(n0 + ty + 8*i) * D_ + k0 + tx] = __float2half_rn(v);
    }
}

// ---------------------------------------------------------------------------
// fp16 tensor-core GEMM: C = A * B. 32 chunks, BK=32, double-buffered 40KB.
// mode >= 0: single weight widx; mode 0 -> dst, 1/2 -> g_q/g_k fp32,
//            3 -> fp16 V^T.
// mode == -1: fused QKV; grid.y spans 24, w = by>>3 selects weight & output.
// ---------------------------------------------------------------------------
#define ASTRIDE 40
#define TILEB (128*ASTRIDE)                 // elems per tile
#define GEMM_SMEM (2*2*TILEB*2)             // 40960 bytes

__global__ __launch_bounds__(256) void mma_gemm(
    int asel, int widx, const float* __restrict__ bq_,
    const float* __restrict__ bv_, float* __restrict__ dst, int mode)
{
    extern __shared__ __half smg[];         // [2][2][TILEB]: A,B

    const int tid  = threadIdx.x;
    const int lane = tid & 31, wid = tid >> 5;
    const int wm = wid & 1, wn = wid >> 1;
    const int bm = blockIdx.x * 128;

    int bn, emode;
    const float* bias;
    if (mode == -1) {               // fused QKV
        int w = blockIdx.y >> 3;
        bn    = (blockIdx.y & 7) * 128;
        widx  = w;
        emode = 1 + w;              // 1=q, 2=k, 3=v
        bias  = (w == 0) ? bq_ : (w == 2) ? bv_ : nullptr;
    } else {
        bn    = blockIdx.y * 128;
        emode = mode;
        bias  = bq_;
    }

    const __half* A = asel ? g_aohi : g_xhi;
    const __half* Bw = g_wthi + (size_t)widx * D_ * D_;

    float acc[4][4][4] = {};

    // prologue: chunk 0
    #pragma unroll
    for (int it = 0; it < 2; it++) {
        int idx = tid + it * 256;
        int r = idx >> 2, c8 = (idx & 3) * 8;
        *(uint4*)&smg[0*TILEB + r*ASTRIDE + c8] =
            *(const uint4*)(A + (size_t)(bm + r) * D_ + c8);
        *(uint4*)&smg[1*TILEB + r*ASTRIDE + c8] =
            *(const uint4*)(Bw + (size_t)(bn + r) * D_ + c8);
    }
    __syncthreads();

    const uint32_t smB = smem_u32(smg);
    const uint32_t aOff = (uint32_t)(wm*64 + (lane & 15)) * 80 + (lane >> 4) * 16;
    const uint32_t bOff = (uint32_t)(wn*32 + (lane & 7) + ((lane >> 4) << 3)) * 80
                          + ((lane >> 3) & 1) * 16;
    const uint32_t TB = TILEB * 2;      // tile bytes
    const uint32_t BUFB = 2 * TB;       // buffer bytes

    const int NCH = 32;
    uint4 p[4];
    for (int t = 0; t < NCH; t++) {
        int buf = t & 1;
        if (t + 1 < NCH) {
            int k0 = (t + 1) * 32;
            #pragma unroll
            for (int it = 0; it < 2; it++) {
                int idx = tid + it * 256;
                int r = idx >> 2, c8 = (idx & 3) * 8;
                p[it*2 + 0] = *(const uint4*)(A  + (size_t)(bm + r) * D_ + k0 + c8);
                p[it*2 + 1] = *(const uint4*)(Bw + (size_t)(bn + r) * D_ + k0 + c8);
            }
        }
        uint32_t aB = smB + buf * BUFB;
        uint32_t bB = aB + TB;
        #pragma unroll
        for (int ks = 0; ks < 2; ks++) {
            uint32_t af[4][4], bf[2][4];
            #pragma unroll
            for (int mt = 0; mt < 4; mt++)
                ldsm4(af[mt], aB + aOff + mt * 16 * 80 + ks * 32);
            #pragma unroll
            for (int bt = 0; bt < 2; bt++)
                ldsm4(bf[bt], bB + bOff + bt * 16 * 80 + ks * 32);
            #pragma unroll
            for (int mt = 0; mt < 4; mt++)
                #pragma unroll
                for (int nt = 0; nt < 4; nt++)
                    mmah16816(acc[mt][nt], af[mt], &bf[nt >> 1][(nt & 1) * 2]);
        }
        if (t + 1 < NCH) {
            int nb = buf ^ 1;
            __half* d0 = smg + nb * 2 * TILEB;
            #pragma unroll
            for (int it = 0; it < 2; it++) {
                int idx = tid + it * 256;
                int r = idx >> 2, c8 = (idx & 3) * 8;
                *(uint4*)&d0[0*TILEB + r*ASTRIDE + c8] = p[it*2 + 0];
                *(uint4*)&d0[1*TILEB + r*ASTRIDE + c8] = p[it*2 + 1];
            }
        }
        __syncthreads();
    }

    const int rg = lane >> 2, cp = (lane & 3) * 2;
    #pragma unroll
    for (int mt = 0; mt < 4; mt++) {
        #pragma unroll
        for (int nt = 0; nt < 4; nt++) {
            int n = bn + wn*32 + nt*8 + cp;
            float b0v = bias ? __ldg(bias + n)     : 0.f;
            float b1v = bias ? __ldg(bias + n + 1) : 0.f;
            #pragma unroll
            for (int h2 = 0; h2 < 2; h2++) {
                int m = bm + wm*64 + mt*16 + rg + h2*8;
                if (m >= M_) continue;
                float v0 = acc[mt][nt][h2*2 + 0] + b0v;
                float v1 = acc[mt][nt][h2*2 + 1] + b1v;
                if (emode == 0) {
                    dst[(size_t)m * D_ + n]     = v0;
                    dst[(size_t)m * D_ + n + 1] = v1;
                } else if (emode == 3) {
                    int b = m / S_, s = m % S_;
                    int h = n >> 6, d = n & 63;
                    size_t o = ((size_t)(b * H_ + h) * HD_ + d) * SVP + s;
                    g_vth[o]       = __float2half_rn(v0);
                    g_vth[o + SVP] = __float2half_rn(v1);
                } else {
                    int b = m / S_, s = m % S_;
                    int h = n >> 6, d = n & 63;
                    float* g = (emode == 1) ? g_q : g_k;
                    size_t o = (((size_t)(b * H_ + h)) * S_ + s) * HD_ + d;
                    g[o]     = v0;
                    g[o + 1] = v1;
                }
            }
        }
    }
}

// ---------------------------------------------------------------------------
// RoPE (patch tokens only) + q-scale; emits fp16 Q and K.
// ---------------------------------------------------------------------------
__global__ void rope_kernel(const float* __restrict__ cosp,
                            const float* __restrict__ sinp)
{
    const int total = B_*H_*S_*32;
    int i = blockIdx.x * blockDim.x + threadIdx.x;
    if (i >= total) return;
    const bool isQ = (blockIdx.y == 0);
    int dh = i & 31;
    int s  = (i >> 5) % S_;
    int bh = i / (32 * S_);
    size_t base = ((size_t)bh * S_ + s) * HD_;
    const float* ptr = (isQ ? g_q : g_k) + base;
    float y0, y1;
    if (s < NPFX) {
        y0 = ptr[dh]; y1 = ptr[dh+32];
    } else {
        int p = s - NPFX;
        float c0 = cosp[p*HD_ + dh],      c1 = cosp[p*HD_ + dh + 32];
        float s0 = sinp[p*HD_ + dh],      s1 = sinp[p*HD_ + dh + 32];
        float x0 = ptr[dh], x1 = ptr[dh+32];
        y0 = x0*c0 - x1*s0;
        y1 = x1*c1 + x0*s1;
    }
    __half* Hp = isQ ? g_qh : g_kh;
    if (isQ) { y0 *= SCALE_; y1 *= SCALE_; }
    Hp[base + dh]      = __float2half_rn(y0);
    Hp[base + dh + 32] = __float2half_rn(y1);
}

// ---------------------------------------------------------------------------
// Tensor-core flash attention, 128-query tiles, 64-key tiles, fp16 1-term.
// 8 warps in 2(q)x4(k); warp q-span 64 (4 m-frags).
// ---------------------------------------------------------------------------
#define QST 72
#define SST 73
// Qhi[128] + Khi[64] + Vthi[64] + Pm[128] rows of QST halves, S32 128xSST fp32
#define ATT_SMEM ((128+64+64+128)*QST*2 + 128*SST*4 + (3*128 + 2*256)*4) // 96320

__global__ __launch_bounds__(256) void attn_kernel()
{
    extern __shared__ char smx[];
    __half* Qhi  = (__half*)smx;            // [128][QST]  (q, d)
    __half* Khi  = Qhi  + 128*QST;          // [64][QST]   (key, d)
    __half* Vthi = Khi  + 64*QST;           // [64][QST]   (d, key)
    __half* Pm   = Vthi + 64*QST;           // [128][QST]  (q, key)
    float*  S32  = (float*)(Pm + 128*QST);  // [128][SST]  (q, key)
    float*  m_s  = S32 + 128*SST;           // [128]
    float*  l_s  = m_s + 128;
    float*  al_s = l_s + 128;
    float*  redm = al_s + 128;              // [2][128]
    float*  reds = redm + 256;              // [2][128]

    const int tid  = threadIdx.x;
    const int lane = tid & 31, wid = tid >> 5;
    const int wm = wid & 1, wn = wid >> 1;     // 2(q) x 4(k) warp grid
    const int rg = lane >> 2, cp = (lane & 3) * 2;
    const int bh = blockIdx.y;
    const int m0 = blockIdx.x * 128;
    const __half* qhp = g_qh + (size_t)bh * S_ * HD_;
    const __half* khp = g_kh + (size_t)bh * S_ * HD_;
    const __half* vhp = g_vth + (size_t)bh * HD_ * SVP;

    // Q tile: 128 x 64, uint4 copies (zero-fill tail rows)
    const uint4 Z4 = make_uint4(0u, 0u, 0u, 0u);
    #pragma unroll
    for (int it = 0; it < 4; it++) {
        int idx = tid + it * 256;              // 0..1023
        int r = idx >> 3, c8 = (idx & 7) * 8;
        uint4 vh = Z4;
        if (m0 + r < S_)
            vh = *(const uint4*)(qhp + (size_t)(m0 + r) * HD_ + c8);
        *(uint4*)&Qhi[r*QST + c8] = vh;
    }
    if (tid < 128) { m_s[tid] = -1e30f; l_s[tid] = 0.f; }

    const uint32_t QhiB = smem_u32(Qhi);
    const uint32_t KhiB = smem_u32(Khi);
    const uint32_t VhiB = smem_u32(Vthi);
    const uint32_t PmB  = smem_u32(Pm);
    const uint32_t aOff = (uint32_t)(wm*64 + (lane & 15)) * 144 + (lane >> 4) * 16;
    const uint32_t bOff = (uint32_t)(wn*16 + (lane & 7) + ((lane >> 4) << 3)) * 144
                          + ((lane >> 3) & 1) * 16;

    float oacc[4][2][4] = {};
    const int sq = tid & 127, part = tid >> 7;   // 2 partials x 32 keys

    for (int n0 = 0; n0 < S_; n0 += 64) {
        __syncthreads();   // protects K/V/P reuse + first-iter init
        // K tile [key][d]
        #pragma unroll
        for (int it = 0; it < 2; it++) {
            int idx = tid + it * 256;
            int r = idx >> 3, c8 = (idx & 7) * 8;
            uint4 vh = Z4;
            if (n0 + r < S_)
                vh = *(const uint4*)(khp + (size_t)(n0 + r) * HD_ + c8);
            *(uint4*)&Khi[r*QST + c8] = vh;
        }
        // Vt tile [d][key]
        #pragma unroll
        for (int it = 0; it < 2; it++) {
            int idx = tid + it * 256;
            int d = idx >> 3, k8 = (idx & 7) * 8;
            *(uint4*)&Vthi[d*QST + k8] =
                *(const uint4*)(vhp + (size_t)d * SVP + n0 + k8);
        }
        __syncthreads();

        // S = Q K^T
        float sacc[4][2][4] = {};
        #pragma unroll
        for (int ks = 0; ks < 4; ks++) {
            uint32_t ah[4][4], bhh[4];
            #pragma unroll
            for (int mt = 0; mt < 4; mt++)
                ldsm4(ah[mt], QhiB + aOff + mt * 16 * 144 + ks * 32);
            ldsm4(bhh, KhiB + bOff + ks * 32);
            #pragma unroll
            for (int mt = 0; mt < 4; mt++)
                #pragma unroll
                for (int nt = 0; nt < 2; nt++)
                    mmah16816(sacc[mt][nt], ah[mt], &bhh[nt*2]);
        }
        // store S frags
        #pragma unroll
        for (int mt = 0; mt < 4; mt++)
            #pragma unroll
            for (int nt = 0; nt < 2; nt++) {
                int q0 = wm*64 + mt*16 + rg;
                int kc = wn*16 + nt*8 + cp;
                S32[q0*SST + kc]       = sacc[mt][nt][0];
                S32[q0*SST + kc + 1]   = sacc[mt][nt][1];
                S32[(q0+8)*SST + kc]     = sacc[mt][nt][2];
                S32[(q0+8)*SST + kc + 1] = sacc[mt][nt][3];
            }
        __syncthreads();

        // per-query max over this tile (2 partials x 32 keys)
        {
            float pm = -1e30f;
            #pragma unroll
            for (int i = 0; i < 32; i++) {
                int kk = part*32 + i;
                float v = S32[sq*SST + kk];
                pm = fmaxf(pm, (n0 + kk < S_) ? v : -1e30f);
            }
            redm[part*128 + sq] = pm;
        }
        __syncthreads();
        if (tid < 128) {
            float nm = fmaxf(fmaxf(redm[sq], redm[128+sq]), m_s[sq]);
            al_s[sq] = __expf(m_s[sq] - nm);
            m_s[sq]  = nm;
        }
        __syncthreads();
        // exp -> P fp16, partial sums
        {
            float mr = m_s[sq];
            float ps = 0.f;
            #pragma unroll
            for (int i = 0; i < 32; i++) {
                int kk = part*32 + i;
                float e = 0.f;
                if (n0 + kk < S_) e = __expf(S32[sq*SST + kk] - mr);
                Pm[sq*QST + kk] = __float2half_rn(e);
                ps += e;
            }
            reds[part*128 + sq] = ps;
        }
        __syncthreads();
        if (tid < 128)
            l_s[sq] = l_s[sq]*al_s[sq] + reds[sq] + reds[128+sq];

        // rescale O frags by alpha
        #pragma unroll
        for (int mt = 0; mt < 4; mt++) {
            float a0 = al_s[wm*64 + mt*16 + rg];
            float a1 = al_s[wm*64 + mt*16 + rg + 8];
            #pragma unroll
            for (int nt = 0; nt < 2; nt++) {
                oacc[mt][nt][0] *= a0; oacc[mt][nt][1] *= a0;
                oacc[mt][nt][2] *= a1; oacc[mt][nt][3] *= a1;
            }
        }
        // O += P * V
        #pragma unroll
        for (int ks = 0; ks < 4; ks++) {
            uint32_t ap[4][4], vh[4];
            #pragma unroll
            for (int mt = 0; mt < 4; mt++)
                ldsm4(ap[mt], PmB + aOff + mt * 16 * 144 + ks * 32);
            ldsm4(vh, VhiB + bOff + ks * 32);
            #pragma unroll
            for (int mt = 0; mt < 4; mt++)
                #pragma unroll
                for (int nt = 0; nt < 2; nt++)
                    mmah16816(oacc[mt][nt], ap[mt], &vh[nt*2]);
        }
    }
    __syncthreads();   // final l_s visible

    // epilogue: write fp16 ao for the output projection
    const int b = bh / H_, h = bh % H_;
    #pragma unroll
    for (int mt = 0; mt < 4; mt++) {
        #pragma unroll
        for (int h2 = 0; h2 < 2; h2++) {
            int q0 = wm*64 + mt*16 + rg + h2*8;
            int m = m0 + q0;
            if (m >= S_) continue;
            float inv = 1.f / l_s[q0];
            #pragma unroll
            for (int nt = 0; nt < 2; nt++) {
                int d0 = wn*16 + nt*8 + cp;
                float w0 = oacc[mt][nt][h2*2 + 0] * inv;
                float w1 = oacc[mt][nt][h2*2 + 1] * inv;
                size_t o = ((size_t)b * S_ + m) * D_ + h * HD_ + d0;
                *(__half2*)&g_aohi[o] = __halves2half2(
                    __float2half_rn(w0), __float2half_rn(w1));
            }
        }
    }
}

// ---------------------------------------------------------------------------
extern "C" void kernel_launch(void* const* d_in, const int* in_sizes, int n_in,
                              void* d_out, int out_size)
{
    const float* x        = (const float*)d_in[0];
    const float* rope_cos = (const float*)d_in[1];
    const float* rope_sin = (const float*)d_in[2];
    const float* Wq       = (const float*)d_in[3];
    const float* bq       = (const float*)d_in[4];
    const float* Wk       = (const float*)d_in[5];
    const float* Wv       = (const float*)d_in[6];
    const float* bv       = (const float*)d_in[7];
    const float* Wo       = (const float*)d_in[8];
    const float* bo       = (const float*)d_in[9];
    float* out = (float*)d_out;

    cudaFuncSetAttribute(attn_kernel,
        cudaFuncAttributeMaxDynamicSharedMemorySize, ATT_SMEM);
    cudaFuncSetAttribute(mma_gemm,
        cudaFuncAttributeMaxDynamicSharedMemorySize, GEMM_SMEM);

    int t4 = M_ * D_ / 4;
    split_act<<<(t4 + 255) / 256, 256>>>(x);

    dim3 wg(32, 32, 4), wb(32, 8);
    split_w<<<wg, wb>>>(Wq, Wk, Wv, Wo);

    // fused QKV projection: grid.y = 24 (3 weights x 8 n-blocks)
    dim3 gq(MPAD / 128, 24);
    mma_gemm<<<gq, 256, GEMM_SMEM>>>(0, 0, bq, bv, nullptr, -1);

    int pairs = B_*H_*S_*32;
    dim3 g2((pairs + 255) / 256, 2);
    rope_kernel<<<g2, 256>>>(rope_cos, rope_sin);

    dim3 g3((S_ + 127) / 128, B_*H_);          // 9 x 128
    attn_kernel<<<g3, 256, ATT_SMEM>>>();

    // output projection
    dim3 go(MPAD / 128, D_ / 128);             // 65 x 8
    mma_gemm<<<go, 256, GEMM_SMEM>>>(1, 3, bo, nullptr, out, 0);
}